// round 1
// baseline (speedup 1.0000x reference)
#include <cuda_runtime.h>
#include <math.h>

// Problem dims
#define BB 2
#define LL 2048
#define DD 1024
#define HH 16
#define DKK 64
#define MM (BB*LL)     // 4096
#define NN 1024        // H*DK = D

// Scratch (device globals: allocation rules forbid cudaMalloc)
__device__ float g_q[BB*HH*LL*DKK];
__device__ float g_k[BB*HH*LL*DKK];
__device__ float g_v[BB*HH*LL*DKK];
__device__ float g_ctx[BB*HH*LL*DKK];

// ---------------------------------------------------------------------------
// SGEMM: C = A(4096x1024) * B(1024x1024) + bias
// MODE 0: A plain row-major, C scattered to (B,H,L,DK) layout  (QKV proj)
// MODE 1: A gathered from (B,H,L,DK) layout, C plain row-major (out proj)
// 128x128x16 tile, 256 threads, 8x8 per-thread microtile.
// ---------------------------------------------------------------------------
template<int MODE>
__global__ __launch_bounds__(256)
void sgemm_kernel(const float* __restrict__ A,
                  const float* __restrict__ Bm,
                  const float* __restrict__ bias,
                  float* __restrict__ C)
{
    constexpr int Bb = 128, Bn = 128, Bk = 16;
    __shared__ float As[Bk][Bb];   // transposed: As[k][m]
    __shared__ float Bs[Bk][Bn];

    const int tid = threadIdx.x;
    const int m0 = blockIdx.y * Bb;
    const int n0 = blockIdx.x * Bn;
    const int tx = tid & 15;
    const int ty = tid >> 4;

    float acc[8][8];
    #pragma unroll
    for (int i = 0; i < 8; i++)
        #pragma unroll
        for (int j = 0; j < 8; j++)
            acc[i][j] = 0.f;

    for (int k0 = 0; k0 < 1024; k0 += Bk) {
        // --- load A tile (128 rows x 16 cols), store transposed ---
        #pragma unroll
        for (int i = 0; i < 2; i++) {
            int id  = tid * 2 + i;       // 0..511
            int row = id >> 2;           // 0..127
            int c4  = (id & 3) * 4;      // 0,4,8,12
            const float* ap;
            if (MODE == 0) {
                ap = &A[(size_t)(m0 + row) * 1024 + k0 + c4];
            } else {
                int m  = m0 + row;
                int bb = m >> 11;        // / L
                int l  = m & 2047;
                int kk = k0 + c4;
                int h  = kk >> 6;
                int d  = kk & 63;
                ap = &A[(size_t)((bb * HH + h) * LL + l) * DKK + d];
            }
            float4 va = *(const float4*)ap;
            As[c4 + 0][row] = va.x;
            As[c4 + 1][row] = va.y;
            As[c4 + 2][row] = va.z;
            As[c4 + 3][row] = va.w;
        }
        // --- load B tile (16 rows x 128 cols) ---
        #pragma unroll
        for (int i = 0; i < 2; i++) {
            int id  = tid * 2 + i;       // 0..511
            int row = id >> 5;           // 0..15
            int c4  = (id & 31) * 4;     // 0..124
            *(float4*)&Bs[row][c4] =
                *(const float4*)&Bm[(size_t)(k0 + row) * 1024 + n0 + c4];
        }
        __syncthreads();

        #pragma unroll
        for (int k = 0; k < Bk; k++) {
            float4 a0 = *(const float4*)&As[k][ty * 4];
            float4 a1 = *(const float4*)&As[k][64 + ty * 4];
            float4 b0 = *(const float4*)&Bs[k][tx * 4];
            float4 b1 = *(const float4*)&Bs[k][64 + tx * 4];
            float a[8] = {a0.x, a0.y, a0.z, a0.w, a1.x, a1.y, a1.z, a1.w};
            float b[8] = {b0.x, b0.y, b0.z, b0.w, b1.x, b1.y, b1.z, b1.w};
            #pragma unroll
            for (int i = 0; i < 8; i++)
                #pragma unroll
                for (int j = 0; j < 8; j++)
                    acc[i][j] = fmaf(a[i], b[j], acc[i][j]);
        }
        __syncthreads();
    }

    // --- epilogue ---
    #pragma unroll
    for (int i = 0; i < 8; i++) {
        int m = m0 + ((i < 4) ? (ty * 4 + i) : (64 + ty * 4 + i - 4));
        #pragma unroll
        for (int j = 0; j < 8; j++) {
            int n = n0 + ((j < 4) ? (tx * 4 + j) : (64 + tx * 4 + j - 4));
            float v = acc[i][j] + bias[n];
            if (MODE == 0) {
                int bb = m >> 11, l = m & 2047;
                int h  = n >> 6,  d = n & 63;
                C[(size_t)((bb * HH + h) * LL + l) * DKK + d] = v;
            } else {
                C[(size_t)m * 1024 + n] = v;
            }
        }
    }
}

// ---------------------------------------------------------------------------
// Flash attention (non-causal): one query per thread, 128 queries per CTA.
// K/V tiles of 32x64 in smem, uniform-broadcast reads, online softmax.
// ---------------------------------------------------------------------------
__global__ __launch_bounds__(128)
void attn_kernel(const float* __restrict__ q,
                 const float* __restrict__ k,
                 const float* __restrict__ v,
                 float* __restrict__ ctx)
{
    constexpr int BQ = 128, BKT = 32;
    __shared__ float Ks[BKT * DKK];
    __shared__ float Vs[BKT * DKK];

    const int t  = threadIdx.x;
    const int bh = blockIdx.y;                 // 0..B*H-1
    const int qi = blockIdx.x * BQ + t;
    const size_t qbase = ((size_t)bh * LL + qi) * DKK;

    // Load & pre-scale the query row into registers
    float qr[DKK];
    #pragma unroll
    for (int d4 = 0; d4 < DKK / 4; d4++) {
        float4 vq = *(const float4*)&q[qbase + d4 * 4];
        qr[d4 * 4 + 0] = vq.x * 0.125f;   // 1/sqrt(64)
        qr[d4 * 4 + 1] = vq.y * 0.125f;
        qr[d4 * 4 + 2] = vq.z * 0.125f;
        qr[d4 * 4 + 3] = vq.w * 0.125f;
    }

    float acc[DKK];
    #pragma unroll
    for (int d = 0; d < DKK; d++) acc[d] = 0.f;
    float mi = -INFINITY, li = 0.f;

    const float* kb = &k[(size_t)bh * LL * DKK];
    const float* vb = &v[(size_t)bh * LL * DKK];

    for (int kt = 0; kt < LL; kt += BKT) {
        __syncthreads();
        // 32x64 tiles are 2048 contiguous floats each; flat float4 copy
        #pragma unroll
        for (int i = 0; i < (BKT * DKK) / (128 * 4); i++) {
            int idx = (i * 128 + t) * 4;
            *(float4*)&Ks[idx] = *(const float4*)&kb[(size_t)kt * DKK + idx];
            *(float4*)&Vs[idx] = *(const float4*)&vb[(size_t)kt * DKK + idx];
        }
        __syncthreads();

        // scores
        float s[BKT];
        #pragma unroll
        for (int j = 0; j < BKT; j++) {
            const float4* kr = (const float4*)&Ks[j * DKK];
            float sv = 0.f;
            #pragma unroll
            for (int d4 = 0; d4 < DKK / 4; d4++) {
                float4 kv = kr[d4];
                sv = fmaf(qr[d4 * 4 + 0], kv.x, sv);
                sv = fmaf(qr[d4 * 4 + 1], kv.y, sv);
                sv = fmaf(qr[d4 * 4 + 2], kv.z, sv);
                sv = fmaf(qr[d4 * 4 + 3], kv.w, sv);
            }
            s[j] = sv;
        }

        // online softmax update
        float tm = s[0];
        #pragma unroll
        for (int j = 1; j < BKT; j++) tm = fmaxf(tm, s[j]);
        float nm   = fmaxf(mi, tm);
        float corr = __expf(mi - nm);
        float ls   = 0.f;
        #pragma unroll
        for (int j = 0; j < BKT; j++) {
            s[j] = __expf(s[j] - nm);
            ls += s[j];
        }
        li = li * corr + ls;
        mi = nm;
        #pragma unroll
        for (int d = 0; d < DKK; d++) acc[d] *= corr;

        // P·V accumulate
        #pragma unroll
        for (int j = 0; j < BKT; j++) {
            float pj = s[j];
            const float4* vr = (const float4*)&Vs[j * DKK];
            #pragma unroll
            for (int d4 = 0; d4 < DKK / 4; d4++) {
                float4 vv = vr[d4];
                acc[d4 * 4 + 0] = fmaf(pj, vv.x, acc[d4 * 4 + 0]);
                acc[d4 * 4 + 1] = fmaf(pj, vv.y, acc[d4 * 4 + 1]);
                acc[d4 * 4 + 2] = fmaf(pj, vv.z, acc[d4 * 4 + 2]);
                acc[d4 * 4 + 3] = fmaf(pj, vv.w, acc[d4 * 4 + 3]);
            }
        }
    }

    float inv = 1.f / li;
    #pragma unroll
    for (int d4 = 0; d4 < DKK / 4; d4++) {
        float4 o;
        o.x = acc[d4 * 4 + 0] * inv;
        o.y = acc[d4 * 4 + 1] * inv;
        o.z = acc[d4 * 4 + 2] * inv;
        o.w = acc[d4 * 4 + 3] * inv;
        *(float4*)&ctx[qbase + d4 * 4] = o;
    }
}

// ---------------------------------------------------------------------------
extern "C" void kernel_launch(void* const* d_in, const int* in_sizes, int n_in,
                              void* d_out, int out_size)
{
    const float* x_q = (const float*)d_in[0];
    const float* x_k = (const float*)d_in[1];
    const float* x_v = (const float*)d_in[2];
    const float* Wq  = (const float*)d_in[3];
    const float* bq  = (const float*)d_in[4];
    const float* Wk  = (const float*)d_in[5];
    const float* bk  = (const float*)d_in[6];
    const float* Wv  = (const float*)d_in[7];
    const float* bv  = (const float*)d_in[8];
    const float* Wo  = (const float*)d_in[9];
    const float* bo  = (const float*)d_in[10];
    float* out = (float*)d_out;

    float *pq, *pk, *pv, *pctx;
    cudaGetSymbolAddress((void**)&pq,   g_q);
    cudaGetSymbolAddress((void**)&pk,   g_k);
    cudaGetSymbolAddress((void**)&pv,   g_v);
    cudaGetSymbolAddress((void**)&pctx, g_ctx);

    dim3 gemm_grid(NN / 128, MM / 128);   // (8, 32)
    sgemm_kernel<0><<<gemm_grid, 256>>>(x_q, Wq, bq, pq);
    sgemm_kernel<0><<<gemm_grid, 256>>>(x_k, Wk, bk, pk);
    sgemm_kernel<0><<<gemm_grid, 256>>>(x_v, Wv, bv, pv);

    dim3 attn_grid(LL / 128, BB * HH);    // (16, 32)
    attn_kernel<<<attn_grid, 128>>>(pq, pk, pv, pctx);

    sgemm_kernel<1><<<gemm_grid, 256>>>(pctx, Wo, bo, out);
}

// round 3
// speedup vs baseline: 1.2871x; 1.2871x over previous
#include <cuda_runtime.h>
#include <math.h>
#include <stdint.h>

// Problem dims
#define BB 2
#define LL 2048
#define DD 1024
#define HH 16
#define DKK 64
#define MM (BB*LL)     // 4096
#define NN 1024        // H*DK

// ---------------------------------------------------------------------------
// Device scratch (no cudaMalloc allowed)
// ---------------------------------------------------------------------------
__device__ float g_q  [BB*HH*LL*DKK];
__device__ float g_k  [BB*HH*LL*DKK];
__device__ float g_v  [BB*HH*LL*DKK];
__device__ float g_ctx[BB*HH*LL*DKK];

// ---------------------------------------------------------------------------
// Helpers (sm_100 baseline ISA only: mma.sync + cp.async, NO tcgen05)
// ---------------------------------------------------------------------------
__device__ __forceinline__ uint32_t smem_u32(const void* p) {
    uint32_t a;
    asm("{ .reg .u64 t; cvta.to.shared.u64 t, %1; cvt.u32.u64 %0, t; }"
        : "=r"(a) : "l"(p));
    return a;
}
__device__ __forceinline__ uint32_t tf32r(float x) {
    uint32_t o;
    asm("cvt.rna.tf32.f32 %0, %1;" : "=r"(o) : "f"(x));
    return o;
}

#define CP_ASYNC16(dst, src) \
    asm volatile("cp.async.cg.shared.global [%0], [%1], 16;" :: "r"(dst), "l"(src))
#define CP_COMMIT()  asm volatile("cp.async.commit_group;" ::: "memory")
#define CP_WAIT1()   asm volatile("cp.async.wait_group 1;" ::: "memory")
#define CP_WAIT0()   asm volatile("cp.async.wait_group 0;" ::: "memory")

// m16n8k8 tf32 MMA, fp32 accumulate
__device__ __forceinline__ void mma_tf32(float* c, const uint32_t* a, const uint32_t* b) {
    asm volatile(
        "mma.sync.aligned.m16n8k8.row.col.f32.tf32.tf32.f32 "
        "{%0,%1,%2,%3}, {%4,%5,%6,%7}, {%8,%9}, {%0,%1,%2,%3};"
        : "+f"(c[0]), "+f"(c[1]), "+f"(c[2]), "+f"(c[3])
        : "r"(a[0]), "r"(a[1]), "r"(a[2]), "r"(a[3]), "r"(b[0]), "r"(b[1]));
}

// ---------------------------------------------------------------------------
// tf32 tensor-core GEMM: C(4096x1024) = A(4096x1024) @ W(1024x1024) + bias
//   A row-major (M,K); W row-major (K,N). tf32 rounding applied in-register.
//   128x128 CTA tile, 8 warps (2x4), warp tile 64x32, K-chunk 32, cp.async
//   double buffered.
// MODE 0: A plain row-major, C scattered to (B,H,L,DK)
// MODE 1: A gathered from (B,H,L,DK) layout, C plain row-major
// ---------------------------------------------------------------------------
static constexpr int ASTR = 36;    // A smem row stride (floats): 16B aligned, conflict-free frags
static constexpr int BSTR = 136;   // B smem row stride (floats): 16B aligned, conflict-free frags
static constexpr int A_TILE = 128 * ASTR;           // floats
static constexpr int B_TILE = 32 * BSTR;            // floats
static constexpr int GSMEM  = (2 * A_TILE + 2 * B_TILE) * 4;   // 71680 bytes

template<int MODE>
__global__ __launch_bounds__(256, 1)
void gemm_mma(const float* __restrict__ A, const float* __restrict__ W,
              const float* __restrict__ bias, float* __restrict__ C)
{
    extern __shared__ float smem[];
    float* const Asm[2] = { smem,              smem + A_TILE };
    float* const Bsm[2] = { smem + 2 * A_TILE, smem + 2 * A_TILE + B_TILE };
    const uint32_t sa[2] = { smem_u32(Asm[0]), smem_u32(Asm[1]) };
    const uint32_t sb[2] = { smem_u32(Bsm[0]), smem_u32(Bsm[1]) };

    const int tid  = threadIdx.x;
    const int lane = tid & 31;
    const int wid  = tid >> 5;
    const int wm   = (wid >> 2) * 64;       // warp m offset in tile
    const int wn   = (wid & 3) * 32;        // warp n offset in tile
    const int gq   = lane >> 2;             // group id (0..7)
    const int gt   = lane & 3;              // thread-in-group (0..3)
    const int m0 = blockIdx.y * 128;
    const int n0 = blockIdx.x * 128;

    auto load_chunk = [&](int ck, int b) {
        const int k0 = ck * 32;
        // A tile: 128 rows x 32 cols -> 1024 16B chunks, 4 per thread
        #pragma unroll
        for (int i = 0; i < 4; i++) {
            const int id  = tid + 256 * i;
            const int row = id >> 3;
            const int cs  = id & 7;
            const float* ga;
            if (MODE == 0) {
                ga = &A[(size_t)(m0 + row) * 1024 + k0 + cs * 4];
            } else {
                const int m  = m0 + row;
                const int bb = m >> 11, l = m & 2047;
                const int kk = k0 + cs * 4;
                const int h  = kk >> 6, d = kk & 63;
                ga = &A[(size_t)((bb * HH + h) * LL + l) * DKK + d];
            }
            CP_ASYNC16(sa[b] + (uint32_t)(row * ASTR + cs * 4) * 4, ga);
        }
        // B tile: 32 rows x 128 cols -> 1024 16B chunks, 4 per thread
        #pragma unroll
        for (int i = 0; i < 4; i++) {
            const int id  = tid + 256 * i;
            const int row = id >> 5;
            const int cs  = id & 31;
            CP_ASYNC16(sb[b] + (uint32_t)(row * BSTR + cs * 4) * 4,
                       &W[(size_t)(k0 + row) * 1024 + n0 + cs * 4]);
        }
    };

    float c[4][4][4];
    #pragma unroll
    for (int mi = 0; mi < 4; mi++)
        #pragma unroll
        for (int ni = 0; ni < 4; ni++)
            #pragma unroll
            for (int r = 0; r < 4; r++) c[mi][ni][r] = 0.f;

    load_chunk(0, 0);
    CP_COMMIT();

    for (int ck = 0; ck < 32; ck++) {
        if (ck + 1 < 32) { load_chunk(ck + 1, (ck + 1) & 1); CP_COMMIT(); CP_WAIT1(); }
        else             { CP_WAIT0(); }
        __syncthreads();

        const float* As = Asm[ck & 1];
        const float* Bs = Bsm[ck & 1];
        #pragma unroll
        for (int ks = 0; ks < 4; ks++) {
            const int kc = ks * 8 + gt;
            uint32_t a[4][4];
            #pragma unroll
            for (int mi = 0; mi < 4; mi++) {
                const int row = wm + mi * 16 + gq;
                a[mi][0] = tf32r(As[row * ASTR + kc]);
                a[mi][1] = tf32r(As[(row + 8) * ASTR + kc]);
                a[mi][2] = tf32r(As[row * ASTR + kc + 4]);
                a[mi][3] = tf32r(As[(row + 8) * ASTR + kc + 4]);
            }
            uint32_t bf[4][2];
            #pragma unroll
            for (int ni = 0; ni < 4; ni++) {
                const int n = wn + ni * 8 + gq;
                bf[ni][0] = tf32r(Bs[kc * BSTR + n]);
                bf[ni][1] = tf32r(Bs[(kc + 4) * BSTR + n]);
            }
            #pragma unroll
            for (int mi = 0; mi < 4; mi++)
                #pragma unroll
                for (int ni = 0; ni < 4; ni++)
                    mma_tf32(c[mi][ni], a[mi], bf[ni]);
        }
        __syncthreads();
    }

    // Epilogue: add bias, scatter/store
    #pragma unroll
    for (int mi = 0; mi < 4; mi++) {
        const int row = m0 + wm + mi * 16 + gq;
        #pragma unroll
        for (int ni = 0; ni < 4; ni++) {
            const int col = n0 + wn + ni * 8 + 2 * gt;
            const float b0 = bias[col], b1 = bias[col + 1];
            float2 v0 = make_float2(c[mi][ni][0] + b0, c[mi][ni][1] + b1);
            float2 v1 = make_float2(c[mi][ni][2] + b0, c[mi][ni][3] + b1);
            if (MODE == 0) {
                const int h = col >> 6, d = col & 63;
                const int bb0 = row >> 11, l0 = row & 2047;
                *(float2*)&C[(size_t)((bb0 * HH + h) * LL + l0) * DKK + d] = v0;
                const int r8 = row + 8;
                const int bb1 = r8 >> 11, l1 = r8 & 2047;
                *(float2*)&C[(size_t)((bb1 * HH + h) * LL + l1) * DKK + d] = v1;
            } else {
                *(float2*)&C[(size_t)row * 1024 + col] = v0;
                *(float2*)&C[(size_t)(row + 8) * 1024 + col] = v1;
            }
        }
    }
}

// ---------------------------------------------------------------------------
// Flash attention (fp32, unchanged from round-1 passing version)
// ---------------------------------------------------------------------------
__global__ __launch_bounds__(128)
void attn_kernel(const float* __restrict__ q,
                 const float* __restrict__ k,
                 const float* __restrict__ v,
                 float* __restrict__ ctx)
{
    constexpr int BQ = 128, BKT = 32;
    __shared__ float Ks[BKT * DKK];
    __shared__ float Vs[BKT * DKK];

    const int t  = threadIdx.x;
    const int bh = blockIdx.y;
    const int qi = blockIdx.x * BQ + t;
    const size_t qbase = ((size_t)bh * LL + qi) * DKK;

    float qr[DKK];
    #pragma unroll
    for (int d4 = 0; d4 < DKK / 4; d4++) {
        float4 vq = *(const float4*)&q[qbase + d4 * 4];
        qr[d4 * 4 + 0] = vq.x * 0.125f;
        qr[d4 * 4 + 1] = vq.y * 0.125f;
        qr[d4 * 4 + 2] = vq.z * 0.125f;
        qr[d4 * 4 + 3] = vq.w * 0.125f;
    }

    float acc[DKK];
    #pragma unroll
    for (int d = 0; d < DKK; d++) acc[d] = 0.f;
    float mi = -INFINITY, li = 0.f;

    const float* kb = &k[(size_t)bh * LL * DKK];
    const float* vb = &v[(size_t)bh * LL * DKK];

    for (int kt = 0; kt < LL; kt += BKT) {
        __syncthreads();
        #pragma unroll
        for (int i = 0; i < (BKT * DKK) / (128 * 4); i++) {
            int idx = (i * 128 + t) * 4;
            *(float4*)&Ks[idx] = *(const float4*)&kb[(size_t)kt * DKK + idx];
            *(float4*)&Vs[idx] = *(const float4*)&vb[(size_t)kt * DKK + idx];
        }
        __syncthreads();

        float s[BKT];
        #pragma unroll
        for (int j = 0; j < BKT; j++) {
            const float4* kr = (const float4*)&Ks[j * DKK];
            float sv = 0.f;
            #pragma unroll
            for (int d4 = 0; d4 < DKK / 4; d4++) {
                float4 kv = kr[d4];
                sv = fmaf(qr[d4 * 4 + 0], kv.x, sv);
                sv = fmaf(qr[d4 * 4 + 1], kv.y, sv);
                sv = fmaf(qr[d4 * 4 + 2], kv.z, sv);
                sv = fmaf(qr[d4 * 4 + 3], kv.w, sv);
            }
            s[j] = sv;
        }

        float tm = s[0];
        #pragma unroll
        for (int j = 1; j < BKT; j++) tm = fmaxf(tm, s[j]);
        float nm   = fmaxf(mi, tm);
        float corr = __expf(mi - nm);
        float ls   = 0.f;
        #pragma unroll
        for (int j = 0; j < BKT; j++) {
            s[j] = __expf(s[j] - nm);
            ls += s[j];
        }
        li = li * corr + ls;
        mi = nm;
        #pragma unroll
        for (int d = 0; d < DKK; d++) acc[d] *= corr;

        #pragma unroll
        for (int j = 0; j < BKT; j++) {
            float pj = s[j];
            const float4* vr = (const float4*)&Vs[j * DKK];
            #pragma unroll
            for (int d4 = 0; d4 < DKK / 4; d4++) {
                float4 vv = vr[d4];
                acc[d4 * 4 + 0] = fmaf(pj, vv.x, acc[d4 * 4 + 0]);
                acc[d4 * 4 + 1] = fmaf(pj, vv.y, acc[d4 * 4 + 1]);
                acc[d4 * 4 + 2] = fmaf(pj, vv.z, acc[d4 * 4 + 2]);
                acc[d4 * 4 + 3] = fmaf(pj, vv.w, acc[d4 * 4 + 3]);
            }
        }
    }

    float inv = 1.f / li;
    #pragma unroll
    for (int d4 = 0; d4 < DKK / 4; d4++) {
        float4 o;
        o.x = acc[d4 * 4 + 0] * inv;
        o.y = acc[d4 * 4 + 1] * inv;
        o.z = acc[d4 * 4 + 2] * inv;
        o.w = acc[d4 * 4 + 3] * inv;
        *(float4*)&ctx[qbase + d4 * 4] = o;
    }
}

// ---------------------------------------------------------------------------
extern "C" void kernel_launch(void* const* d_in, const int* in_sizes, int n_in,
                              void* d_out, int out_size)
{
    const float* x_q = (const float*)d_in[0];
    const float* x_k = (const float*)d_in[1];
    const float* x_v = (const float*)d_in[2];
    const float* Wq  = (const float*)d_in[3];
    const float* bq  = (const float*)d_in[4];
    const float* Wk  = (const float*)d_in[5];
    const float* bk  = (const float*)d_in[6];
    const float* Wv  = (const float*)d_in[7];
    const float* bv  = (const float*)d_in[8];
    const float* Wo  = (const float*)d_in[9];
    const float* bo  = (const float*)d_in[10];
    float* out = (float*)d_out;

    float *pq, *pk, *pv, *pctx;
    cudaGetSymbolAddress((void**)&pq,   g_q);
    cudaGetSymbolAddress((void**)&pk,   g_k);
    cudaGetSymbolAddress((void**)&pv,   g_v);
    cudaGetSymbolAddress((void**)&pctx, g_ctx);

    cudaFuncSetAttribute(gemm_mma<0>, cudaFuncAttributeMaxDynamicSharedMemorySize, GSMEM);
    cudaFuncSetAttribute(gemm_mma<1>, cudaFuncAttributeMaxDynamicSharedMemorySize, GSMEM);

    dim3 ggrid(8, 32);                 // (n tiles, m tiles)
    dim3 agrid(LL / 128, BB * HH);

    gemm_mma<0><<<ggrid, 256, GSMEM>>>(x_q, Wq, bq, pq);
    gemm_mma<0><<<ggrid, 256, GSMEM>>>(x_k, Wk, bk, pk);
    gemm_mma<0><<<ggrid, 256, GSMEM>>>(x_v, Wv, bv, pv);

    attn_kernel<<<agrid, 128>>>(pq, pk, pv, pctx);

    gemm_mma<1><<<ggrid, 256, GSMEM>>>(pctx, Wo, bo, out);
}

// round 4
// speedup vs baseline: 2.9877x; 2.3213x over previous
#include <cuda_runtime.h>
#include <math.h>
#include <stdint.h>

// Problem dims
#define BB 2
#define LL 2048
#define DD 1024
#define HH 16
#define DKK 64
#define MM (BB*LL)     // 4096
#define NN 1024        // H*DK

// ---------------------------------------------------------------------------
// Device scratch (no cudaMalloc allowed)
// ---------------------------------------------------------------------------
__device__ float g_q  [BB*HH*LL*DKK];
__device__ float g_k  [BB*HH*LL*DKK];
__device__ float g_v  [BB*HH*LL*DKK];
__device__ float g_ctx[BB*HH*LL*DKK];

// ---------------------------------------------------------------------------
// Helpers (sm_100 baseline ISA: mma.sync + cp.async; NO tcgen05)
// ---------------------------------------------------------------------------
__device__ __forceinline__ uint32_t smem_u32(const void* p) {
    uint32_t a;
    asm("{ .reg .u64 t; cvta.to.shared.u64 t, %1; cvt.u32.u64 %0, t; }"
        : "=r"(a) : "l"(p));
    return a;
}
__device__ __forceinline__ uint32_t tf32r(float x) {
    uint32_t o;
    asm("cvt.rna.tf32.f32 %0, %1;" : "=r"(o) : "f"(x));
    return o;
}

#define CP_ASYNC16(dst, src) \
    asm volatile("cp.async.cg.shared.global [%0], [%1], 16;" :: "r"(dst), "l"(src))
#define CP_COMMIT()  asm volatile("cp.async.commit_group;" ::: "memory")
#define CP_WAIT1()   asm volatile("cp.async.wait_group 1;" ::: "memory")
#define CP_WAIT0()   asm volatile("cp.async.wait_group 0;" ::: "memory")

// m16n8k8 tf32 MMA, fp32 accumulate
__device__ __forceinline__ void mma_tf32(float* c, const uint32_t* a, const uint32_t* b) {
    asm volatile(
        "mma.sync.aligned.m16n8k8.row.col.f32.tf32.tf32.f32 "
        "{%0,%1,%2,%3}, {%4,%5,%6,%7}, {%8,%9}, {%0,%1,%2,%3};"
        : "+f"(c[0]), "+f"(c[1]), "+f"(c[2]), "+f"(c[3])
        : "r"(a[0]), "r"(a[1]), "r"(a[2]), "r"(a[3]), "r"(b[0]), "r"(b[1]));
}

// ---------------------------------------------------------------------------
// tf32 tensor-core GEMM: C(4096x1024) = A(4096x1024) @ W(1024x1024) + bias
// MODE 0: A plain row-major, C scattered to (B,H,L,DK)
// MODE 1: A gathered from (B,H,L,DK) layout, C plain row-major
// RND  1: round output to tf32 (and multiply by exact-pow2 scale) so the
//         attention kernel can consume operands without any cvt.
// ---------------------------------------------------------------------------
static constexpr int ASTR = 36;
static constexpr int BSTR = 136;
static constexpr int A_TILE = 128 * ASTR;
static constexpr int B_TILE = 32 * BSTR;
static constexpr int GSMEM  = (2 * A_TILE + 2 * B_TILE) * 4;   // 71680 bytes

template<int MODE, int RND>
__global__ __launch_bounds__(256, 1)
void gemm_mma(const float* __restrict__ A, const float* __restrict__ W,
              const float* __restrict__ bias, float* __restrict__ C, float scale)
{
    extern __shared__ float smem[];
    float* const Asm[2] = { smem,              smem + A_TILE };
    float* const Bsm[2] = { smem + 2 * A_TILE, smem + 2 * A_TILE + B_TILE };
    const uint32_t sa[2] = { smem_u32(Asm[0]), smem_u32(Asm[1]) };
    const uint32_t sb[2] = { smem_u32(Bsm[0]), smem_u32(Bsm[1]) };

    const int tid  = threadIdx.x;
    const int lane = tid & 31;
    const int wid  = tid >> 5;
    const int wm   = (wid >> 2) * 64;
    const int wn   = (wid & 3) * 32;
    const int gq   = lane >> 2;
    const int gt   = lane & 3;
    const int m0 = blockIdx.y * 128;
    const int n0 = blockIdx.x * 128;

    auto load_chunk = [&](int ck, int b) {
        const int k0 = ck * 32;
        #pragma unroll
        for (int i = 0; i < 4; i++) {
            const int id  = tid + 256 * i;
            const int row = id >> 3;
            const int cs  = id & 7;
            const float* ga;
            if (MODE == 0) {
                ga = &A[(size_t)(m0 + row) * 1024 + k0 + cs * 4];
            } else {
                const int m  = m0 + row;
                const int bb = m >> 11, l = m & 2047;
                const int kk = k0 + cs * 4;
                const int h  = kk >> 6, d = kk & 63;
                ga = &A[(size_t)((bb * HH + h) * LL + l) * DKK + d];
            }
            CP_ASYNC16(sa[b] + (uint32_t)(row * ASTR + cs * 4) * 4, ga);
        }
        #pragma unroll
        for (int i = 0; i < 4; i++) {
            const int id  = tid + 256 * i;
            const int row = id >> 5;
            const int cs  = id & 31;
            CP_ASYNC16(sb[b] + (uint32_t)(row * BSTR + cs * 4) * 4,
                       &W[(size_t)(k0 + row) * 1024 + n0 + cs * 4]);
        }
    };

    float c[4][4][4];
    #pragma unroll
    for (int mi = 0; mi < 4; mi++)
        #pragma unroll
        for (int ni = 0; ni < 4; ni++)
            #pragma unroll
            for (int r = 0; r < 4; r++) c[mi][ni][r] = 0.f;

    load_chunk(0, 0);
    CP_COMMIT();

    for (int ck = 0; ck < 32; ck++) {
        if (ck + 1 < 32) { load_chunk(ck + 1, (ck + 1) & 1); CP_COMMIT(); CP_WAIT1(); }
        else             { CP_WAIT0(); }
        __syncthreads();

        const float* As = Asm[ck & 1];
        const float* Bs = Bsm[ck & 1];
        #pragma unroll
        for (int ks = 0; ks < 4; ks++) {
            const int kc = ks * 8 + gt;
            uint32_t a[4][4];
            #pragma unroll
            for (int mi = 0; mi < 4; mi++) {
                const int row = wm + mi * 16 + gq;
                a[mi][0] = tf32r(As[row * ASTR + kc]);
                a[mi][1] = tf32r(As[(row + 8) * ASTR + kc]);
                a[mi][2] = tf32r(As[row * ASTR + kc + 4]);
                a[mi][3] = tf32r(As[(row + 8) * ASTR + kc + 4]);
            }
            uint32_t bf[4][2];
            #pragma unroll
            for (int ni = 0; ni < 4; ni++) {
                const int n = wn + ni * 8 + gq;
                bf[ni][0] = tf32r(Bs[kc * BSTR + n]);
                bf[ni][1] = tf32r(Bs[(kc + 4) * BSTR + n]);
            }
            #pragma unroll
            for (int mi = 0; mi < 4; mi++)
                #pragma unroll
                for (int ni = 0; ni < 4; ni++)
                    mma_tf32(c[mi][ni], a[mi], bf[ni]);
        }
        __syncthreads();
    }

    // Epilogue
    #pragma unroll
    for (int mi = 0; mi < 4; mi++) {
        const int row = m0 + wm + mi * 16 + gq;
        #pragma unroll
        for (int ni = 0; ni < 4; ni++) {
            const int col = n0 + wn + ni * 8 + 2 * gt;
            const float b0 = bias[col], b1 = bias[col + 1];
            float vals[4] = { c[mi][ni][0] + b0, c[mi][ni][1] + b1,
                              c[mi][ni][2] + b0, c[mi][ni][3] + b1 };
            if (RND) {
                #pragma unroll
                for (int r = 0; r < 4; r++)
                    vals[r] = __uint_as_float(tf32r(vals[r])) * scale;
            }
            float2 v0 = make_float2(vals[0], vals[1]);
            float2 v1 = make_float2(vals[2], vals[3]);
            if (MODE == 0) {
                const int h = col >> 6, d = col & 63;
                const int bb0 = row >> 11, l0 = row & 2047;
                *(float2*)&C[(size_t)((bb0 * HH + h) * LL + l0) * DKK + d] = v0;
                const int r8 = row + 8;
                const int bb1 = r8 >> 11, l1 = r8 & 2047;
                *(float2*)&C[(size_t)((bb1 * HH + h) * LL + l1) * DKK + d] = v1;
            } else {
                *(float2*)&C[(size_t)row * 1024 + col] = v0;
                *(float2*)&C[(size_t)(row + 8) * 1024 + col] = v1;
            }
        }
    }
}

// ---------------------------------------------------------------------------
// Tensor-core flash attention.
//   CTA: 128 q rows, 8 warps (16 rows each), KV tile 64, cp.async dbl-buffer.
//   Inputs pre-rounded to tf32 (Q also pre-scaled by 1/8) by GEMM epilogues.
//   S = Q@K^T via m16n8k8 (K rows are col-major B directly).
//   P@V: P bounced via smem (warp-private rows); V read scalar as B(k,n).
//   Conflict-free strides: KSTR/PSTR=68, VSTR=72.
// ---------------------------------------------------------------------------
static constexpr int ATT_BM = 128;
static constexpr int KSTR = 68, VSTR = 72, PSTR = 68;
static constexpr int SK0 = 0;
static constexpr int SK1 = SK0 + 64 * KSTR;
static constexpr int SV0 = SK1 + 64 * KSTR;
static constexpr int SV1 = SV0 + 64 * VSTR;
static constexpr int SP  = SV1 + 64 * VSTR;
static constexpr int ATT_SMEM = (SP + ATT_BM * PSTR) * 4;   // 106496 bytes

__global__ __launch_bounds__(256, 1)
void attn_mma(const float* __restrict__ q, const float* __restrict__ k,
              const float* __restrict__ v, float* __restrict__ ctx)
{
    extern __shared__ float sm[];
    const uint32_t sb = smem_u32(sm);
    const int tid = threadIdx.x, lane = tid & 31, wid = tid >> 5;
    const int gq = lane >> 2, gt = lane & 3;
    const int wm = wid * 16;
    const int bh = blockIdx.y;
    const int q0 = blockIdx.x * ATT_BM;
    const float* kb = k + (size_t)bh * LL * DKK;
    const float* vb = v + (size_t)bh * LL * DKK;

    // Stage Q tile into Ps, build warp-resident A fragments (already tf32)
    {
        const int row = tid >> 1, d0 = (tid & 1) * 32;
        const float* gp = q + ((size_t)bh * LL + q0 + row) * DKK + d0;
        #pragma unroll
        for (int i = 0; i < 8; i++)
            *(float4*)&sm[SP + row * PSTR + d0 + i * 4] = *(const float4*)&gp[i * 4];
    }
    __syncthreads();
    uint32_t aq[8][4];
    #pragma unroll
    for (int s = 0; s < 8; s++) {
        aq[s][0] = __float_as_uint(sm[SP + (wm + gq) * PSTR + s * 8 + gt]);
        aq[s][1] = __float_as_uint(sm[SP + (wm + gq + 8) * PSTR + s * 8 + gt]);
        aq[s][2] = __float_as_uint(sm[SP + (wm + gq) * PSTR + s * 8 + gt + 4]);
        aq[s][3] = __float_as_uint(sm[SP + (wm + gq + 8) * PSTR + s * 8 + gt + 4]);
    }

    float co[8][4];
    #pragma unroll
    for (int ni = 0; ni < 8; ni++)
        #pragma unroll
        for (int r = 0; r < 4; r++) co[ni][r] = 0.f;
    float m0 = -INFINITY, m1 = -INFINITY, l0 = 0.f, l1 = 0.f;

    auto load_kv = [&](int kt, int b) {
        const int koff = b ? SK1 : SK0, voff = b ? SV1 : SV0;
        #pragma unroll
        for (int i = 0; i < 4; i++) {
            const int id = tid + 256 * i;
            const int row = id >> 4, c = id & 15;
            CP_ASYNC16(sb + (uint32_t)(koff + row * KSTR + c * 4) * 4,
                       &kb[((size_t)kt * 64 + row) * DKK + c * 4]);
            CP_ASYNC16(sb + (uint32_t)(voff + row * VSTR + c * 4) * 4,
                       &vb[((size_t)kt * 64 + row) * DKK + c * 4]);
        }
    };
    load_kv(0, 0); CP_COMMIT();

    for (int kt = 0; kt < LL / 64; kt++) {
        __syncthreads();   // prior iteration done reading the buffer we refill
        if (kt + 1 < LL / 64) { load_kv(kt + 1, (kt + 1) & 1); CP_COMMIT(); CP_WAIT1(); }
        else                  { CP_WAIT0(); }
        __syncthreads();
        const int kbuf = (kt & 1) ? SK1 : SK0;
        const int vbuf = (kt & 1) ? SV1 : SV0;

        // S = Q @ K^T
        float sc[8][4];
        #pragma unroll
        for (int ni = 0; ni < 8; ni++)
            #pragma unroll
            for (int r = 0; r < 4; r++) sc[ni][r] = 0.f;
        #pragma unroll
        for (int s = 0; s < 8; s++) {
            uint32_t bf[8][2];
            #pragma unroll
            for (int ni = 0; ni < 8; ni++) {
                bf[ni][0] = __float_as_uint(sm[kbuf + (ni * 8 + gq) * KSTR + s * 8 + gt]);
                bf[ni][1] = __float_as_uint(sm[kbuf + (ni * 8 + gq) * KSTR + s * 8 + gt + 4]);
            }
            #pragma unroll
            for (int ni = 0; ni < 8; ni++)
                mma_tf32(sc[ni], aq[s], bf[ni]);
        }

        // Online softmax (rows gq and gq+8 of this warp's 16-row block)
        float rm0 = sc[0][0], rm1 = sc[0][2];
        #pragma unroll
        for (int ni = 0; ni < 8; ni++) {
            rm0 = fmaxf(rm0, fmaxf(sc[ni][0], sc[ni][1]));
            rm1 = fmaxf(rm1, fmaxf(sc[ni][2], sc[ni][3]));
        }
        rm0 = fmaxf(rm0, __shfl_xor_sync(0xffffffff, rm0, 1));
        rm0 = fmaxf(rm0, __shfl_xor_sync(0xffffffff, rm0, 2));
        rm1 = fmaxf(rm1, __shfl_xor_sync(0xffffffff, rm1, 1));
        rm1 = fmaxf(rm1, __shfl_xor_sync(0xffffffff, rm1, 2));
        const float nm0 = fmaxf(m0, rm0), nm1 = fmaxf(m1, rm1);
        const float cr0 = __expf(m0 - nm0), cr1 = __expf(m1 - nm1);
        float rs0 = 0.f, rs1 = 0.f;
        #pragma unroll
        for (int ni = 0; ni < 8; ni++) {
            const float e00 = __expf(sc[ni][0] - nm0);
            const float e01 = __expf(sc[ni][1] - nm0);
            const float e10 = __expf(sc[ni][2] - nm1);
            const float e11 = __expf(sc[ni][3] - nm1);
            rs0 += e00 + e01;
            rs1 += e10 + e11;
            const int col = ni * 8 + 2 * gt;
            float2 p0 = make_float2(__uint_as_float(tf32r(e00)), __uint_as_float(tf32r(e01)));
            float2 p1 = make_float2(__uint_as_float(tf32r(e10)), __uint_as_float(tf32r(e11)));
            *(float2*)&sm[SP + (wm + gq) * PSTR + col] = p0;
            *(float2*)&sm[SP + (wm + gq + 8) * PSTR + col] = p1;
        }
        rs0 += __shfl_xor_sync(0xffffffff, rs0, 1);
        rs0 += __shfl_xor_sync(0xffffffff, rs0, 2);
        rs1 += __shfl_xor_sync(0xffffffff, rs1, 1);
        rs1 += __shfl_xor_sync(0xffffffff, rs1, 2);
        m0 = nm0; m1 = nm1;
        l0 = l0 * cr0 + rs0;
        l1 = l1 * cr1 + rs1;
        #pragma unroll
        for (int ni = 0; ni < 8; ni++) {
            co[ni][0] *= cr0; co[ni][1] *= cr0;
            co[ni][2] *= cr1; co[ni][3] *= cr1;
        }

        // ctx += P @ V
        #pragma unroll
        for (int s = 0; s < 8; s++) {
            uint32_t ap[4] = {
                __float_as_uint(sm[SP + (wm + gq) * PSTR + s * 8 + gt]),
                __float_as_uint(sm[SP + (wm + gq + 8) * PSTR + s * 8 + gt]),
                __float_as_uint(sm[SP + (wm + gq) * PSTR + s * 8 + gt + 4]),
                __float_as_uint(sm[SP + (wm + gq + 8) * PSTR + s * 8 + gt + 4]) };
            uint32_t bv_[8][2];
            #pragma unroll
            for (int ni = 0; ni < 8; ni++) {
                bv_[ni][0] = __float_as_uint(sm[vbuf + (s * 8 + gt) * VSTR + ni * 8 + gq]);
                bv_[ni][1] = __float_as_uint(sm[vbuf + (s * 8 + gt + 4) * VSTR + ni * 8 + gq]);
            }
            #pragma unroll
            for (int ni = 0; ni < 8; ni++)
                mma_tf32(co[ni], ap, bv_[ni]);
        }
    }

    // Epilogue: normalize + store ctx (fp32; out-proj GEMM rounds in-register)
    const float inv0 = 1.f / l0, inv1 = 1.f / l1;
    const int row0 = q0 + wm + gq, row1 = row0 + 8;
    #pragma unroll
    for (int ni = 0; ni < 8; ni++) {
        const int col = ni * 8 + 2 * gt;
        float2 o0 = make_float2(co[ni][0] * inv0, co[ni][1] * inv0);
        float2 o1 = make_float2(co[ni][2] * inv1, co[ni][3] * inv1);
        *(float2*)&ctx[((size_t)bh * LL + row0) * DKK + col] = o0;
        *(float2*)&ctx[((size_t)bh * LL + row1) * DKK + col] = o1;
    }
}

// ---------------------------------------------------------------------------
extern "C" void kernel_launch(void* const* d_in, const int* in_sizes, int n_in,
                              void* d_out, int out_size)
{
    const float* x_q = (const float*)d_in[0];
    const float* x_k = (const float*)d_in[1];
    const float* x_v = (const float*)d_in[2];
    const float* Wq  = (const float*)d_in[3];
    const float* bq  = (const float*)d_in[4];
    const float* Wk  = (const float*)d_in[5];
    const float* bk  = (const float*)d_in[6];
    const float* Wv  = (const float*)d_in[7];
    const float* bv  = (const float*)d_in[8];
    const float* Wo  = (const float*)d_in[9];
    const float* bo  = (const float*)d_in[10];
    float* out = (float*)d_out;

    float *pq, *pk, *pv, *pctx;
    cudaGetSymbolAddress((void**)&pq,   g_q);
    cudaGetSymbolAddress((void**)&pk,   g_k);
    cudaGetSymbolAddress((void**)&pv,   g_v);
    cudaGetSymbolAddress((void**)&pctx, g_ctx);

    cudaFuncSetAttribute(gemm_mma<0,1>, cudaFuncAttributeMaxDynamicSharedMemorySize, GSMEM);
    cudaFuncSetAttribute(gemm_mma<1,0>, cudaFuncAttributeMaxDynamicSharedMemorySize, GSMEM);
    cudaFuncSetAttribute(attn_mma,      cudaFuncAttributeMaxDynamicSharedMemorySize, ATT_SMEM);

    dim3 ggrid(8, 32);
    dim3 agrid(LL / ATT_BM, BB * HH);   // (16, 32)

    gemm_mma<0,1><<<ggrid, 256, GSMEM>>>(x_q, Wq, bq, pq, 0.125f);  // Q: tf32 + 1/sqrt(dk)
    gemm_mma<0,1><<<ggrid, 256, GSMEM>>>(x_k, Wk, bk, pk, 1.0f);    // K: tf32
    gemm_mma<0,1><<<ggrid, 256, GSMEM>>>(x_v, Wv, bv, pv, 1.0f);    // V: tf32

    attn_mma<<<agrid, 256, ATT_SMEM>>>(pq, pk, pv, pctx);

    gemm_mma<1,0><<<ggrid, 256, GSMEM>>>(pctx, Wo, bo, out, 1.0f);
}

// round 5
// speedup vs baseline: 3.1906x; 1.0679x over previous
#include <cuda_runtime.h>
#include <math.h>
#include <stdint.h>

// Problem dims
#define BB 2
#define LL 2048
#define DD 1024
#define HH 16
#define DKK 64
#define MM (BB*LL)     // 4096
#define NN 1024        // H*DK

// ---------------------------------------------------------------------------
// Device scratch (no cudaMalloc allowed)
// ---------------------------------------------------------------------------
__device__ float g_q  [BB*HH*LL*DKK];   // (b,h,l,dk)
__device__ float g_k  [BB*HH*LL*DKK];   // (b,h,l,dk)
__device__ float g_v  [BB*HH*LL*DKK];   // (b,h,dk,l)  TRANSPOSED for ldmatrix
__device__ float g_ctx[BB*HH*LL*DKK];   // (b,h,l,dk)  tf32-rounded
__device__ float g_xq [MM*DD];          // tf32-rounded activations
__device__ float g_xk [MM*DD];
__device__ float g_xv [MM*DD];
__device__ float g_wt [4 * DD * NN];    // W^T, tf32-rounded: Wt[n][k]

// ---------------------------------------------------------------------------
// Helpers (sm_100 baseline ISA: mma.sync + cp.async + ldmatrix)
// ---------------------------------------------------------------------------
__device__ __forceinline__ uint32_t smem_u32(const void* p) {
    uint32_t a;
    asm("{ .reg .u64 t; cvta.to.shared.u64 t, %1; cvt.u32.u64 %0, t; }"
        : "=r"(a) : "l"(p));
    return a;
}
__device__ __forceinline__ uint32_t tf32r(float x) {
    uint32_t o;
    asm("cvt.rna.tf32.f32 %0, %1;" : "=r"(o) : "f"(x));
    return o;
}

#define CP_ASYNC16(dst, src) \
    asm volatile("cp.async.cg.shared.global [%0], [%1], 16;" :: "r"(dst), "l"(src))
#define CP_COMMIT()  asm volatile("cp.async.commit_group;" ::: "memory")
#define CP_WAIT1()   asm volatile("cp.async.wait_group 1;" ::: "memory")
#define CP_WAIT0()   asm volatile("cp.async.wait_group 0;" ::: "memory")

// m16n8k8 tf32 MMA, fp32 accumulate
__device__ __forceinline__ void mma_tf32(float* c, const uint32_t* a, const uint32_t* b) {
    asm volatile(
        "mma.sync.aligned.m16n8k8.row.col.f32.tf32.tf32.f32 "
        "{%0,%1,%2,%3}, {%4,%5,%6,%7}, {%8,%9}, {%0,%1,%2,%3};"
        : "+f"(c[0]), "+f"(c[1]), "+f"(c[2]), "+f"(c[3])
        : "r"(a[0]), "r"(a[1]), "r"(a[2]), "r"(a[3]), "r"(b[0]), "r"(b[1]));
}

// ldmatrix x4 on fp32 data: each 8x4-float piece == one 8x8 b16 matrix.
// Lane L of a piece receives (row L>>2, float-col L&3) == tf32 fragment layout.
__device__ __forceinline__ void ldsm4(uint32_t* r, uint32_t addr) {
    asm volatile("ldmatrix.sync.aligned.m8n8.x4.shared.b16 {%0,%1,%2,%3}, [%4];"
                 : "=r"(r[0]), "=r"(r[1]), "=r"(r[2]), "=r"(r[3]) : "r"(addr));
}

// ---------------------------------------------------------------------------
// Pre-pass 1: transpose + round weights  Wt[n][k] = rn_tf32(W[k][n])
// ---------------------------------------------------------------------------
__global__ __launch_bounds__(256)
void transpose_round(const float* __restrict__ W, float* __restrict__ Wt)
{
    __shared__ float t[32][33];
    int x = blockIdx.x * 32 + threadIdx.x;
    int y = blockIdx.y * 32 + threadIdx.y;
    #pragma unroll
    for (int i = 0; i < 32; i += 8)
        t[threadIdx.y + i][threadIdx.x] = W[(size_t)(y + i) * 1024 + x];
    __syncthreads();
    x = blockIdx.y * 32 + threadIdx.x;
    y = blockIdx.x * 32 + threadIdx.y;
    #pragma unroll
    for (int i = 0; i < 32; i += 8)
        Wt[(size_t)(y + i) * 1024 + x] = __uint_as_float(tf32r(t[threadIdx.x][threadIdx.y + i]));
}

// ---------------------------------------------------------------------------
// Pre-pass 2: round activations to tf32
// ---------------------------------------------------------------------------
__global__ __launch_bounds__(256)
void round_copy(const float* __restrict__ in, float* __restrict__ out)
{
    int i = blockIdx.x * 256 + threadIdx.x;
    float4 v = *(const float4*)&in[(size_t)i * 4];
    v.x = __uint_as_float(tf32r(v.x));
    v.y = __uint_as_float(tf32r(v.y));
    v.z = __uint_as_float(tf32r(v.z));
    v.w = __uint_as_float(tf32r(v.w));
    *(float4*)&out[(size_t)i * 4] = v;
}

// ---------------------------------------------------------------------------
// tf32 GEMM via ldmatrix: C(4096x1024) = A @ Wt^T + bias
//   A: [m][k] rows (pre-rounded tf32); Wt: [n][k] rows (pre-rounded tf32).
//   128x128 CTA tile, 8 warps (2x4), warp 64x32, K-chunk 32, dbl-buffered.
// MODE 0: A plain rows, C scattered to (b,h,l,dk)
// MODE 1: A gathered from (b,h,l,dk), C plain rows
// MODE 2: A plain rows, C scattered TRANSPOSED to (b,h,dk,l)   [V]
// RND  1: round output to tf32 and multiply by exact-pow2 scale
// ---------------------------------------------------------------------------
static constexpr int GSTR  = 36;                 // tile row stride (floats)
static constexpr int GTILE = 128 * GSTR;
static constexpr int GSMEM = 4 * GTILE * 4;      // 73728 bytes

template<int MODE, int RND>
__global__ __launch_bounds__(256, 1)
void gemm_ld(const float* __restrict__ A, const float* __restrict__ Wt,
             const float* __restrict__ bias, float* __restrict__ C, float scale)
{
    extern __shared__ float smem[];
    // [As0][As1][Bs0][Bs1]
    const uint32_t sb = smem_u32(smem);
    const uint32_t sa[2] = { sb,             sb + GTILE * 4 };
    const uint32_t sw[2] = { sb + 2u * GTILE * 4, sb + 3u * GTILE * 4 };

    const int tid  = threadIdx.x;
    const int lane = tid & 31;
    const int wid  = tid >> 5;
    const int wm   = (wid >> 2) * 64;
    const int wn   = (wid & 3) * 32;
    const int gq   = lane >> 2;
    const int gt   = lane & 3;
    const int l7   = lane & 7;
    const int lg8  = (lane >> 3) & 1;
    const int lg16 = lane >> 4;
    const int m0 = blockIdx.y * 128;
    const int n0 = blockIdx.x * 128;

    // per-lane ldmatrix base offsets (floats)
    const int aBase = (wm + l7 + lg8 * 8) * GSTR + lg16 * 4;       // +mi*16*GSTR +ks*8
    const int bBase = (wn + lg16 * 8 + l7) * GSTR + lg8 * 4;       // +nb*16*GSTR +ks*8

    auto load_chunk = [&](int ck, int b) {
        const int k0 = ck * 32;
        #pragma unroll
        for (int i = 0; i < 4; i++) {
            const int id  = tid + 256 * i;
            const int row = id >> 3;
            const int cs  = id & 7;
            const float* ga;
            if (MODE != 1) {
                ga = &A[(size_t)(m0 + row) * 1024 + k0 + cs * 4];
            } else {
                const int m  = m0 + row;
                const int bb = m >> 11, l = m & 2047;
                const int kk = k0 + cs * 4;
                const int h  = kk >> 6, d = kk & 63;
                ga = &A[(size_t)((bb * HH + h) * LL + l) * DKK + d];
            }
            CP_ASYNC16(sa[b] + (uint32_t)(row * GSTR + cs * 4) * 4, ga);
            CP_ASYNC16(sw[b] + (uint32_t)(row * GSTR + cs * 4) * 4,
                       &Wt[(size_t)(n0 + row) * 1024 + k0 + cs * 4]);
        }
    };

    float c[4][4][4];
    #pragma unroll
    for (int mi = 0; mi < 4; mi++)
        #pragma unroll
        for (int ni = 0; ni < 4; ni++)
            #pragma unroll
            for (int r = 0; r < 4; r++) c[mi][ni][r] = 0.f;

    load_chunk(0, 0);
    CP_COMMIT();

    for (int ck = 0; ck < 32; ck++) {
        if (ck + 1 < 32) { load_chunk(ck + 1, (ck + 1) & 1); CP_COMMIT(); CP_WAIT1(); }
        else             { CP_WAIT0(); }
        __syncthreads();
        const uint32_t As = sa[ck & 1], Ws = sw[ck & 1];

        #pragma unroll
        for (int ks = 0; ks < 4; ks++) {
            uint32_t a[4][4];
            #pragma unroll
            for (int mi = 0; mi < 4; mi++)
                ldsm4(a[mi], As + (uint32_t)(aBase + mi * 16 * GSTR + ks * 8) * 4);
            uint32_t b[4][2];
            #pragma unroll
            for (int nb = 0; nb < 2; nb++) {
                uint32_t r[4];
                ldsm4(r, Ws + (uint32_t)(bBase + nb * 16 * GSTR + ks * 8) * 4);
                b[nb * 2][0] = r[0]; b[nb * 2][1] = r[1];
                b[nb * 2 + 1][0] = r[2]; b[nb * 2 + 1][1] = r[3];
            }
            #pragma unroll
            for (int mi = 0; mi < 4; mi++)
                #pragma unroll
                for (int ni = 0; ni < 4; ni++)
                    mma_tf32(c[mi][ni], a[mi], b[ni]);
        }
        __syncthreads();
    }

    // Epilogue
    #pragma unroll
    for (int mi = 0; mi < 4; mi++) {
        const int row = m0 + wm + mi * 16 + gq;
        #pragma unroll
        for (int ni = 0; ni < 4; ni++) {
            const int col = n0 + wn + ni * 8 + 2 * gt;
            const float b0 = bias[col], b1 = bias[col + 1];
            float vals[4] = { c[mi][ni][0] + b0, c[mi][ni][1] + b1,
                              c[mi][ni][2] + b0, c[mi][ni][3] + b1 };
            if (RND) {
                #pragma unroll
                for (int r = 0; r < 4; r++)
                    vals[r] = __uint_as_float(tf32r(vals[r])) * scale;
            }
            if (MODE == 0) {
                const int h = col >> 6, d = col & 63;
                const int bb0 = row >> 11, l0 = row & 2047;
                *(float2*)&C[(size_t)((bb0 * HH + h) * LL + l0) * DKK + d] =
                    make_float2(vals[0], vals[1]);
                const int r8 = row + 8;
                const int bb1 = r8 >> 11, l1 = r8 & 2047;
                *(float2*)&C[(size_t)((bb1 * HH + h) * LL + l1) * DKK + d] =
                    make_float2(vals[2], vals[3]);
            } else if (MODE == 1) {
                *(float2*)&C[(size_t)row * 1024 + col] = make_float2(vals[0], vals[1]);
                *(float2*)&C[(size_t)(row + 8) * 1024 + col] = make_float2(vals[2], vals[3]);
            } else {   // MODE 2: transposed V scatter (b,h,dk,l)
                const int h = col >> 6, d = col & 63;
                const int bb0 = row >> 11, l0 = row & 2047;
                const int r8 = row + 8;
                const int bb1 = r8 >> 11, l1 = r8 & 2047;
                C[((size_t)(bb0 * HH + h) * DKK + d)     * LL + l0] = vals[0];
                C[((size_t)(bb0 * HH + h) * DKK + d + 1) * LL + l0] = vals[1];
                C[((size_t)(bb1 * HH + h) * DKK + d)     * LL + l1] = vals[2];
                C[((size_t)(bb1 * HH + h) * DKK + d + 1) * LL + l1] = vals[3];
            }
        }
    }
}

// ---------------------------------------------------------------------------
// Tensor-core flash attention with ldmatrix fragment loads.
//   CTA: 128 q rows, 8 warps (16 rows each), KV tile 64, cp.async dbl-buffer.
//   Q/K (b,h,l,dk) pre-rounded tf32; V (b,h,dk,l) pre-rounded tf32.
//   K smem [kv][d] -> B-frags for S;  V smem [d][kv] -> B-frags for P@V.
//   P bounced via warp-private smem rows, A-frags via ldmatrix.
// ---------------------------------------------------------------------------
static constexpr int ATT_BM = 128;
static constexpr int TSTR = 68;
static constexpr int SK0 = 0;
static constexpr int SK1 = SK0 + 64 * TSTR;
static constexpr int SV0 = SK1 + 64 * TSTR;
static constexpr int SV1 = SV0 + 64 * TSTR;
static constexpr int SP  = SV1 + 64 * TSTR;
static constexpr int ATT_SMEM = (SP + ATT_BM * TSTR) * 4;   // 104448 bytes

__global__ __launch_bounds__(256, 1)
void attn_mma(const float* __restrict__ q, const float* __restrict__ k,
              const float* __restrict__ v, float* __restrict__ ctx)
{
    extern __shared__ float sm[];
    const uint32_t sb = smem_u32(sm);
    const int tid = threadIdx.x, lane = tid & 31, wid = tid >> 5;
    const int gq = lane >> 2, gt = lane & 3;
    const int l7 = lane & 7, lg8 = (lane >> 3) & 1, lg16 = lane >> 4;
    const int wm = wid * 16;
    const int bh = blockIdx.y;
    const int q0 = blockIdx.x * ATT_BM;
    const float* kb = k + (size_t)bh * LL * DKK;
    const float* vb = v + (size_t)bh * DKK * LL;

    // ldmatrix per-lane bases (floats)
    const int aBase = (wm + l7 + lg8 * 8) * TSTR + lg16 * 4;   // A-type (P/Q): +s*8
    const int bBase = (lg16 * 8 + l7) * TSTR + lg8 * 4;        // B-type (K/V): +nb*16*TSTR +s*8

    // Stage Q tile into P region; build persistent A fragments
    {
        const int row = tid >> 1, d0 = (tid & 1) * 32;
        const float* gp = q + ((size_t)bh * LL + q0 + row) * DKK + d0;
        #pragma unroll
        for (int i = 0; i < 8; i++)
            *(float4*)&sm[SP + row * TSTR + d0 + i * 4] = *(const float4*)&gp[i * 4];
    }
    __syncthreads();
    uint32_t aq[8][4];
    #pragma unroll
    for (int s = 0; s < 8; s++)
        ldsm4(aq[s], sb + (uint32_t)(SP + aBase + s * 8) * 4);

    float co[8][4];
    #pragma unroll
    for (int ni = 0; ni < 8; ni++)
        #pragma unroll
        for (int r = 0; r < 4; r++) co[ni][r] = 0.f;
    float m0 = -INFINITY, m1 = -INFINITY, l0 = 0.f, l1 = 0.f;

    auto load_kv = [&](int kt, int b) {
        const int koff = b ? SK1 : SK0, voff = b ? SV1 : SV0;
        #pragma unroll
        for (int i = 0; i < 4; i++) {
            const int id = tid + 256 * i;
            const int row = id >> 4, c = id & 15;
            CP_ASYNC16(sb + (uint32_t)(koff + row * TSTR + c * 4) * 4,
                       &kb[((size_t)kt * 64 + row) * DKK + c * 4]);
            CP_ASYNC16(sb + (uint32_t)(voff + row * TSTR + c * 4) * 4,
                       &vb[(size_t)row * LL + kt * 64 + c * 4]);
        }
    };
    load_kv(0, 0); CP_COMMIT();

    for (int kt = 0; kt < LL / 64; kt++) {
        __syncthreads();
        if (kt + 1 < LL / 64) { load_kv(kt + 1, (kt + 1) & 1); CP_COMMIT(); CP_WAIT1(); }
        else                  { CP_WAIT0(); }
        __syncthreads();
        const int kbuf = (kt & 1) ? SK1 : SK0;
        const int vbuf = (kt & 1) ? SV1 : SV0;

        // S = Q @ K^T
        float sc[8][4];
        #pragma unroll
        for (int ni = 0; ni < 8; ni++)
            #pragma unroll
            for (int r = 0; r < 4; r++) sc[ni][r] = 0.f;
        #pragma unroll
        for (int s = 0; s < 8; s++) {
            uint32_t bf[8][2];
            #pragma unroll
            for (int nb = 0; nb < 4; nb++) {
                uint32_t r[4];
                ldsm4(r, sb + (uint32_t)(kbuf + bBase + nb * 16 * TSTR + s * 8) * 4);
                bf[nb * 2][0] = r[0]; bf[nb * 2][1] = r[1];
                bf[nb * 2 + 1][0] = r[2]; bf[nb * 2 + 1][1] = r[3];
            }
            #pragma unroll
            for (int ni = 0; ni < 8; ni++)
                mma_tf32(sc[ni], aq[s], bf[ni]);
        }

        // Online softmax
        float rm0 = sc[0][0], rm1 = sc[0][2];
        #pragma unroll
        for (int ni = 0; ni < 8; ni++) {
            rm0 = fmaxf(rm0, fmaxf(sc[ni][0], sc[ni][1]));
            rm1 = fmaxf(rm1, fmaxf(sc[ni][2], sc[ni][3]));
        }
        rm0 = fmaxf(rm0, __shfl_xor_sync(0xffffffff, rm0, 1));
        rm0 = fmaxf(rm0, __shfl_xor_sync(0xffffffff, rm0, 2));
        rm1 = fmaxf(rm1, __shfl_xor_sync(0xffffffff, rm1, 1));
        rm1 = fmaxf(rm1, __shfl_xor_sync(0xffffffff, rm1, 2));
        const float nm0 = fmaxf(m0, rm0), nm1 = fmaxf(m1, rm1);
        const float cr0 = __expf(m0 - nm0), cr1 = __expf(m1 - nm1);
        float rs0 = 0.f, rs1 = 0.f;
        #pragma unroll
        for (int ni = 0; ni < 8; ni++) {
            const float e00 = __expf(sc[ni][0] - nm0);
            const float e01 = __expf(sc[ni][1] - nm0);
            const float e10 = __expf(sc[ni][2] - nm1);
            const float e11 = __expf(sc[ni][3] - nm1);
            rs0 += e00 + e01;
            rs1 += e10 + e11;
            const int col = ni * 8 + 2 * gt;
            *(float2*)&sm[SP + (wm + gq) * TSTR + col] =
                make_float2(__uint_as_float(tf32r(e00)), __uint_as_float(tf32r(e01)));
            *(float2*)&sm[SP + (wm + gq + 8) * TSTR + col] =
                make_float2(__uint_as_float(tf32r(e10)), __uint_as_float(tf32r(e11)));
        }
        rs0 += __shfl_xor_sync(0xffffffff, rs0, 1);
        rs0 += __shfl_xor_sync(0xffffffff, rs0, 2);
        rs1 += __shfl_xor_sync(0xffffffff, rs1, 1);
        rs1 += __shfl_xor_sync(0xffffffff, rs1, 2);
        m0 = nm0; m1 = nm1;
        l0 = l0 * cr0 + rs0;
        l1 = l1 * cr1 + rs1;
        #pragma unroll
        for (int ni = 0; ni < 8; ni++) {
            co[ni][0] *= cr0; co[ni][1] *= cr0;
            co[ni][2] *= cr1; co[ni][3] *= cr1;
        }
        __syncwarp();   // P rows are warp-private; order STS before ldmatrix

        // ctx += P @ V
        #pragma unroll
        for (int s = 0; s < 8; s++) {
            uint32_t ap[4];
            ldsm4(ap, sb + (uint32_t)(SP + aBase + s * 8) * 4);
            uint32_t bv_[8][2];
            #pragma unroll
            for (int nb = 0; nb < 4; nb++) {
                uint32_t r[4];
                ldsm4(r, sb + (uint32_t)(vbuf + bBase + nb * 16 * TSTR + s * 8) * 4);
                bv_[nb * 2][0] = r[0]; bv_[nb * 2][1] = r[1];
                bv_[nb * 2 + 1][0] = r[2]; bv_[nb * 2 + 1][1] = r[3];
            }
            #pragma unroll
            for (int ni = 0; ni < 8; ni++)
                mma_tf32(co[ni], ap, bv_[ni]);
        }
        __syncwarp();
    }

    // Epilogue: normalize, round to tf32 (out-proj consumes without cvt)
    const float inv0 = 1.f / l0, inv1 = 1.f / l1;
    const int row0 = q0 + wm + gq, row1 = row0 + 8;
    #pragma unroll
    for (int ni = 0; ni < 8; ni++) {
        const int col = ni * 8 + 2 * gt;
        float2 o0 = make_float2(__uint_as_float(tf32r(co[ni][0] * inv0)),
                                __uint_as_float(tf32r(co[ni][1] * inv0)));
        float2 o1 = make_float2(__uint_as_float(tf32r(co[ni][2] * inv1)),
                                __uint_as_float(tf32r(co[ni][3] * inv1)));
        *(float2*)&ctx[((size_t)bh * LL + row0) * DKK + col] = o0;
        *(float2*)&ctx[((size_t)bh * LL + row1) * DKK + col] = o1;
    }
}

// ---------------------------------------------------------------------------
extern "C" void kernel_launch(void* const* d_in, const int* in_sizes, int n_in,
                              void* d_out, int out_size)
{
    const float* x_q = (const float*)d_in[0];
    const float* x_k = (const float*)d_in[1];
    const float* x_v = (const float*)d_in[2];
    const float* Wq  = (const float*)d_in[3];
    const float* bq  = (const float*)d_in[4];
    const float* Wk  = (const float*)d_in[5];
    const float* bk  = (const float*)d_in[6];
    const float* Wv  = (const float*)d_in[7];
    const float* bv  = (const float*)d_in[8];
    const float* Wo  = (const float*)d_in[9];
    const float* bo  = (const float*)d_in[10];
    float* out = (float*)d_out;

    float *pq, *pk, *pv, *pctx, *pxq, *pxk, *pxv, *pwt;
    cudaGetSymbolAddress((void**)&pq,   g_q);
    cudaGetSymbolAddress((void**)&pk,   g_k);
    cudaGetSymbolAddress((void**)&pv,   g_v);
    cudaGetSymbolAddress((void**)&pctx, g_ctx);
    cudaGetSymbolAddress((void**)&pxq,  g_xq);
    cudaGetSymbolAddress((void**)&pxk,  g_xk);
    cudaGetSymbolAddress((void**)&pxv,  g_xv);
    cudaGetSymbolAddress((void**)&pwt,  g_wt);
    float* wtq = pwt;
    float* wtk = pwt + 1 * DD * NN;
    float* wtv = pwt + 2 * DD * NN;
    float* wto = pwt + 3 * DD * NN;

    cudaFuncSetAttribute(gemm_ld<0,1>, cudaFuncAttributeMaxDynamicSharedMemorySize, GSMEM);
    cudaFuncSetAttribute(gemm_ld<2,1>, cudaFuncAttributeMaxDynamicSharedMemorySize, GSMEM);
    cudaFuncSetAttribute(gemm_ld<1,0>, cudaFuncAttributeMaxDynamicSharedMemorySize, GSMEM);
    cudaFuncSetAttribute(attn_mma,     cudaFuncAttributeMaxDynamicSharedMemorySize, ATT_SMEM);

    dim3 tgrid(32, 32), tblk(32, 8);
    dim3 ggrid(8, 32);
    dim3 agrid(LL / ATT_BM, BB * HH);
    const int rblocks = (MM * DD) / (256 * 4);

    transpose_round<<<tgrid, tblk>>>(Wq, wtq);
    transpose_round<<<tgrid, tblk>>>(Wk, wtk);
    transpose_round<<<tgrid, tblk>>>(Wv, wtv);
    transpose_round<<<tgrid, tblk>>>(Wo, wto);
    round_copy<<<rblocks, 256>>>(x_q, pxq);
    round_copy<<<rblocks, 256>>>(x_k, pxk);
    round_copy<<<rblocks, 256>>>(x_v, pxv);

    gemm_ld<0,1><<<ggrid, 256, GSMEM>>>(pxq, wtq, bq, pq, 0.125f);  // Q (pre-scaled)
    gemm_ld<0,1><<<ggrid, 256, GSMEM>>>(pxk, wtk, bk, pk, 1.0f);    // K
    gemm_ld<2,1><<<ggrid, 256, GSMEM>>>(pxv, wtv, bv, pv, 1.0f);    // V (transposed out)

    attn_mma<<<agrid, 256, ATT_SMEM>>>(pq, pk, pv, pctx);

    gemm_ld<1,0><<<ggrid, 256, GSMEM>>>(pctx, wto, bo, out, 1.0f);  // out-proj
}

// round 6
// speedup vs baseline: 3.8073x; 1.1933x over previous
#include <cuda_runtime.h>
#include <math.h>
#include <stdint.h>

// Problem dims
#define BB 2
#define LL 2048
#define DD 1024
#define HH 16
#define DKK 64
#define MM (BB*LL)     // 4096
#define NN 1024        // H*DK

// ---------------------------------------------------------------------------
// Device scratch (no cudaMalloc allowed)
// ---------------------------------------------------------------------------
__device__ float g_q  [BB*HH*LL*DKK];   // (b,h,l,dk)   tf32, pre-scaled 1/8
__device__ float g_k  [BB*HH*LL*DKK];   // (b,h,l,dk)   tf32
__device__ float g_v  [BB*HH*LL*DKK];   // (b,h,dk,l)   tf32, transposed
__device__ float g_ctx[BB*HH*LL*DKK];   // (b,h,l,dk)   tf32
__device__ float g_wt [4 * DD * NN];    // W^T, tf32-rounded: Wt[n][k]

// ---------------------------------------------------------------------------
// Helpers (sm_100 baseline ISA: mma.sync + cp.async + ldmatrix)
// ---------------------------------------------------------------------------
__device__ __forceinline__ uint32_t smem_u32(const void* p) {
    uint32_t a;
    asm("{ .reg .u64 t; cvta.to.shared.u64 t, %1; cvt.u32.u64 %0, t; }"
        : "=r"(a) : "l"(p));
    return a;
}
__device__ __forceinline__ uint32_t tf32r(float x) {
    uint32_t o;
    asm("cvt.rna.tf32.f32 %0, %1;" : "=r"(o) : "f"(x));
    return o;
}
__device__ __forceinline__ uint32_t tf32ru(uint32_t x) {
    uint32_t o;
    asm("cvt.rna.tf32.f32 %0, %1;" : "=r"(o) : "f"(__uint_as_float(x)));
    return o;
}

#define CP_ASYNC16(dst, src) \
    asm volatile("cp.async.cg.shared.global [%0], [%1], 16;" :: "r"(dst), "l"(src))
#define CP_COMMIT()  asm volatile("cp.async.commit_group;" ::: "memory")
#define CP_WAIT1()   asm volatile("cp.async.wait_group 1;" ::: "memory")
#define CP_WAIT0()   asm volatile("cp.async.wait_group 0;" ::: "memory")

// m16n8k8 tf32 MMA, fp32 accumulate
__device__ __forceinline__ void mma_tf32(float* c, const uint32_t* a, const uint32_t* b) {
    asm volatile(
        "mma.sync.aligned.m16n8k8.row.col.f32.tf32.tf32.f32 "
        "{%0,%1,%2,%3}, {%4,%5,%6,%7}, {%8,%9}, {%0,%1,%2,%3};"
        : "+f"(c[0]), "+f"(c[1]), "+f"(c[2]), "+f"(c[3])
        : "r"(a[0]), "r"(a[1]), "r"(a[2]), "r"(a[3]), "r"(b[0]), "r"(b[1]));
}

// ldmatrix x4 on fp32 data: each 8x4-float piece == one 8x8 b16 matrix.
__device__ __forceinline__ void ldsm4(uint32_t* r, uint32_t addr) {
    asm volatile("ldmatrix.sync.aligned.m8n8.x4.shared.b16 {%0,%1,%2,%3}, [%4];"
                 : "=r"(r[0]), "=r"(r[1]), "=r"(r[2]), "=r"(r[3]) : "r"(addr));
}

// ---------------------------------------------------------------------------
// Fused pre-pass: transpose + tf32-round all four weights (grid.z selects)
// ---------------------------------------------------------------------------
__global__ __launch_bounds__(256)
void transpose_round4(const float* __restrict__ W0, const float* __restrict__ W1,
                      const float* __restrict__ W2, const float* __restrict__ W3,
                      float* __restrict__ T)
{
    const float* W = (blockIdx.z == 0) ? W0 : (blockIdx.z == 1) ? W1
                   : (blockIdx.z == 2) ? W2 : W3;
    float* Wt = T + (size_t)blockIdx.z * DD * NN;
    __shared__ float t[32][33];
    int x = blockIdx.x * 32 + threadIdx.x;
    int y = blockIdx.y * 32 + threadIdx.y;
    #pragma unroll
    for (int i = 0; i < 32; i += 8)
        t[threadIdx.y + i][threadIdx.x] = W[(size_t)(y + i) * 1024 + x];
    __syncthreads();
    x = blockIdx.y * 32 + threadIdx.x;
    y = blockIdx.x * 32 + threadIdx.y;
    #pragma unroll
    for (int i = 0; i < 32; i += 8)
        Wt[(size_t)(y + i) * 1024 + x] = __uint_as_float(tf32r(t[threadIdx.x][threadIdx.y + i]));
}

// ---------------------------------------------------------------------------
// tf32 GEMM via ldmatrix, 3-stage cp.async pipeline, 1 barrier per chunk.
//   A: [m][k] rows; Wt: [n][k] rows (pre-rounded tf32).
//   128x128 CTA tile, 8 warps (2x4), warp 64x32, K-chunk 32.
// MODE 0: A plain rows, C scattered to (b,h,l,dk)
// MODE 1: A gathered from (b,h,l,dk), C plain rows
// MODE 2: A plain rows, C scattered TRANSPOSED to (b,h,dk,l)   [V]
// RND 1: round output to tf32, multiply by exact-pow2 scale
// CVT 1: A is raw fp32 -> round A-fragments after ldmatrix
// ---------------------------------------------------------------------------
static constexpr int GSTR  = 36;                  // row stride (floats)
static constexpr int GTILE = 128 * GSTR;          // one A or B tile (floats)
static constexpr int GSMEM = 6 * GTILE * 4;       // 3 stages x (A+B) = 110592 B

template<int MODE, int RND, int CVT>
__global__ __launch_bounds__(256, 1)
void gemm_ld(const float* __restrict__ A, const float* __restrict__ Wt,
             const float* __restrict__ bias, float* __restrict__ C, float scale)
{
    extern __shared__ float smem[];
    const uint32_t sb = smem_u32(smem);
    // layout: [A0][B0][A1][B1][A2][B2]
    const int tid  = threadIdx.x;
    const int lane = tid & 31;
    const int wid  = tid >> 5;
    const int wm   = (wid >> 2) * 64;
    const int wn   = (wid & 3) * 32;
    const int gq   = lane >> 2;
    const int gt   = lane & 3;
    const int l7   = lane & 7;
    const int lg8  = (lane >> 3) & 1;
    const int lg16 = lane >> 4;
    const int m0 = blockIdx.y * 128;
    const int n0 = blockIdx.x * 128;

    const int aBase = (wm + l7 + lg8 * 8) * GSTR + lg16 * 4;
    const int bBase = (wn + lg16 * 8 + l7) * GSTR + lg8 * 4;

    auto load_chunk = [&](int ck, int st) {
        const int k0 = ck * 32;
        const uint32_t sa = sb + (uint32_t)(2 * st) * GTILE * 4;
        const uint32_t sw = sb + (uint32_t)(2 * st + 1) * GTILE * 4;
        #pragma unroll
        for (int i = 0; i < 4; i++) {
            const int id  = tid + 256 * i;
            const int row = id >> 3;
            const int cs  = id & 7;
            const float* ga;
            if (MODE != 1) {
                ga = &A[(size_t)(m0 + row) * 1024 + k0 + cs * 4];
            } else {
                const int m  = m0 + row;
                const int bb = m >> 11, l = m & 2047;
                const int kk = k0 + cs * 4;
                const int h  = kk >> 6, d = kk & 63;
                ga = &A[(size_t)((bb * HH + h) * LL + l) * DKK + d];
            }
            CP_ASYNC16(sa + (uint32_t)(row * GSTR + cs * 4) * 4, ga);
            CP_ASYNC16(sw + (uint32_t)(row * GSTR + cs * 4) * 4,
                       &Wt[(size_t)(n0 + row) * 1024 + k0 + cs * 4]);
        }
    };

    float c[4][4][4];
    #pragma unroll
    for (int mi = 0; mi < 4; mi++)
        #pragma unroll
        for (int ni = 0; ni < 4; ni++)
            #pragma unroll
            for (int r = 0; r < 4; r++) c[mi][ni][r] = 0.f;

    load_chunk(0, 0); CP_COMMIT();
    load_chunk(1, 1); CP_COMMIT();

    for (int ck = 0; ck < 32; ck++) {
        if (ck < 31) CP_WAIT1(); else CP_WAIT0();
        __syncthreads();
        const int st = ck % 3;
        const uint32_t As = sb + (uint32_t)(2 * st) * GTILE * 4;
        const uint32_t Ws = sb + (uint32_t)(2 * st + 1) * GTILE * 4;

        #pragma unroll
        for (int ks = 0; ks < 4; ks++) {
            uint32_t a[4][4];
            #pragma unroll
            for (int mi = 0; mi < 4; mi++) {
                ldsm4(a[mi], As + (uint32_t)(aBase + mi * 16 * GSTR + ks * 8) * 4);
                if (CVT) {
                    #pragma unroll
                    for (int r = 0; r < 4; r++) a[mi][r] = tf32ru(a[mi][r]);
                }
            }
            uint32_t b[4][2];
            #pragma unroll
            for (int nb = 0; nb < 2; nb++) {
                uint32_t r[4];
                ldsm4(r, Ws + (uint32_t)(bBase + nb * 16 * GSTR + ks * 8) * 4);
                b[nb * 2][0] = r[0]; b[nb * 2][1] = r[1];
                b[nb * 2 + 1][0] = r[2]; b[nb * 2 + 1][1] = r[3];
            }
            #pragma unroll
            for (int mi = 0; mi < 4; mi++)
                #pragma unroll
                for (int ni = 0; ni < 4; ni++)
                    mma_tf32(c[mi][ni], a[mi], b[ni]);
        }
        if (ck + 2 < 32) { load_chunk(ck + 2, (ck + 2) % 3); CP_COMMIT(); }
    }

    // Epilogue
    #pragma unroll
    for (int mi = 0; mi < 4; mi++) {
        const int row = m0 + wm + mi * 16 + gq;
        #pragma unroll
        for (int ni = 0; ni < 4; ni++) {
            const int col = n0 + wn + ni * 8 + 2 * gt;
            const float b0 = bias[col], b1 = bias[col + 1];
            float vals[4] = { c[mi][ni][0] + b0, c[mi][ni][1] + b1,
                              c[mi][ni][2] + b0, c[mi][ni][3] + b1 };
            if (RND) {
                #pragma unroll
                for (int r = 0; r < 4; r++)
                    vals[r] = __uint_as_float(tf32r(vals[r])) * scale;
            }
            if (MODE == 0) {
                const int h = col >> 6, d = col & 63;
                const int bb0 = row >> 11, l0 = row & 2047;
                *(float2*)&C[(size_t)((bb0 * HH + h) * LL + l0) * DKK + d] =
                    make_float2(vals[0], vals[1]);
                const int r8 = row + 8;
                const int bb1 = r8 >> 11, l1 = r8 & 2047;
                *(float2*)&C[(size_t)((bb1 * HH + h) * LL + l1) * DKK + d] =
                    make_float2(vals[2], vals[3]);
            } else if (MODE == 1) {
                *(float2*)&C[(size_t)row * 1024 + col] = make_float2(vals[0], vals[1]);
                *(float2*)&C[(size_t)(row + 8) * 1024 + col] = make_float2(vals[2], vals[3]);
            } else {   // MODE 2: transposed V scatter (b,h,dk,l)
                const int h = col >> 6, d = col & 63;
                const int bb0 = row >> 11, l0 = row & 2047;
                const int r8 = row + 8;
                const int bb1 = r8 >> 11, l1 = r8 & 2047;
                C[((size_t)(bb0 * HH + h) * DKK + d)     * LL + l0] = vals[0];
                C[((size_t)(bb0 * HH + h) * DKK + d + 1) * LL + l0] = vals[1];
                C[((size_t)(bb1 * HH + h) * DKK + d)     * LL + l1] = vals[2];
                C[((size_t)(bb1 * HH + h) * DKK + d + 1) * LL + l1] = vals[3];
            }
        }
    }
}

// ---------------------------------------------------------------------------
// Tensor-core flash attention (ldmatrix), 2 CTAs/SM via launch_bounds(256,2).
// ---------------------------------------------------------------------------
static constexpr int ATT_BM = 128;
static constexpr int TSTR = 68;
static constexpr int SK0 = 0;
static constexpr int SK1 = SK0 + 64 * TSTR;
static constexpr int SV0 = SK1 + 64 * TSTR;
static constexpr int SV1 = SV0 + 64 * TSTR;
static constexpr int SP  = SV1 + 64 * TSTR;
static constexpr int ATT_SMEM = (SP + ATT_BM * TSTR) * 4;   // 104448 bytes

__global__ __launch_bounds__(256, 2)
void attn_mma(const float* __restrict__ q, const float* __restrict__ k,
              const float* __restrict__ v, float* __restrict__ ctx)
{
    extern __shared__ float sm[];
    const uint32_t sb = smem_u32(sm);
    const int tid = threadIdx.x, lane = tid & 31, wid = tid >> 5;
    const int gq = lane >> 2, gt = lane & 3;
    const int l7 = lane & 7, lg8 = (lane >> 3) & 1, lg16 = lane >> 4;
    const int wm = wid * 16;
    const int bh = blockIdx.y;
    const int q0 = blockIdx.x * ATT_BM;
    const float* kb = k + (size_t)bh * LL * DKK;
    const float* vb = v + (size_t)bh * DKK * LL;

    const int aBase = (wm + l7 + lg8 * 8) * TSTR + lg16 * 4;
    const int bBase = (lg16 * 8 + l7) * TSTR + lg8 * 4;

    // Stage Q tile into P region; build persistent A fragments
    {
        const int row = tid >> 1, d0 = (tid & 1) * 32;
        const float* gp = q + ((size_t)bh * LL + q0 + row) * DKK + d0;
        #pragma unroll
        for (int i = 0; i < 8; i++)
            *(float4*)&sm[SP + row * TSTR + d0 + i * 4] = *(const float4*)&gp[i * 4];
    }
    __syncthreads();
    uint32_t aq[8][4];
    #pragma unroll
    for (int s = 0; s < 8; s++)
        ldsm4(aq[s], sb + (uint32_t)(SP + aBase + s * 8) * 4);

    float co[8][4];
    #pragma unroll
    for (int ni = 0; ni < 8; ni++)
        #pragma unroll
        for (int r = 0; r < 4; r++) co[ni][r] = 0.f;
    float m0 = -INFINITY, m1 = -INFINITY, l0 = 0.f, l1 = 0.f;

    auto load_kv = [&](int kt, int b) {
        const int koff = b ? SK1 : SK0, voff = b ? SV1 : SV0;
        #pragma unroll
        for (int i = 0; i < 4; i++) {
            const int id = tid + 256 * i;
            const int row = id >> 4, c = id & 15;
            CP_ASYNC16(sb + (uint32_t)(koff + row * TSTR + c * 4) * 4,
                       &kb[((size_t)kt * 64 + row) * DKK + c * 4]);
            CP_ASYNC16(sb + (uint32_t)(voff + row * TSTR + c * 4) * 4,
                       &vb[(size_t)row * LL + kt * 64 + c * 4]);
        }
    };
    load_kv(0, 0); CP_COMMIT();

    for (int kt = 0; kt < LL / 64; kt++) {
        __syncthreads();
        if (kt + 1 < LL / 64) { load_kv(kt + 1, (kt + 1) & 1); CP_COMMIT(); CP_WAIT1(); }
        else                  { CP_WAIT0(); }
        __syncthreads();
        const int kbuf = (kt & 1) ? SK1 : SK0;
        const int vbuf = (kt & 1) ? SV1 : SV0;

        // S = Q @ K^T
        float sc[8][4];
        #pragma unroll
        for (int ni = 0; ni < 8; ni++)
            #pragma unroll
            for (int r = 0; r < 4; r++) sc[ni][r] = 0.f;
        #pragma unroll
        for (int s = 0; s < 8; s++) {
            uint32_t bf[8][2];
            #pragma unroll
            for (int nb = 0; nb < 4; nb++) {
                uint32_t r[4];
                ldsm4(r, sb + (uint32_t)(kbuf + bBase + nb * 16 * TSTR + s * 8) * 4);
                bf[nb * 2][0] = r[0]; bf[nb * 2][1] = r[1];
                bf[nb * 2 + 1][0] = r[2]; bf[nb * 2 + 1][1] = r[3];
            }
            #pragma unroll
            for (int ni = 0; ni < 8; ni++)
                mma_tf32(sc[ni], aq[s], bf[ni]);
        }

        // Online softmax
        float rm0 = sc[0][0], rm1 = sc[0][2];
        #pragma unroll
        for (int ni = 0; ni < 8; ni++) {
            rm0 = fmaxf(rm0, fmaxf(sc[ni][0], sc[ni][1]));
            rm1 = fmaxf(rm1, fmaxf(sc[ni][2], sc[ni][3]));
        }
        rm0 = fmaxf(rm0, __shfl_xor_sync(0xffffffff, rm0, 1));
        rm0 = fmaxf(rm0, __shfl_xor_sync(0xffffffff, rm0, 2));
        rm1 = fmaxf(rm1, __shfl_xor_sync(0xffffffff, rm1, 1));
        rm1 = fmaxf(rm1, __shfl_xor_sync(0xffffffff, rm1, 2));
        const float nm0 = fmaxf(m0, rm0), nm1 = fmaxf(m1, rm1);
        const float cr0 = __expf(m0 - nm0), cr1 = __expf(m1 - nm1);
        float rs0 = 0.f, rs1 = 0.f;
        #pragma unroll
        for (int ni = 0; ni < 8; ni++) {
            const float e00 = __expf(sc[ni][0] - nm0);
            const float e01 = __expf(sc[ni][1] - nm0);
            const float e10 = __expf(sc[ni][2] - nm1);
            const float e11 = __expf(sc[ni][3] - nm1);
            rs0 += e00 + e01;
            rs1 += e10 + e11;
            const int col = ni * 8 + 2 * gt;
            *(float2*)&sm[SP + (wm + gq) * TSTR + col] =
                make_float2(__uint_as_float(tf32r(e00)), __uint_as_float(tf32r(e01)));
            *(float2*)&sm[SP + (wm + gq + 8) * TSTR + col] =
                make_float2(__uint_as_float(tf32r(e10)), __uint_as_float(tf32r(e11)));
        }
        rs0 += __shfl_xor_sync(0xffffffff, rs0, 1);
        rs0 += __shfl_xor_sync(0xffffffff, rs0, 2);
        rs1 += __shfl_xor_sync(0xffffffff, rs1, 1);
        rs1 += __shfl_xor_sync(0xffffffff, rs1, 2);
        m0 = nm0; m1 = nm1;
        l0 = l0 * cr0 + rs0;
        l1 = l1 * cr1 + rs1;
        #pragma unroll
        for (int ni = 0; ni < 8; ni++) {
            co[ni][0] *= cr0; co[ni][1] *= cr0;
            co[ni][2] *= cr1; co[ni][3] *= cr1;
        }
        __syncwarp();   // P rows are warp-private; order STS before ldmatrix

        // ctx += P @ V
        #pragma unroll
        for (int s = 0; s < 8; s++) {
            uint32_t ap[4];
            ldsm4(ap, sb + (uint32_t)(SP + aBase + s * 8) * 4);
            uint32_t bv_[8][2];
            #pragma unroll
            for (int nb = 0; nb < 4; nb++) {
                uint32_t r[4];
                ldsm4(r, sb + (uint32_t)(vbuf + bBase + nb * 16 * TSTR + s * 8) * 4);
                bv_[nb * 2][0] = r[0]; bv_[nb * 2][1] = r[1];
                bv_[nb * 2 + 1][0] = r[2]; bv_[nb * 2 + 1][1] = r[3];
            }
            #pragma unroll
            for (int ni = 0; ni < 8; ni++)
                mma_tf32(co[ni], ap, bv_[ni]);
        }
        __syncwarp();
    }

    // Epilogue: normalize, round to tf32 (out-proj consumes without cvt)
    const float inv0 = 1.f / l0, inv1 = 1.f / l1;
    const int row0 = q0 + wm + gq, row1 = row0 + 8;
    #pragma unroll
    for (int ni = 0; ni < 8; ni++) {
        const int col = ni * 8 + 2 * gt;
        float2 o0 = make_float2(__uint_as_float(tf32r(co[ni][0] * inv0)),
                                __uint_as_float(tf32r(co[ni][1] * inv0)));
        float2 o1 = make_float2(__uint_as_float(tf32r(co[ni][2] * inv1)),
                                __uint_as_float(tf32r(co[ni][3] * inv1)));
        *(float2*)&ctx[((size_t)bh * LL + row0) * DKK + col] = o0;
        *(float2*)&ctx[((size_t)bh * LL + row1) * DKK + col] = o1;
    }
}

// ---------------------------------------------------------------------------
extern "C" void kernel_launch(void* const* d_in, const int* in_sizes, int n_in,
                              void* d_out, int out_size)
{
    const float* x_q = (const float*)d_in[0];
    const float* x_k = (const float*)d_in[1];
    const float* x_v = (const float*)d_in[2];
    const float* Wq  = (const float*)d_in[3];
    const float* bq  = (const float*)d_in[4];
    const float* Wk  = (const float*)d_in[5];
    const float* bk  = (const float*)d_in[6];
    const float* Wv  = (const float*)d_in[7];
    const float* bv  = (const float*)d_in[8];
    const float* Wo  = (const float*)d_in[9];
    const float* bo  = (const float*)d_in[10];
    float* out = (float*)d_out;

    float *pq, *pk, *pv, *pctx, *pwt;
    cudaGetSymbolAddress((void**)&pq,   g_q);
    cudaGetSymbolAddress((void**)&pk,   g_k);
    cudaGetSymbolAddress((void**)&pv,   g_v);
    cudaGetSymbolAddress((void**)&pctx, g_ctx);
    cudaGetSymbolAddress((void**)&pwt,  g_wt);
    float* wtq = pwt;
    float* wtk = pwt + 1 * DD * NN;
    float* wtv = pwt + 2 * DD * NN;
    float* wto = pwt + 3 * DD * NN;

    cudaFuncSetAttribute(gemm_ld<0,1,1>, cudaFuncAttributeMaxDynamicSharedMemorySize, GSMEM);
    cudaFuncSetAttribute(gemm_ld<2,1,1>, cudaFuncAttributeMaxDynamicSharedMemorySize, GSMEM);
    cudaFuncSetAttribute(gemm_ld<1,0,0>, cudaFuncAttributeMaxDynamicSharedMemorySize, GSMEM);
    cudaFuncSetAttribute(attn_mma,       cudaFuncAttributeMaxDynamicSharedMemorySize, ATT_SMEM);

    dim3 tgrid(32, 32, 4), tblk(32, 8);
    dim3 ggrid(8, 32);
    dim3 agrid(LL / ATT_BM, BB * HH);

    transpose_round4<<<tgrid, tblk>>>(Wq, Wk, Wv, Wo, pwt);

    gemm_ld<0,1,1><<<ggrid, 256, GSMEM>>>(x_q, wtq, bq, pq, 0.125f);  // Q (pre-scaled)
    gemm_ld<0,1,1><<<ggrid, 256, GSMEM>>>(x_k, wtk, bk, pk, 1.0f);    // K
    gemm_ld<2,1,1><<<ggrid, 256, GSMEM>>>(x_v, wtv, bv, pv, 1.0f);    // V (transposed out)

    attn_mma<<<agrid, 256, ATT_SMEM>>>(pq, pk, pv, pctx);

    gemm_ld<1,0,0><<<ggrid, 256, GSMEM>>>(pctx, wto, bo, out, 1.0f);  // out-proj
}

// round 7
// speedup vs baseline: 4.1729x; 1.0960x over previous
#include <cuda_runtime.h>
#include <math.h>
#include <stdint.h>

// Problem dims
#define BB 2
#define LL 2048
#define DD 1024
#define HH 16
#define DKK 64
#define MM (BB*LL)     // 4096
#define NN 1024        // H*DK

// ---------------------------------------------------------------------------
// Device scratch (no cudaMalloc allowed)
// ---------------------------------------------------------------------------
__device__ float g_q  [BB*HH*LL*DKK];   // (b,h,l,dk)   tf32, pre-scaled 1/8
__device__ float g_k  [BB*HH*LL*DKK];   // (b,h,l,dk)   tf32
__device__ float g_v  [BB*HH*LL*DKK];   // (b,h,dk,l)   tf32, transposed
__device__ float g_ctx[BB*HH*LL*DKK];   // (b,h,l,dk)   tf32
__device__ float g_wt [4 * DD * NN];    // W^T, tf32-rounded: Wt[n][k]

// ---------------------------------------------------------------------------
// Helpers (sm_100 baseline ISA: mma.sync + cp.async + ldmatrix)
// ---------------------------------------------------------------------------
__device__ __forceinline__ uint32_t smem_u32(const void* p) {
    uint32_t a;
    asm("{ .reg .u64 t; cvta.to.shared.u64 t, %1; cvt.u32.u64 %0, t; }"
        : "=r"(a) : "l"(p));
    return a;
}
__device__ __forceinline__ uint32_t tf32r(float x) {
    uint32_t o;
    asm("cvt.rna.tf32.f32 %0, %1;" : "=r"(o) : "f"(x));
    return o;
}
__device__ __forceinline__ uint32_t tf32ru(uint32_t x) {
    uint32_t o;
    asm("cvt.rna.tf32.f32 %0, %1;" : "=r"(o) : "f"(__uint_as_float(x)));
    return o;
}

#define CP_ASYNC16(dst, src) \
    asm volatile("cp.async.cg.shared.global [%0], [%1], 16;" :: "r"(dst), "l"(src))
#define CP_COMMIT()  asm volatile("cp.async.commit_group;" ::: "memory")
#define CP_WAIT1()   asm volatile("cp.async.wait_group 1;" ::: "memory")
#define CP_WAIT0()   asm volatile("cp.async.wait_group 0;" ::: "memory")

// m16n8k8 tf32 MMA, fp32 accumulate
__device__ __forceinline__ void mma_tf32(float* c, const uint32_t* a, const uint32_t* b) {
    asm volatile(
        "mma.sync.aligned.m16n8k8.row.col.f32.tf32.tf32.f32 "
        "{%0,%1,%2,%3}, {%4,%5,%6,%7}, {%8,%9}, {%0,%1,%2,%3};"
        : "+f"(c[0]), "+f"(c[1]), "+f"(c[2]), "+f"(c[3])
        : "r"(a[0]), "r"(a[1]), "r"(a[2]), "r"(a[3]), "r"(b[0]), "r"(b[1]));
}

// ldmatrix x4 on fp32 data: each 8x4-float piece == one 8x8 b16 matrix.
__device__ __forceinline__ void ldsm4(uint32_t* r, uint32_t addr) {
    asm volatile("ldmatrix.sync.aligned.m8n8.x4.shared.b16 {%0,%1,%2,%3}, [%4];"
                 : "=r"(r[0]), "=r"(r[1]), "=r"(r[2]), "=r"(r[3]) : "r"(addr));
}

// ---------------------------------------------------------------------------
// Fused pre-pass: transpose + tf32-round all four weights (grid.z selects)
// ---------------------------------------------------------------------------
__global__ __launch_bounds__(256)
void transpose_round4(const float* __restrict__ W0, const float* __restrict__ W1,
                      const float* __restrict__ W2, const float* __restrict__ W3,
                      float* __restrict__ T)
{
    const float* W = (blockIdx.z == 0) ? W0 : (blockIdx.z == 1) ? W1
                   : (blockIdx.z == 2) ? W2 : W3;
    float* Wt = T + (size_t)blockIdx.z * DD * NN;
    __shared__ float t[32][33];
    int x = blockIdx.x * 32 + threadIdx.x;
    int y = blockIdx.y * 32 + threadIdx.y;
    #pragma unroll
    for (int i = 0; i < 32; i += 8)
        t[threadIdx.y + i][threadIdx.x] = W[(size_t)(y + i) * 1024 + x];
    __syncthreads();
    x = blockIdx.y * 32 + threadIdx.x;
    y = blockIdx.x * 32 + threadIdx.y;
    #pragma unroll
    for (int i = 0; i < 32; i += 8)
        Wt[(size_t)(y + i) * 1024 + x] = __uint_as_float(tf32r(t[threadIdx.x][threadIdx.y + i]));
}

// ---------------------------------------------------------------------------
// Shared GEMM machinery: 128x128 CTA tile, 8 warps (2x4), warp 64x32,
// K-chunk 32, 3-stage cp.async pipeline, 1 barrier per chunk.
// ---------------------------------------------------------------------------
static constexpr int GSTR  = 36;
static constexpr int GTILE = 128 * GSTR;
static constexpr int GSMEM = 6 * GTILE * 4;       // 110592 B; x2 CTAs = 221184 <= 228KB

struct GemmCtx {
    uint32_t sb;
    int tid, lane, wid, wm, wn, gq, gt, aBase, bBase, m0, n0;
};

__device__ __forceinline__ void gemm_init(GemmCtx& g, const float* smem) {
    g.sb   = smem_u32(smem);
    g.tid  = threadIdx.x;
    g.lane = g.tid & 31;
    g.wid  = g.tid >> 5;
    g.wm   = (g.wid >> 2) * 64;
    g.wn   = (g.wid & 3) * 32;
    g.gq   = g.lane >> 2;
    g.gt   = g.lane & 3;
    const int l7 = g.lane & 7, lg8 = (g.lane >> 3) & 1, lg16 = g.lane >> 4;
    g.aBase = (g.wm + l7 + lg8 * 8) * GSTR + lg16 * 4;
    g.bBase = (g.wn + lg16 * 8 + l7) * GSTR + lg8 * 4;
    g.m0 = blockIdx.y * 128;
    g.n0 = blockIdx.x * 128;
}

// GATHER: 0 = A plain rows; 1 = A gathered from (b,h,l,dk)
template<int GATHER>
__device__ __forceinline__ void gemm_load_chunk(const GemmCtx& g, const float* A,
                                                const float* Wt, int ck, int st) {
    const int k0 = ck * 32;
    const uint32_t sa = g.sb + (uint32_t)(2 * st) * GTILE * 4;
    const uint32_t sw = g.sb + (uint32_t)(2 * st + 1) * GTILE * 4;
    #pragma unroll
    for (int i = 0; i < 4; i++) {
        const int id  = g.tid + 256 * i;
        const int row = id >> 3;
        const int cs  = id & 7;
        const float* ga;
        if (!GATHER) {
            ga = &A[(size_t)(g.m0 + row) * 1024 + k0 + cs * 4];
        } else {
            const int m  = g.m0 + row;
            const int bb = m >> 11, l = m & 2047;
            const int kk = k0 + cs * 4;
            const int h  = kk >> 6, d = kk & 63;
            ga = &A[(size_t)((bb * HH + h) * LL + l) * DKK + d];
        }
        CP_ASYNC16(sa + (uint32_t)(row * GSTR + cs * 4) * 4, ga);
        CP_ASYNC16(sw + (uint32_t)(row * GSTR + cs * 4) * 4,
                   &Wt[(size_t)(g.n0 + row) * 1024 + k0 + cs * 4]);
    }
}

// Mainloop over 32 k-chunks. CVT: round A-fragments post-ldmatrix.
template<int GATHER, int CVT>
__device__ __forceinline__ void gemm_main(const GemmCtx& g, const float* A,
                                          const float* Wt, float c[4][4][4]) {
    #pragma unroll
    for (int mi = 0; mi < 4; mi++)
        #pragma unroll
        for (int ni = 0; ni < 4; ni++)
            #pragma unroll
            for (int r = 0; r < 4; r++) c[mi][ni][r] = 0.f;

    gemm_load_chunk<GATHER>(g, A, Wt, 0, 0); CP_COMMIT();
    gemm_load_chunk<GATHER>(g, A, Wt, 1, 1); CP_COMMIT();

    for (int ck = 0; ck < 32; ck++) {
        if (ck < 31) CP_WAIT1(); else CP_WAIT0();
        __syncthreads();
        const int st = ck % 3;
        const uint32_t As = g.sb + (uint32_t)(2 * st) * GTILE * 4;
        const uint32_t Ws = g.sb + (uint32_t)(2 * st + 1) * GTILE * 4;

        #pragma unroll
        for (int ks = 0; ks < 4; ks++) {
            uint32_t a[4][4];
            #pragma unroll
            for (int mi = 0; mi < 4; mi++) {
                ldsm4(a[mi], As + (uint32_t)(g.aBase + mi * 16 * GSTR + ks * 8) * 4);
                if (CVT) {
                    #pragma unroll
                    for (int r = 0; r < 4; r++) a[mi][r] = tf32ru(a[mi][r]);
                }
            }
            uint32_t b[4][2];
            #pragma unroll
            for (int nb = 0; nb < 2; nb++) {
                uint32_t r[4];
                ldsm4(r, Ws + (uint32_t)(g.bBase + nb * 16 * GSTR + ks * 8) * 4);
                b[nb * 2][0] = r[0]; b[nb * 2][1] = r[1];
                b[nb * 2 + 1][0] = r[2]; b[nb * 2 + 1][1] = r[3];
            }
            #pragma unroll
            for (int mi = 0; mi < 4; mi++)
                #pragma unroll
                for (int ni = 0; ni < 4; ni++)
                    mma_tf32(c[mi][ni], a[mi], b[ni]);
        }
        if (ck + 2 < 32) { gemm_load_chunk<GATHER>(g, A, Wt, ck + 2, (ck + 2) % 3); CP_COMMIT(); }
    }
}

// ---------------------------------------------------------------------------
// Fused QKV projection GEMM (grid.z = 0:Q, 1:K, 2:V). 2 CTAs/SM.
//   Q/K: scatter (b,h,l,dk) rounded tf32 (Q pre-scaled 1/8). V: transposed
//   scatter (b,h,dk,l) rounded tf32.
// ---------------------------------------------------------------------------
__global__ __launch_bounds__(256, 2)
void gemm_qkv(const float* __restrict__ xq, const float* __restrict__ xk,
              const float* __restrict__ xv, const float* __restrict__ wt,
              const float* __restrict__ bq, const float* __restrict__ bk,
              const float* __restrict__ bv,
              float* __restrict__ oq, float* __restrict__ ok, float* __restrict__ ov)
{
    extern __shared__ float smem[];
    GemmCtx g; gemm_init(g, smem);
    const int z = blockIdx.z;
    const float* A    = (z == 0) ? xq : (z == 1) ? xk : xv;
    const float* Wt   = wt + (size_t)z * DD * NN;
    const float* bias = (z == 0) ? bq : (z == 1) ? bk : bv;
    float* C          = (z == 0) ? oq : (z == 1) ? ok : ov;
    const float scale = (z == 0) ? 0.125f : 1.0f;

    float c[4][4][4];
    gemm_main<0, 1>(g, A, Wt, c);

    #pragma unroll
    for (int mi = 0; mi < 4; mi++) {
        const int row = g.m0 + g.wm + mi * 16 + g.gq;
        #pragma unroll
        for (int ni = 0; ni < 4; ni++) {
            const int col = g.n0 + g.wn + ni * 8 + 2 * g.gt;
            const float b0 = bias[col], b1 = bias[col + 1];
            float vals[4] = { c[mi][ni][0] + b0, c[mi][ni][1] + b1,
                              c[mi][ni][2] + b0, c[mi][ni][3] + b1 };
            #pragma unroll
            for (int r = 0; r < 4; r++)
                vals[r] = __uint_as_float(tf32r(vals[r])) * scale;
            const int h = col >> 6, d = col & 63;
            const int bb0 = row >> 11, l0 = row & 2047;
            const int r8 = row + 8;
            const int bb1 = r8 >> 11, l1 = r8 & 2047;
            if (z != 2) {
                *(float2*)&C[(size_t)((bb0 * HH + h) * LL + l0) * DKK + d] =
                    make_float2(vals[0], vals[1]);
                *(float2*)&C[(size_t)((bb1 * HH + h) * LL + l1) * DKK + d] =
                    make_float2(vals[2], vals[3]);
            } else {
                C[((size_t)(bb0 * HH + h) * DKK + d)     * LL + l0] = vals[0];
                C[((size_t)(bb0 * HH + h) * DKK + d + 1) * LL + l0] = vals[1];
                C[((size_t)(bb1 * HH + h) * DKK + d)     * LL + l1] = vals[2];
                C[((size_t)(bb1 * HH + h) * DKK + d + 1) * LL + l1] = vals[3];
            }
        }
    }
}

// ---------------------------------------------------------------------------
// Output projection GEMM: ctx (b,h,l,dk; pre-rounded tf32) @ Wo^T + bo.
// ---------------------------------------------------------------------------
__global__ __launch_bounds__(256, 2)
void gemm_out(const float* __restrict__ ctx, const float* __restrict__ wt,
              const float* __restrict__ bias, float* __restrict__ C)
{
    extern __shared__ float smem[];
    GemmCtx g; gemm_init(g, smem);

    float c[4][4][4];
    gemm_main<1, 0>(g, ctx, wt, c);

    #pragma unroll
    for (int mi = 0; mi < 4; mi++) {
        const int row = g.m0 + g.wm + mi * 16 + g.gq;
        #pragma unroll
        for (int ni = 0; ni < 4; ni++) {
            const int col = g.n0 + g.wn + ni * 8 + 2 * g.gt;
            const float b0 = bias[col], b1 = bias[col + 1];
            *(float2*)&C[(size_t)row * 1024 + col] =
                make_float2(c[mi][ni][0] + b0, c[mi][ni][1] + b1);
            *(float2*)&C[(size_t)(row + 8) * 1024 + col] =
                make_float2(c[mi][ni][2] + b0, c[mi][ni][3] + b1);
        }
    }
}

// ---------------------------------------------------------------------------
// Tensor-core flash attention (ldmatrix), 2 CTAs/SM.
// ---------------------------------------------------------------------------
static constexpr int ATT_BM = 128;
static constexpr int TSTR = 68;
static constexpr int SK0 = 0;
static constexpr int SK1 = SK0 + 64 * TSTR;
static constexpr int SV0 = SK1 + 64 * TSTR;
static constexpr int SV1 = SV0 + 64 * TSTR;
static constexpr int SP  = SV1 + 64 * TSTR;
static constexpr int ATT_SMEM = (SP + ATT_BM * TSTR) * 4;   // 104448 bytes

__global__ __launch_bounds__(256, 2)
void attn_mma(const float* __restrict__ q, const float* __restrict__ k,
              const float* __restrict__ v, float* __restrict__ ctx)
{
    extern __shared__ float sm[];
    const uint32_t sb = smem_u32(sm);
    const int tid = threadIdx.x, lane = tid & 31, wid = tid >> 5;
    const int gq = lane >> 2, gt = lane & 3;
    const int l7 = lane & 7, lg8 = (lane >> 3) & 1, lg16 = lane >> 4;
    const int wm = wid * 16;
    const int bh = blockIdx.y;
    const int q0 = blockIdx.x * ATT_BM;
    const float* kb = k + (size_t)bh * LL * DKK;
    const float* vb = v + (size_t)bh * DKK * LL;

    const int aBase = (wm + l7 + lg8 * 8) * TSTR + lg16 * 4;
    const int bBase = (lg16 * 8 + l7) * TSTR + lg8 * 4;

    {
        const int row = tid >> 1, d0 = (tid & 1) * 32;
        const float* gp = q + ((size_t)bh * LL + q0 + row) * DKK + d0;
        #pragma unroll
        for (int i = 0; i < 8; i++)
            *(float4*)&sm[SP + row * TSTR + d0 + i * 4] = *(const float4*)&gp[i * 4];
    }
    __syncthreads();
    uint32_t aq[8][4];
    #pragma unroll
    for (int s = 0; s < 8; s++)
        ldsm4(aq[s], sb + (uint32_t)(SP + aBase + s * 8) * 4);

    float co[8][4];
    #pragma unroll
    for (int ni = 0; ni < 8; ni++)
        #pragma unroll
        for (int r = 0; r < 4; r++) co[ni][r] = 0.f;
    float m0 = -INFINITY, m1 = -INFINITY, l0 = 0.f, l1 = 0.f;

    auto load_kv = [&](int kt, int b) {
        const int koff = b ? SK1 : SK0, voff = b ? SV1 : SV0;
        #pragma unroll
        for (int i = 0; i < 4; i++) {
            const int id = tid + 256 * i;
            const int row = id >> 4, c = id & 15;
            CP_ASYNC16(sb + (uint32_t)(koff + row * TSTR + c * 4) * 4,
                       &kb[((size_t)kt * 64 + row) * DKK + c * 4]);
            CP_ASYNC16(sb + (uint32_t)(voff + row * TSTR + c * 4) * 4,
                       &vb[(size_t)row * LL + kt * 64 + c * 4]);
        }
    };
    load_kv(0, 0); CP_COMMIT();

    for (int kt = 0; kt < LL / 64; kt++) {
        __syncthreads();
        if (kt + 1 < LL / 64) { load_kv(kt + 1, (kt + 1) & 1); CP_COMMIT(); CP_WAIT1(); }
        else                  { CP_WAIT0(); }
        __syncthreads();
        const int kbuf = (kt & 1) ? SK1 : SK0;
        const int vbuf = (kt & 1) ? SV1 : SV0;

        float sc[8][4];
        #pragma unroll
        for (int ni = 0; ni < 8; ni++)
            #pragma unroll
            for (int r = 0; r < 4; r++) sc[ni][r] = 0.f;
        #pragma unroll
        for (int s = 0; s < 8; s++) {
            uint32_t bf[8][2];
            #pragma unroll
            for (int nb = 0; nb < 4; nb++) {
                uint32_t r[4];
                ldsm4(r, sb + (uint32_t)(kbuf + bBase + nb * 16 * TSTR + s * 8) * 4);
                bf[nb * 2][0] = r[0]; bf[nb * 2][1] = r[1];
                bf[nb * 2 + 1][0] = r[2]; bf[nb * 2 + 1][1] = r[3];
            }
            #pragma unroll
            for (int ni = 0; ni < 8; ni++)
                mma_tf32(sc[ni], aq[s], bf[ni]);
        }

        float rm0 = sc[0][0], rm1 = sc[0][2];
        #pragma unroll
        for (int ni = 0; ni < 8; ni++) {
            rm0 = fmaxf(rm0, fmaxf(sc[ni][0], sc[ni][1]));
            rm1 = fmaxf(rm1, fmaxf(sc[ni][2], sc[ni][3]));
        }
        rm0 = fmaxf(rm0, __shfl_xor_sync(0xffffffff, rm0, 1));
        rm0 = fmaxf(rm0, __shfl_xor_sync(0xffffffff, rm0, 2));
        rm1 = fmaxf(rm1, __shfl_xor_sync(0xffffffff, rm1, 1));
        rm1 = fmaxf(rm1, __shfl_xor_sync(0xffffffff, rm1, 2));
        const float nm0 = fmaxf(m0, rm0), nm1 = fmaxf(m1, rm1);
        const float cr0 = __expf(m0 - nm0), cr1 = __expf(m1 - nm1);
        float rs0 = 0.f, rs1 = 0.f;
        #pragma unroll
        for (int ni = 0; ni < 8; ni++) {
            const float e00 = __expf(sc[ni][0] - nm0);
            const float e01 = __expf(sc[ni][1] - nm0);
            const float e10 = __expf(sc[ni][2] - nm1);
            const float e11 = __expf(sc[ni][3] - nm1);
            rs0 += e00 + e01;
            rs1 += e10 + e11;
            const int col = ni * 8 + 2 * gt;
            *(float2*)&sm[SP + (wm + gq) * TSTR + col] =
                make_float2(__uint_as_float(tf32r(e00)), __uint_as_float(tf32r(e01)));
            *(float2*)&sm[SP + (wm + gq + 8) * TSTR + col] =
                make_float2(__uint_as_float(tf32r(e10)), __uint_as_float(tf32r(e11)));
        }
        rs0 += __shfl_xor_sync(0xffffffff, rs0, 1);
        rs0 += __shfl_xor_sync(0xffffffff, rs0, 2);
        rs1 += __shfl_xor_sync(0xffffffff, rs1, 1);
        rs1 += __shfl_xor_sync(0xffffffff, rs1, 2);
        m0 = nm0; m1 = nm1;
        l0 = l0 * cr0 + rs0;
        l1 = l1 * cr1 + rs1;
        #pragma unroll
        for (int ni = 0; ni < 8; ni++) {
            co[ni][0] *= cr0; co[ni][1] *= cr0;
            co[ni][2] *= cr1; co[ni][3] *= cr1;
        }
        __syncwarp();

        #pragma unroll
        for (int s = 0; s < 8; s++) {
            uint32_t ap[4];
            ldsm4(ap, sb + (uint32_t)(SP + aBase + s * 8) * 4);
            uint32_t bv_[8][2];
            #pragma unroll
            for (int nb = 0; nb < 4; nb++) {
                uint32_t r[4];
                ldsm4(r, sb + (uint32_t)(vbuf + bBase + nb * 16 * TSTR + s * 8) * 4);
                bv_[nb * 2][0] = r[0]; bv_[nb * 2][1] = r[1];
                bv_[nb * 2 + 1][0] = r[2]; bv_[nb * 2 + 1][1] = r[3];
            }
            #pragma unroll
            for (int ni = 0; ni < 8; ni++)
                mma_tf32(co[ni], ap, bv_[ni]);
        }
        __syncwarp();
    }

    const float inv0 = 1.f / l0, inv1 = 1.f / l1;
    const int row0 = q0 + wm + gq, row1 = row0 + 8;
    #pragma unroll
    for (int ni = 0; ni < 8; ni++) {
        const int col = ni * 8 + 2 * gt;
        float2 o0 = make_float2(__uint_as_float(tf32r(co[ni][0] * inv0)),
                                __uint_as_float(tf32r(co[ni][1] * inv0)));
        float2 o1 = make_float2(__uint_as_float(tf32r(co[ni][2] * inv1)),
                                __uint_as_float(tf32r(co[ni][3] * inv1)));
        *(float2*)&ctx[((size_t)bh * LL + row0) * DKK + col] = o0;
        *(float2*)&ctx[((size_t)bh * LL + row1) * DKK + col] = o1;
    }
}

// ---------------------------------------------------------------------------
extern "C" void kernel_launch(void* const* d_in, const int* in_sizes, int n_in,
                              void* d_out, int out_size)
{
    const float* x_q = (const float*)d_in[0];
    const float* x_k = (const float*)d_in[1];
    const float* x_v = (const float*)d_in[2];
    const float* Wq  = (const float*)d_in[3];
    const float* bq  = (const float*)d_in[4];
    const float* Wk  = (const float*)d_in[5];
    const float* bk  = (const float*)d_in[6];
    const float* Wv  = (const float*)d_in[7];
    const float* bv  = (const float*)d_in[8];
    const float* Wo  = (const float*)d_in[9];
    const float* bo  = (const float*)d_in[10];
    float* out = (float*)d_out;

    float *pq, *pk, *pv, *pctx, *pwt;
    cudaGetSymbolAddress((void**)&pq,   g_q);
    cudaGetSymbolAddress((void**)&pk,   g_k);
    cudaGetSymbolAddress((void**)&pv,   g_v);
    cudaGetSymbolAddress((void**)&pctx, g_ctx);
    cudaGetSymbolAddress((void**)&pwt,  g_wt);
    float* wto = pwt + 3 * DD * NN;

    cudaFuncSetAttribute(gemm_qkv, cudaFuncAttributeMaxDynamicSharedMemorySize, GSMEM);
    cudaFuncSetAttribute(gemm_out, cudaFuncAttributeMaxDynamicSharedMemorySize, GSMEM);
    cudaFuncSetAttribute(attn_mma, cudaFuncAttributeMaxDynamicSharedMemorySize, ATT_SMEM);

    dim3 tgrid(32, 32, 4), tblk(32, 8);
    dim3 qkvgrid(8, 32, 3);
    dim3 ggrid(8, 32);
    dim3 agrid(LL / ATT_BM, BB * HH);

    transpose_round4<<<tgrid, tblk>>>(Wq, Wk, Wv, Wo, pwt);

    gemm_qkv<<<qkvgrid, 256, GSMEM>>>(x_q, x_k, x_v, pwt, bq, bk, bv, pq, pk, pv);

    attn_mma<<<agrid, 256, ATT_SMEM>>>(pq, pk, pv, pctx);

    gemm_out<<<ggrid, 256, GSMEM>>>(pctx, wto, bo, out);
}

// round 8
// speedup vs baseline: 4.3371x; 1.0393x over previous
#include <cuda_runtime.h>
#include <math.h>
#include <stdint.h>

// Problem dims
#define BB 2
#define LL 2048
#define DD 1024
#define HH 16
#define DKK 64
#define MM (BB*LL)     // 4096
#define NN 1024        // H*DK

// ---------------------------------------------------------------------------
// Device scratch (no cudaMalloc allowed)
// ---------------------------------------------------------------------------
__device__ float g_q  [BB*HH*LL*DKK];   // (b,h,l,dk)   tf32, pre-scaled 1/8
__device__ float g_k  [BB*HH*LL*DKK];   // (b,h,l,dk)   tf32
__device__ float g_v  [BB*HH*LL*DKK];   // (b,h,dk,l)   tf32, transposed
__device__ float g_ctx[BB*HH*LL*DKK];   // (b,h,l,dk)   tf32
__device__ float g_wt [4 * DD * NN];    // W^T, tf32-rounded: Wt[n][k]

// ---------------------------------------------------------------------------
// Helpers (sm_100 baseline ISA: mma.sync + cp.async + ldmatrix)
// ---------------------------------------------------------------------------
__device__ __forceinline__ uint32_t smem_u32(const void* p) {
    uint32_t a;
    asm("{ .reg .u64 t; cvta.to.shared.u64 t, %1; cvt.u32.u64 %0, t; }"
        : "=r"(a) : "l"(p));
    return a;
}
__device__ __forceinline__ uint32_t tf32r(float x) {
    uint32_t o;
    asm("cvt.rna.tf32.f32 %0, %1;" : "=r"(o) : "f"(x));
    return o;
}
__device__ __forceinline__ uint32_t tf32ru(uint32_t x) {
    uint32_t o;
    asm("cvt.rna.tf32.f32 %0, %1;" : "=r"(o) : "f"(__uint_as_float(x)));
    return o;
}

#define CP_ASYNC16(dst, src) \
    asm volatile("cp.async.cg.shared.global [%0], [%1], 16;" :: "r"(dst), "l"(src))
#define CP_COMMIT()  asm volatile("cp.async.commit_group;" ::: "memory")
#define CP_WAIT1()   asm volatile("cp.async.wait_group 1;" ::: "memory")
#define CP_WAIT0()   asm volatile("cp.async.wait_group 0;" ::: "memory")

// m16n8k8 tf32 MMA, fp32 accumulate
__device__ __forceinline__ void mma_tf32(float* c, const uint32_t* a, const uint32_t* b) {
    asm volatile(
        "mma.sync.aligned.m16n8k8.row.col.f32.tf32.tf32.f32 "
        "{%0,%1,%2,%3}, {%4,%5,%6,%7}, {%8,%9}, {%0,%1,%2,%3};"
        : "+f"(c[0]), "+f"(c[1]), "+f"(c[2]), "+f"(c[3])
        : "r"(a[0]), "r"(a[1]), "r"(a[2]), "r"(a[3]), "r"(b[0]), "r"(b[1]));
}

// ldmatrix x4 on fp32 data: each 8x4-float piece == one 8x8 b16 matrix.
__device__ __forceinline__ void ldsm4(uint32_t* r, uint32_t addr) {
    asm volatile("ldmatrix.sync.aligned.m8n8.x4.shared.b16 {%0,%1,%2,%3}, [%4];"
                 : "=r"(r[0]), "=r"(r[1]), "=r"(r[2]), "=r"(r[3]) : "r"(addr));
}

// ---------------------------------------------------------------------------
// Fused pre-pass: transpose + tf32-round all four weights (grid.z selects)
// ---------------------------------------------------------------------------
__global__ __launch_bounds__(256)
void transpose_round4(const float* __restrict__ W0, const float* __restrict__ W1,
                      const float* __restrict__ W2, const float* __restrict__ W3,
                      float* __restrict__ T)
{
    const float* W = (blockIdx.z == 0) ? W0 : (blockIdx.z == 1) ? W1
                   : (blockIdx.z == 2) ? W2 : W3;
    float* Wt = T + (size_t)blockIdx.z * DD * NN;
    __shared__ float t[32][33];
    int x = blockIdx.x * 32 + threadIdx.x;
    int y = blockIdx.y * 32 + threadIdx.y;
    #pragma unroll
    for (int i = 0; i < 32; i += 8)
        t[threadIdx.y + i][threadIdx.x] = W[(size_t)(y + i) * 1024 + x];
    __syncthreads();
    x = blockIdx.y * 32 + threadIdx.x;
    y = blockIdx.x * 32 + threadIdx.y;
    #pragma unroll
    for (int i = 0; i < 32; i += 8)
        Wt[(size_t)(y + i) * 1024 + x] = __uint_as_float(tf32r(t[threadIdx.x][threadIdx.y + i]));
}

// ---------------------------------------------------------------------------
// GEMM machinery: 128x128 CTA tile, 128 threads = 4 warps (2x2), warp 64x64.
// K-chunk 32, 3-stage cp.async, 1 barrier per chunk. A/B each read only 2x
// from smem per chunk (was 4x/2x with the 2x4 shape).
// ---------------------------------------------------------------------------
static constexpr int GSTR  = 36;
static constexpr int GTILE = 128 * GSTR;
static constexpr int GSMEM = 6 * GTILE * 4;       // 110592 B; x2 CTAs fits

struct GemmCtx {
    uint32_t sb;
    int tid, lane, wm, wn, gq, gt, aBase, bBase, m0, n0;
};

__device__ __forceinline__ void gemm_init(GemmCtx& g, const float* smem) {
    g.sb   = smem_u32(smem);
    g.tid  = threadIdx.x;
    g.lane = g.tid & 31;
    const int wid = g.tid >> 5;
    g.wm   = (wid >> 1) * 64;
    g.wn   = (wid & 1) * 64;
    g.gq   = g.lane >> 2;
    g.gt   = g.lane & 3;
    const int l7 = g.lane & 7, lg8 = (g.lane >> 3) & 1, lg16 = g.lane >> 4;
    g.aBase = (g.wm + l7 + lg8 * 8) * GSTR + lg16 * 4;
    g.bBase = (g.wn + lg16 * 8 + l7) * GSTR + lg8 * 4;
    g.m0 = blockIdx.y * 128;
    g.n0 = blockIdx.x * 128;
}

// GATHER: 0 = A plain rows; 1 = A gathered from (b,h,l,dk)
template<int GATHER>
__device__ __forceinline__ void gemm_load_chunk(const GemmCtx& g, const float* A,
                                                const float* Wt, int ck, int st) {
    const int k0 = ck * 32;
    const uint32_t sa = g.sb + (uint32_t)(2 * st) * GTILE * 4;
    const uint32_t sw = g.sb + (uint32_t)(2 * st + 1) * GTILE * 4;
    #pragma unroll
    for (int i = 0; i < 8; i++) {
        const int id  = g.tid + 128 * i;
        const int row = id >> 3;
        const int cs  = id & 7;
        const float* ga;
        if (!GATHER) {
            ga = &A[(size_t)(g.m0 + row) * 1024 + k0 + cs * 4];
        } else {
            const int m  = g.m0 + row;
            const int bb = m >> 11, l = m & 2047;
            const int kk = k0 + cs * 4;
            const int h  = kk >> 6, d = kk & 63;
            ga = &A[(size_t)((bb * HH + h) * LL + l) * DKK + d];
        }
        CP_ASYNC16(sa + (uint32_t)(row * GSTR + cs * 4) * 4, ga);
        CP_ASYNC16(sw + (uint32_t)(row * GSTR + cs * 4) * 4,
                   &Wt[(size_t)(g.n0 + row) * 1024 + k0 + cs * 4]);
    }
}

// Mainloop over 32 k-chunks. CVT: round A-fragments post-ldmatrix.
template<int GATHER, int CVT>
__device__ __forceinline__ void gemm_main(const GemmCtx& g, const float* A,
                                          const float* Wt, float c[4][8][4]) {
    #pragma unroll
    for (int mi = 0; mi < 4; mi++)
        #pragma unroll
        for (int ni = 0; ni < 8; ni++)
            #pragma unroll
            for (int r = 0; r < 4; r++) c[mi][ni][r] = 0.f;

    gemm_load_chunk<GATHER>(g, A, Wt, 0, 0); CP_COMMIT();
    gemm_load_chunk<GATHER>(g, A, Wt, 1, 1); CP_COMMIT();

    for (int ck = 0; ck < 32; ck++) {
        if (ck < 31) CP_WAIT1(); else CP_WAIT0();
        __syncthreads();
        const int st = ck % 3;
        const uint32_t As = g.sb + (uint32_t)(2 * st) * GTILE * 4;
        const uint32_t Ws = g.sb + (uint32_t)(2 * st + 1) * GTILE * 4;

        #pragma unroll
        for (int ks = 0; ks < 4; ks++) {
            uint32_t a[4][4];
            #pragma unroll
            for (int mi = 0; mi < 4; mi++) {
                ldsm4(a[mi], As + (uint32_t)(g.aBase + mi * 16 * GSTR + ks * 8) * 4);
                if (CVT) {
                    #pragma unroll
                    for (int r = 0; r < 4; r++) a[mi][r] = tf32ru(a[mi][r]);
                }
            }
            uint32_t b[8][2];
            #pragma unroll
            for (int nb = 0; nb < 4; nb++) {
                uint32_t r[4];
                ldsm4(r, Ws + (uint32_t)(g.bBase + nb * 16 * GSTR + ks * 8) * 4);
                b[nb * 2][0] = r[0]; b[nb * 2][1] = r[1];
                b[nb * 2 + 1][0] = r[2]; b[nb * 2 + 1][1] = r[3];
            }
            #pragma unroll
            for (int mi = 0; mi < 4; mi++)
                #pragma unroll
                for (int ni = 0; ni < 8; ni++)
                    mma_tf32(c[mi][ni], a[mi], b[ni]);
        }
        if (ck + 2 < 32) { gemm_load_chunk<GATHER>(g, A, Wt, ck + 2, (ck + 2) % 3); CP_COMMIT(); }
    }
}

// ---------------------------------------------------------------------------
// Fused QKV projection GEMM (grid.z = 0:Q, 1:K, 2:V). 128 thr, 2 CTAs/SM.
// ---------------------------------------------------------------------------
__global__ __launch_bounds__(128, 2)
void gemm_qkv(const float* __restrict__ xq, const float* __restrict__ xk,
              const float* __restrict__ xv, const float* __restrict__ wt,
              const float* __restrict__ bq, const float* __restrict__ bk,
              const float* __restrict__ bv,
              float* __restrict__ oq, float* __restrict__ ok, float* __restrict__ ov)
{
    extern __shared__ float smem[];
    GemmCtx g; gemm_init(g, smem);
    const int z = blockIdx.z;
    const float* A    = (z == 0) ? xq : (z == 1) ? xk : xv;
    const float* Wt   = wt + (size_t)z * DD * NN;
    const float* bias = (z == 0) ? bq : (z == 1) ? bk : bv;
    float* C          = (z == 0) ? oq : (z == 1) ? ok : ov;
    const float scale = (z == 0) ? 0.125f : 1.0f;

    float c[4][8][4];
    gemm_main<0, 1>(g, A, Wt, c);

    #pragma unroll
    for (int mi = 0; mi < 4; mi++) {
        const int row = g.m0 + g.wm + mi * 16 + g.gq;
        #pragma unroll
        for (int ni = 0; ni < 8; ni++) {
            const int col = g.n0 + g.wn + ni * 8 + 2 * g.gt;
            const float b0 = bias[col], b1 = bias[col + 1];
            float vals[4] = { c[mi][ni][0] + b0, c[mi][ni][1] + b1,
                              c[mi][ni][2] + b0, c[mi][ni][3] + b1 };
            #pragma unroll
            for (int r = 0; r < 4; r++)
                vals[r] = __uint_as_float(tf32r(vals[r])) * scale;
            const int h = col >> 6, d = col & 63;
            const int bb0 = row >> 11, l0 = row & 2047;
            const int r8 = row + 8;
            const int bb1 = r8 >> 11, l1 = r8 & 2047;
            if (z != 2) {
                *(float2*)&C[(size_t)((bb0 * HH + h) * LL + l0) * DKK + d] =
                    make_float2(vals[0], vals[1]);
                *(float2*)&C[(size_t)((bb1 * HH + h) * LL + l1) * DKK + d] =
                    make_float2(vals[2], vals[3]);
            } else {
                C[((size_t)(bb0 * HH + h) * DKK + d)     * LL + l0] = vals[0];
                C[((size_t)(bb0 * HH + h) * DKK + d + 1) * LL + l0] = vals[1];
                C[((size_t)(bb1 * HH + h) * DKK + d)     * LL + l1] = vals[2];
                C[((size_t)(bb1 * HH + h) * DKK + d + 1) * LL + l1] = vals[3];
            }
        }
    }
}

// ---------------------------------------------------------------------------
// Output projection GEMM: ctx (b,h,l,dk; pre-rounded tf32) @ Wo^T + bo.
// ---------------------------------------------------------------------------
__global__ __launch_bounds__(128, 2)
void gemm_out(const float* __restrict__ ctx, const float* __restrict__ wt,
              const float* __restrict__ bias, float* __restrict__ C)
{
    extern __shared__ float smem[];
    GemmCtx g; gemm_init(g, smem);

    float c[4][8][4];
    gemm_main<1, 0>(g, ctx, wt, c);

    #pragma unroll
    for (int mi = 0; mi < 4; mi++) {
        const int row = g.m0 + g.wm + mi * 16 + g.gq;
        #pragma unroll
        for (int ni = 0; ni < 8; ni++) {
            const int col = g.n0 + g.wn + ni * 8 + 2 * g.gt;
            const float b0 = bias[col], b1 = bias[col + 1];
            *(float2*)&C[(size_t)row * 1024 + col] =
                make_float2(c[mi][ni][0] + b0, c[mi][ni][1] + b1);
            *(float2*)&C[(size_t)(row + 8) * 1024 + col] =
                make_float2(c[mi][ni][2] + b0, c[mi][ni][3] + b1);
        }
    }
}

// ---------------------------------------------------------------------------
// Tensor-core flash attention: 128 threads = 4 warps, BM=128, warp = 32 rows
// (2 m-blocks). K/V fragment redundancy drops 8x -> 4x.
// ---------------------------------------------------------------------------
static constexpr int ATT_BM = 128;
static constexpr int TSTR = 68;
static constexpr int SK0 = 0;
static constexpr int SK1 = SK0 + 64 * TSTR;
static constexpr int SV0 = SK1 + 64 * TSTR;
static constexpr int SV1 = SV0 + 64 * TSTR;
static constexpr int SP  = SV1 + 64 * TSTR;
static constexpr int ATT_SMEM = (SP + ATT_BM * TSTR) * 4;   // 104448 bytes

__global__ __launch_bounds__(128, 2)
void attn_mma(const float* __restrict__ q, const float* __restrict__ k,
              const float* __restrict__ v, float* __restrict__ ctx)
{
    extern __shared__ float sm[];
    const uint32_t sb = smem_u32(sm);
    const int tid = threadIdx.x, lane = tid & 31, wid = tid >> 5;
    const int gq = lane >> 2, gt = lane & 3;
    const int l7 = lane & 7, lg8 = (lane >> 3) & 1, lg16 = lane >> 4;
    const int wm = wid * 32;                 // 32 q-rows per warp
    const int bh = blockIdx.y;
    const int q0 = blockIdx.x * ATT_BM;
    const float* kb = k + (size_t)bh * LL * DKK;
    const float* vb = v + (size_t)bh * DKK * LL;

    const int aBase = (wm + l7 + lg8 * 8) * TSTR + lg16 * 4;   // +mb*16*TSTR +s*8
    const int bBase = (lg16 * 8 + l7) * TSTR + lg8 * 4;        // +nb*16*TSTR +s*8

    // Stage Q tile (128 rows x 64); one row per thread
    {
        const int row = tid;
        const float* gp = q + ((size_t)bh * LL + q0 + row) * DKK;
        #pragma unroll
        for (int i = 0; i < 16; i++)
            *(float4*)&sm[SP + row * TSTR + i * 4] = *(const float4*)&gp[i * 4];
    }
    __syncthreads();
    uint32_t aq[8][2][4];
    #pragma unroll
    for (int s = 0; s < 8; s++)
        #pragma unroll
        for (int mb = 0; mb < 2; mb++)
            ldsm4(aq[s][mb], sb + (uint32_t)(SP + aBase + mb * 16 * TSTR + s * 8) * 4);

    float co[2][8][4];
    #pragma unroll
    for (int mb = 0; mb < 2; mb++)
        #pragma unroll
        for (int ni = 0; ni < 8; ni++)
            #pragma unroll
            for (int r = 0; r < 4; r++) co[mb][ni][r] = 0.f;
    float mx[2][2], li[2][2];
    #pragma unroll
    for (int mb = 0; mb < 2; mb++)
        #pragma unroll
        for (int h = 0; h < 2; h++) { mx[mb][h] = -INFINITY; li[mb][h] = 0.f; }

    auto load_kv = [&](int kt, int b) {
        const int koff = b ? SK1 : SK0, voff = b ? SV1 : SV0;
        #pragma unroll
        for (int i = 0; i < 8; i++) {
            const int id = tid + 128 * i;
            const int row = id >> 4, c = id & 15;
            CP_ASYNC16(sb + (uint32_t)(koff + row * TSTR + c * 4) * 4,
                       &kb[((size_t)kt * 64 + row) * DKK + c * 4]);
            CP_ASYNC16(sb + (uint32_t)(voff + row * TSTR + c * 4) * 4,
                       &vb[(size_t)row * LL + kt * 64 + c * 4]);
        }
    };
    load_kv(0, 0); CP_COMMIT();

    for (int kt = 0; kt < LL / 64; kt++) {
        __syncthreads();
        if (kt + 1 < LL / 64) { load_kv(kt + 1, (kt + 1) & 1); CP_COMMIT(); CP_WAIT1(); }
        else                  { CP_WAIT0(); }
        __syncthreads();
        const int kbuf = (kt & 1) ? SK1 : SK0;
        const int vbuf = (kt & 1) ? SV1 : SV0;

        // S = Q @ K^T
        float sc[2][8][4];
        #pragma unroll
        for (int mb = 0; mb < 2; mb++)
            #pragma unroll
            for (int ni = 0; ni < 8; ni++)
                #pragma unroll
                for (int r = 0; r < 4; r++) sc[mb][ni][r] = 0.f;
        #pragma unroll
        for (int s = 0; s < 8; s++) {
            uint32_t bf[8][2];
            #pragma unroll
            for (int nb = 0; nb < 4; nb++) {
                uint32_t r[4];
                ldsm4(r, sb + (uint32_t)(kbuf + bBase + nb * 16 * TSTR + s * 8) * 4);
                bf[nb * 2][0] = r[0]; bf[nb * 2][1] = r[1];
                bf[nb * 2 + 1][0] = r[2]; bf[nb * 2 + 1][1] = r[3];
            }
            #pragma unroll
            for (int mb = 0; mb < 2; mb++)
                #pragma unroll
                for (int ni = 0; ni < 8; ni++)
                    mma_tf32(sc[mb][ni], aq[s][mb], bf[ni]);
        }

        // Online softmax (4 row-groups: mb x {gq, gq+8})
        #pragma unroll
        for (int mb = 0; mb < 2; mb++) {
            float rm0 = sc[mb][0][0], rm1 = sc[mb][0][2];
            #pragma unroll
            for (int ni = 0; ni < 8; ni++) {
                rm0 = fmaxf(rm0, fmaxf(sc[mb][ni][0], sc[mb][ni][1]));
                rm1 = fmaxf(rm1, fmaxf(sc[mb][ni][2], sc[mb][ni][3]));
            }
            rm0 = fmaxf(rm0, __shfl_xor_sync(0xffffffff, rm0, 1));
            rm0 = fmaxf(rm0, __shfl_xor_sync(0xffffffff, rm0, 2));
            rm1 = fmaxf(rm1, __shfl_xor_sync(0xffffffff, rm1, 1));
            rm1 = fmaxf(rm1, __shfl_xor_sync(0xffffffff, rm1, 2));
            const float nm0 = fmaxf(mx[mb][0], rm0), nm1 = fmaxf(mx[mb][1], rm1);
            const float cr0 = __expf(mx[mb][0] - nm0), cr1 = __expf(mx[mb][1] - nm1);
            float rs0 = 0.f, rs1 = 0.f;
            #pragma unroll
            for (int ni = 0; ni < 8; ni++) {
                const float e00 = __expf(sc[mb][ni][0] - nm0);
                const float e01 = __expf(sc[mb][ni][1] - nm0);
                const float e10 = __expf(sc[mb][ni][2] - nm1);
                const float e11 = __expf(sc[mb][ni][3] - nm1);
                rs0 += e00 + e01;
                rs1 += e10 + e11;
                const int col = ni * 8 + 2 * gt;
                *(float2*)&sm[SP + (wm + mb * 16 + gq) * TSTR + col] =
                    make_float2(__uint_as_float(tf32r(e00)), __uint_as_float(tf32r(e01)));
                *(float2*)&sm[SP + (wm + mb * 16 + gq + 8) * TSTR + col] =
                    make_float2(__uint_as_float(tf32r(e10)), __uint_as_float(tf32r(e11)));
            }
            rs0 += __shfl_xor_sync(0xffffffff, rs0, 1);
            rs0 += __shfl_xor_sync(0xffffffff, rs0, 2);
            rs1 += __shfl_xor_sync(0xffffffff, rs1, 1);
            rs1 += __shfl_xor_sync(0xffffffff, rs1, 2);
            mx[mb][0] = nm0; mx[mb][1] = nm1;
            li[mb][0] = li[mb][0] * cr0 + rs0;
            li[mb][1] = li[mb][1] * cr1 + rs1;
            #pragma unroll
            for (int ni = 0; ni < 8; ni++) {
                co[mb][ni][0] *= cr0; co[mb][ni][1] *= cr0;
                co[mb][ni][2] *= cr1; co[mb][ni][3] *= cr1;
            }
        }
        __syncwarp();   // P rows are warp-private; order STS before ldmatrix

        // ctx += P @ V
        #pragma unroll
        for (int s = 0; s < 8; s++) {
            uint32_t ap[2][4];
            #pragma unroll
            for (int mb = 0; mb < 2; mb++)
                ldsm4(ap[mb], sb + (uint32_t)(SP + aBase + mb * 16 * TSTR + s * 8) * 4);
            uint32_t bv_[8][2];
            #pragma unroll
            for (int nb = 0; nb < 4; nb++) {
                uint32_t r[4];
                ldsm4(r, sb + (uint32_t)(vbuf + bBase + nb * 16 * TSTR + s * 8) * 4);
                bv_[nb * 2][0] = r[0]; bv_[nb * 2][1] = r[1];
                bv_[nb * 2 + 1][0] = r[2]; bv_[nb * 2 + 1][1] = r[3];
            }
            #pragma unroll
            for (int mb = 0; mb < 2; mb++)
                #pragma unroll
                for (int ni = 0; ni < 8; ni++)
                    mma_tf32(co[mb][ni], ap[mb], bv_[ni]);
        }
        __syncwarp();
    }

    // Epilogue: normalize, round to tf32 (out-proj consumes without cvt)
    #pragma unroll
    for (int mb = 0; mb < 2; mb++) {
        const float inv0 = 1.f / li[mb][0], inv1 = 1.f / li[mb][1];
        const int row0 = q0 + wm + mb * 16 + gq, row1 = row0 + 8;
        #pragma unroll
        for (int ni = 0; ni < 8; ni++) {
            const int col = ni * 8 + 2 * gt;
            float2 o0 = make_float2(__uint_as_float(tf32r(co[mb][ni][0] * inv0)),
                                    __uint_as_float(tf32r(co[mb][ni][1] * inv0)));
            float2 o1 = make_float2(__uint_as_float(tf32r(co[mb][ni][2] * inv1)),
                                    __uint_as_float(tf32r(co[mb][ni][3] * inv1)));
            *(float2*)&ctx[((size_t)bh * LL + row0) * DKK + col] = o0;
            *(float2*)&ctx[((size_t)bh * LL + row1) * DKK + col] = o1;
        }
    }
}

// ---------------------------------------------------------------------------
extern "C" void kernel_launch(void* const* d_in, const int* in_sizes, int n_in,
                              void* d_out, int out_size)
{
    const float* x_q = (const float*)d_in[0];
    const float* x_k = (const float*)d_in[1];
    const float* x_v = (const float*)d_in[2];
    const float* Wq  = (const float*)d_in[3];
    const float* bq  = (const float*)d_in[4];
    const float* Wk  = (const float*)d_in[5];
    const float* bk  = (const float*)d_in[6];
    const float* Wv  = (const float*)d_in[7];
    const float* bv  = (const float*)d_in[8];
    const float* Wo  = (const float*)d_in[9];
    const float* bo  = (const float*)d_in[10];
    float* out = (float*)d_out;

    float *pq, *pk, *pv, *pctx, *pwt;
    cudaGetSymbolAddress((void**)&pq,   g_q);
    cudaGetSymbolAddress((void**)&pk,   g_k);
    cudaGetSymbolAddress((void**)&pv,   g_v);
    cudaGetSymbolAddress((void**)&pctx, g_ctx);
    cudaGetSymbolAddress((void**)&pwt,  g_wt);
    float* wto = pwt + 3 * DD * NN;

    cudaFuncSetAttribute(gemm_qkv, cudaFuncAttributeMaxDynamicSharedMemorySize, GSMEM);
    cudaFuncSetAttribute(gemm_out, cudaFuncAttributeMaxDynamicSharedMemorySize, GSMEM);
    cudaFuncSetAttribute(attn_mma, cudaFuncAttributeMaxDynamicSharedMemorySize, ATT_SMEM);

    dim3 tgrid(32, 32, 4), tblk(32, 8);
    dim3 qkvgrid(8, 32, 3);
    dim3 ggrid(8, 32);
    dim3 agrid(LL / ATT_BM, BB * HH);

    transpose_round4<<<tgrid, tblk>>>(Wq, Wk, Wv, Wo, pwt);

    gemm_qkv<<<qkvgrid, 128, GSMEM>>>(x_q, x_k, x_v, pwt, bq, bk, bv, pq, pk, pv);

    attn_mma<<<agrid, 128, ATT_SMEM>>>(pq, pk, pv, pctx);

    gemm_out<<<ggrid, 128, GSMEM>>>(pctx, wto, bo, out);
}

// round 9
// speedup vs baseline: 7.4612x; 1.7203x over previous
#include <cuda_runtime.h>
#include <cuda_fp16.h>
#include <math.h>
#include <stdint.h>

// Problem dims
#define BB 2
#define LL 2048
#define DD 1024
#define HH 16
#define DKK 64
#define MM (BB*LL)     // 4096
#define NN 1024        // H*DK

// ---------------------------------------------------------------------------
// Device scratch (no cudaMalloc allowed)
// ---------------------------------------------------------------------------
__device__ __half g_qh  [BB*HH*LL*DKK];   // (b,h,l,dk)  fp16, pre-scaled 1/8
__device__ __half g_kh  [BB*HH*LL*DKK];   // (b,h,l,dk)  fp16
__device__ __half g_vh  [BB*HH*LL*DKK];   // (b,h,dk,l)  fp16, transposed
__device__ __half g_ctxh[BB*HH*LL*DKK];   // (b,h,l,dk)  fp16
__device__ __half g_xh  [3*MM*DD];        // fp16 activations (q,k,v inputs)
__device__ __half g_wth [4*DD*NN];        // W^T fp16: Wt[n][k]

// ---------------------------------------------------------------------------
// Helpers
// ---------------------------------------------------------------------------
__device__ __forceinline__ uint32_t smem_u32(const void* p) {
    uint32_t a;
    asm("{ .reg .u64 t; cvta.to.shared.u64 t, %1; cvt.u32.u64 %0, t; }"
        : "=r"(a) : "l"(p));
    return a;
}

#define CP_ASYNC16(dst, src) \
    asm volatile("cp.async.cg.shared.global [%0], [%1], 16;" :: "r"(dst), "l"(src))
#define CP_COMMIT()  asm volatile("cp.async.commit_group;" ::: "memory")
#define CP_WAIT1()   asm volatile("cp.async.wait_group 1;" ::: "memory")
#define CP_WAIT0()   asm volatile("cp.async.wait_group 0;" ::: "memory")

// m16n8k16 fp16 MMA, fp32 accumulate
__device__ __forceinline__ void mma_f16(float* c, const uint32_t* a, const uint32_t* b) {
    asm volatile(
        "mma.sync.aligned.m16n8k16.row.col.f32.f16.f16.f32 "
        "{%0,%1,%2,%3}, {%4,%5,%6,%7}, {%8,%9}, {%0,%1,%2,%3};"
        : "+f"(c[0]), "+f"(c[1]), "+f"(c[2]), "+f"(c[3])
        : "r"(a[0]), "r"(a[1]), "r"(a[2]), "r"(a[3]), "r"(b[0]), "r"(b[1]));
}

__device__ __forceinline__ void ldsm4(uint32_t* r, uint32_t addr) {
    asm volatile("ldmatrix.sync.aligned.m8n8.x4.shared.b16 {%0,%1,%2,%3}, [%4];"
                 : "=r"(r[0]), "=r"(r[1]), "=r"(r[2]), "=r"(r[3]) : "r"(addr));
}

// ---------------------------------------------------------------------------
// Pre-pass 1: transpose + fp16-round weights (grid.z selects matrix)
// ---------------------------------------------------------------------------
__global__ __launch_bounds__(256)
void transpose_half4(const float* __restrict__ W0, const float* __restrict__ W1,
                     const float* __restrict__ W2, const float* __restrict__ W3,
                     __half* __restrict__ T)
{
    const float* W = (blockIdx.z == 0) ? W0 : (blockIdx.z == 1) ? W1
                   : (blockIdx.z == 2) ? W2 : W3;
    __half* Wt = T + (size_t)blockIdx.z * DD * NN;
    __shared__ float t[32][33];
    int x = blockIdx.x * 32 + threadIdx.x;
    int y = blockIdx.y * 32 + threadIdx.y;
    #pragma unroll
    for (int i = 0; i < 32; i += 8)
        t[threadIdx.y + i][threadIdx.x] = W[(size_t)(y + i) * 1024 + x];
    __syncthreads();
    x = blockIdx.y * 32 + threadIdx.x;
    y = blockIdx.x * 32 + threadIdx.y;
    #pragma unroll
    for (int i = 0; i < 32; i += 8)
        Wt[(size_t)(y + i) * 1024 + x] = __float2half_rn(t[threadIdx.x][threadIdx.y + i]);
}

// ---------------------------------------------------------------------------
// Pre-pass 2: convert activations to fp16 (grid.y = 0:q, 1:k, 2:v)
// ---------------------------------------------------------------------------
__global__ __launch_bounds__(256)
void cvt_half3(const float* __restrict__ x0, const float* __restrict__ x1,
               const float* __restrict__ x2, __half* __restrict__ o)
{
    const float* x = (blockIdx.y == 0) ? x0 : (blockIdx.y == 1) ? x1 : x2;
    __half* dst = o + (size_t)blockIdx.y * MM * DD;
    int i = blockIdx.x * 256 + threadIdx.x;        // over float4
    float4 v = *(const float4*)&x[(size_t)i * 4];
    __half2 h0 = __floats2half2_rn(v.x, v.y);
    __half2 h1 = __floats2half2_rn(v.z, v.w);
    *(__half2*)&dst[(size_t)i * 4]     = h0;
    *(__half2*)&dst[(size_t)i * 4 + 2] = h1;
}

// ---------------------------------------------------------------------------
// fp16 GEMM machinery: 128x128 CTA, 256 thr = 8 warps (2x4), warp 64x32.
// K-chunk 64 halves, 3-stage cp.async, 1 barrier per chunk.
// ---------------------------------------------------------------------------
static constexpr int HSTR   = 72;                   // row stride in halves (144B)
static constexpr int GTILEH = 128 * HSTR;           // halves per tile
static constexpr int GSMEM  = 6 * GTILEH * 2;       // 110592 B; x2 CTAs fits

struct GemmCtx {
    uint32_t sb;
    int tid, lane, wm, wn, gq, gt, aBase, bBase, m0, n0;
};

__device__ __forceinline__ void gemm_init(GemmCtx& g, const void* smem) {
    g.sb   = smem_u32(smem);
    g.tid  = threadIdx.x;
    g.lane = g.tid & 31;
    const int wid = g.tid >> 5;
    g.wm   = (wid >> 2) * 64;
    g.wn   = (wid & 3) * 32;
    g.gq   = g.lane >> 2;
    g.gt   = g.lane & 3;
    const int l7 = g.lane & 7, lg8 = (g.lane >> 3) & 1, lg16 = g.lane >> 4;
    g.aBase = (g.wm + l7 + lg8 * 8) * HSTR + lg16 * 8;   // halves
    g.bBase = (g.wn + lg16 * 8 + l7) * HSTR + lg8 * 8;   // halves
    g.m0 = blockIdx.y * 128;
    g.n0 = blockIdx.x * 128;
}

// GATHER: 0 = A plain rows [m][k]; 1 = A gathered from (b,h,l,dk)
template<int GATHER>
__device__ __forceinline__ void gemm_load_chunk(const GemmCtx& g, const __half* A,
                                                const __half* Wt, int ck, int st) {
    const int k0 = ck * 64;
    const uint32_t sa = g.sb + (uint32_t)(2 * st) * GTILEH * 2;
    const uint32_t sw = g.sb + (uint32_t)(2 * st + 1) * GTILEH * 2;
    #pragma unroll
    for (int i = 0; i < 4; i++) {
        const int id  = g.tid + 256 * i;
        const int row = id >> 3;
        const int cs  = id & 7;                    // 8-half (16B) chunk
        const __half* ga;
        if (!GATHER) {
            ga = &A[(size_t)(g.m0 + row) * 1024 + k0 + cs * 8];
        } else {
            const int m  = g.m0 + row;
            const int bb = m >> 11, l = m & 2047;
            const int kk = k0 + cs * 8;
            const int h  = kk >> 6, d = kk & 63;
            ga = &A[(size_t)((bb * HH + h) * LL + l) * DKK + d];
        }
        CP_ASYNC16(sa + (uint32_t)(row * HSTR + cs * 8) * 2, ga);
        CP_ASYNC16(sw + (uint32_t)(row * HSTR + cs * 8) * 2,
                   &Wt[(size_t)(g.n0 + row) * 1024 + k0 + cs * 8]);
    }
}

template<int GATHER>
__device__ __forceinline__ void gemm_main(const GemmCtx& g, const __half* A,
                                          const __half* Wt, float c[4][4][4]) {
    #pragma unroll
    for (int mi = 0; mi < 4; mi++)
        #pragma unroll
        for (int ni = 0; ni < 4; ni++)
            #pragma unroll
            for (int r = 0; r < 4; r++) c[mi][ni][r] = 0.f;

    gemm_load_chunk<GATHER>(g, A, Wt, 0, 0); CP_COMMIT();
    gemm_load_chunk<GATHER>(g, A, Wt, 1, 1); CP_COMMIT();

    for (int ck = 0; ck < 16; ck++) {
        if (ck < 15) CP_WAIT1(); else CP_WAIT0();
        __syncthreads();
        const int st = ck % 3;
        const uint32_t As = g.sb + (uint32_t)(2 * st) * GTILEH * 2;
        const uint32_t Ws = g.sb + (uint32_t)(2 * st + 1) * GTILEH * 2;

        #pragma unroll
        for (int ks = 0; ks < 4; ks++) {          // k16 steps within k64 chunk
            uint32_t a[4][4];
            #pragma unroll
            for (int mi = 0; mi < 4; mi++)
                ldsm4(a[mi], As + (uint32_t)(g.aBase + mi * 16 * HSTR + ks * 16) * 2);
            uint32_t b[4][2];
            #pragma unroll
            for (int nb = 0; nb < 2; nb++) {
                uint32_t r[4];
                ldsm4(r, Ws + (uint32_t)(g.bBase + nb * 16 * HSTR + ks * 16) * 2);
                b[nb * 2][0] = r[0]; b[nb * 2][1] = r[1];
                b[nb * 2 + 1][0] = r[2]; b[nb * 2 + 1][1] = r[3];
            }
            #pragma unroll
            for (int mi = 0; mi < 4; mi++)
                #pragma unroll
                for (int ni = 0; ni < 4; ni++)
                    mma_f16(c[mi][ni], a[mi], b[ni]);
        }
        if (ck + 2 < 16) { gemm_load_chunk<GATHER>(g, A, Wt, ck + 2, (ck + 2) % 3); CP_COMMIT(); }
    }
}

// ---------------------------------------------------------------------------
// Fused QKV projection GEMM (grid.z = 0:Q, 1:K, 2:V)
// ---------------------------------------------------------------------------
__global__ __launch_bounds__(256, 2)
void gemm_qkv(const __half* __restrict__ xh, const __half* __restrict__ wt,
              const float* __restrict__ bq, const float* __restrict__ bk,
              const float* __restrict__ bv,
              __half* __restrict__ oq, __half* __restrict__ ok, __half* __restrict__ ov)
{
    extern __shared__ char smem[];
    GemmCtx g; gemm_init(g, smem);
    const int z = blockIdx.z;
    const __half* A    = xh + (size_t)z * MM * DD;
    const __half* Wt   = wt + (size_t)z * DD * NN;
    const float* bias  = (z == 0) ? bq : (z == 1) ? bk : bv;
    __half* C          = (z == 0) ? oq : (z == 1) ? ok : ov;
    const float scale  = (z == 0) ? 0.125f : 1.0f;

    float c[4][4][4];
    gemm_main<0>(g, A, Wt, c);

    #pragma unroll
    for (int mi = 0; mi < 4; mi++) {
        const int row = g.m0 + g.wm + mi * 16 + g.gq;
        #pragma unroll
        for (int ni = 0; ni < 4; ni++) {
            const int col = g.n0 + g.wn + ni * 8 + 2 * g.gt;
            const float b0 = bias[col], b1 = bias[col + 1];
            const float v0 = (c[mi][ni][0] + b0) * scale;
            const float v1 = (c[mi][ni][1] + b1) * scale;
            const float v2 = (c[mi][ni][2] + b0) * scale;
            const float v3 = (c[mi][ni][3] + b1) * scale;
            const int h = col >> 6, d = col & 63;
            const int bb0 = row >> 11, l0 = row & 2047;
            const int r8 = row + 8;
            const int bb1 = r8 >> 11, l1 = r8 & 2047;
            if (z != 2) {
                *(__half2*)&C[(size_t)((bb0 * HH + h) * LL + l0) * DKK + d] =
                    __floats2half2_rn(v0, v1);
                *(__half2*)&C[(size_t)((bb1 * HH + h) * LL + l1) * DKK + d] =
                    __floats2half2_rn(v2, v3);
            } else {   // V: transposed scatter (b,h,dk,l)
                C[((size_t)(bb0 * HH + h) * DKK + d)     * LL + l0] = __float2half_rn(v0);
                C[((size_t)(bb0 * HH + h) * DKK + d + 1) * LL + l0] = __float2half_rn(v1);
                C[((size_t)(bb1 * HH + h) * DKK + d)     * LL + l1] = __float2half_rn(v2);
                C[((size_t)(bb1 * HH + h) * DKK + d + 1) * LL + l1] = __float2half_rn(v3);
            }
        }
    }
}

// ---------------------------------------------------------------------------
// Output projection: out = ctx(fp16, gathered) @ Wo^T + bo   (fp32 out)
// ---------------------------------------------------------------------------
__global__ __launch_bounds__(256, 2)
void gemm_out(const __half* __restrict__ ctx, const __half* __restrict__ wt,
              const float* __restrict__ bias, float* __restrict__ C)
{
    extern __shared__ char smem[];
    GemmCtx g; gemm_init(g, smem);

    float c[4][4][4];
    gemm_main<1>(g, ctx, wt, c);

    #pragma unroll
    for (int mi = 0; mi < 4; mi++) {
        const int row = g.m0 + g.wm + mi * 16 + g.gq;
        #pragma unroll
        for (int ni = 0; ni < 4; ni++) {
            const int col = g.n0 + g.wn + ni * 8 + 2 * g.gt;
            const float b0 = bias[col], b1 = bias[col + 1];
            *(float2*)&C[(size_t)row * 1024 + col] =
                make_float2(c[mi][ni][0] + b0, c[mi][ni][1] + b1);
            *(float2*)&C[(size_t)(row + 8) * 1024 + col] =
                make_float2(c[mi][ni][2] + b0, c[mi][ni][3] + b1);
        }
    }
}

// ---------------------------------------------------------------------------
// fp16 tensor-core flash attention.
//   256 thr = 8 warps, BM=128, warp = 16 q-rows. KV tile 64, dbl-buffered.
//   Q/K (b,h,l,dk) fp16; V (b,h,dk,l) fp16. P stored fp16 in smem.
// ---------------------------------------------------------------------------
static constexpr int SK0 = 0;
static constexpr int SK1 = SK0 + 64 * HSTR;
static constexpr int SV0 = SK1 + 64 * HSTR;
static constexpr int SV1 = SV0 + 64 * HSTR;
static constexpr int SP  = SV1 + 64 * HSTR;
static constexpr int ATT_SMEM = (SP + 128 * HSTR) * 2;   // 55296 bytes

__global__ __launch_bounds__(256, 2)
void attn_mma(const __half* __restrict__ q, const __half* __restrict__ k,
              const __half* __restrict__ v, __half* __restrict__ ctx)
{
    extern __shared__ char smraw[];
    __half* smh = (__half*)smraw;
    const uint32_t sb = smem_u32(smraw);
    const int tid = threadIdx.x, lane = tid & 31, wid = tid >> 5;
    const int gq = lane >> 2, gt = lane & 3;
    const int l7 = lane & 7, lg8 = (lane >> 3) & 1, lg16 = lane >> 4;
    const int wm = wid * 16;
    const int bh = blockIdx.y;
    const int q0 = blockIdx.x * 128;
    const __half* kb = k + (size_t)bh * LL * DKK;
    const __half* vb = v + (size_t)bh * DKK * LL;

    const int aBase = (wm + l7 + lg8 * 8) * HSTR + lg16 * 8;   // halves; +s*16
    const int bBase = (lg16 * 8 + l7) * HSTR + lg8 * 8;        // +nb*16*HSTR +s*16

    // Stage Q tile (128 rows x 64 halves)
    {
        const int row = tid >> 1, part = (tid & 1) * 32;
        const __half* gp = q + ((size_t)bh * LL + q0 + row) * DKK + part;
        #pragma unroll
        for (int i = 0; i < 4; i++)
            *(uint4*)&smh[SP + row * HSTR + part + i * 8] = *(const uint4*)&gp[i * 8];
    }
    __syncthreads();
    uint32_t aq[4][4];
    #pragma unroll
    for (int s = 0; s < 4; s++)
        ldsm4(aq[s], sb + (uint32_t)(SP + aBase + s * 16) * 2);

    float co[8][4];
    #pragma unroll
    for (int ni = 0; ni < 8; ni++)
        #pragma unroll
        for (int r = 0; r < 4; r++) co[ni][r] = 0.f;
    float m0 = -INFINITY, m1 = -INFINITY, l0 = 0.f, l1 = 0.f;

    auto load_kv = [&](int kt, int b) {
        const int koff = b ? SK1 : SK0, voff = b ? SV1 : SV0;
        #pragma unroll
        for (int i = 0; i < 2; i++) {
            const int id = tid + 256 * i;
            const int row = id >> 3, c = id & 7;
            CP_ASYNC16(sb + (uint32_t)(koff + row * HSTR + c * 8) * 2,
                       &kb[((size_t)kt * 64 + row) * DKK + c * 8]);
            CP_ASYNC16(sb + (uint32_t)(voff + row * HSTR + c * 8) * 2,
                       &vb[(size_t)row * LL + kt * 64 + c * 8]);
        }
    };
    load_kv(0, 0); CP_COMMIT();

    for (int kt = 0; kt < LL / 64; kt++) {
        __syncthreads();
        if (kt + 1 < LL / 64) { load_kv(kt + 1, (kt + 1) & 1); CP_COMMIT(); CP_WAIT1(); }
        else                  { CP_WAIT0(); }
        __syncthreads();
        const int kbuf = (kt & 1) ? SK1 : SK0;
        const int vbuf = (kt & 1) ? SV1 : SV0;

        // S = Q @ K^T
        float sc[8][4];
        #pragma unroll
        for (int ni = 0; ni < 8; ni++)
            #pragma unroll
            for (int r = 0; r < 4; r++) sc[ni][r] = 0.f;
        #pragma unroll
        for (int s = 0; s < 4; s++) {
            uint32_t bf[8][2];
            #pragma unroll
            for (int nb = 0; nb < 4; nb++) {
                uint32_t r[4];
                ldsm4(r, sb + (uint32_t)(kbuf + bBase + nb * 16 * HSTR + s * 16) * 2);
                bf[nb * 2][0] = r[0]; bf[nb * 2][1] = r[1];
                bf[nb * 2 + 1][0] = r[2]; bf[nb * 2 + 1][1] = r[3];
            }
            #pragma unroll
            for (int ni = 0; ni < 8; ni++)
                mma_f16(sc[ni], aq[s], bf[ni]);
        }

        // Online softmax (fp32)
        float rm0 = sc[0][0], rm1 = sc[0][2];
        #pragma unroll
        for (int ni = 0; ni < 8; ni++) {
            rm0 = fmaxf(rm0, fmaxf(sc[ni][0], sc[ni][1]));
            rm1 = fmaxf(rm1, fmaxf(sc[ni][2], sc[ni][3]));
        }
        rm0 = fmaxf(rm0, __shfl_xor_sync(0xffffffff, rm0, 1));
        rm0 = fmaxf(rm0, __shfl_xor_sync(0xffffffff, rm0, 2));
        rm1 = fmaxf(rm1, __shfl_xor_sync(0xffffffff, rm1, 1));
        rm1 = fmaxf(rm1, __shfl_xor_sync(0xffffffff, rm1, 2));
        const float nm0 = fmaxf(m0, rm0), nm1 = fmaxf(m1, rm1);
        const float cr0 = __expf(m0 - nm0), cr1 = __expf(m1 - nm1);
        float rs0 = 0.f, rs1 = 0.f;
        #pragma unroll
        for (int ni = 0; ni < 8; ni++) {
            const float e00 = __expf(sc[ni][0] - nm0);
            const float e01 = __expf(sc[ni][1] - nm0);
            const float e10 = __expf(sc[ni][2] - nm1);
            const float e11 = __expf(sc[ni][3] - nm1);
            rs0 += e00 + e01;
            rs1 += e10 + e11;
            const int col = ni * 8 + 2 * gt;
            *(__half2*)&smh[SP + (wm + gq) * HSTR + col]     = __floats2half2_rn(e00, e01);
            *(__half2*)&smh[SP + (wm + gq + 8) * HSTR + col] = __floats2half2_rn(e10, e11);
        }
        rs0 += __shfl_xor_sync(0xffffffff, rs0, 1);
        rs0 += __shfl_xor_sync(0xffffffff, rs0, 2);
        rs1 += __shfl_xor_sync(0xffffffff, rs1, 1);
        rs1 += __shfl_xor_sync(0xffffffff, rs1, 2);
        m0 = nm0; m1 = nm1;
        l0 = l0 * cr0 + rs0;
        l1 = l1 * cr1 + rs1;
        #pragma unroll
        for (int ni = 0; ni < 8; ni++) {
            co[ni][0] *= cr0; co[ni][1] *= cr0;
            co[ni][2] *= cr1; co[ni][3] *= cr1;
        }
        __syncwarp();   // P rows warp-private; order STS before ldmatrix

        // ctx += P @ V
        #pragma unroll
        for (int s = 0; s < 4; s++) {
            uint32_t ap[4];
            ldsm4(ap, sb + (uint32_t)(SP + aBase + s * 16) * 2);
            uint32_t bv_[8][2];
            #pragma unroll
            for (int nb = 0; nb < 4; nb++) {
                uint32_t r[4];
                ldsm4(r, sb + (uint32_t)(vbuf + bBase + nb * 16 * HSTR + s * 16) * 2);
                bv_[nb * 2][0] = r[0]; bv_[nb * 2][1] = r[1];
                bv_[nb * 2 + 1][0] = r[2]; bv_[nb * 2 + 1][1] = r[3];
            }
            #pragma unroll
            for (int ni = 0; ni < 8; ni++)
                mma_f16(co[ni], ap, bv_[ni]);
        }
        __syncwarp();
    }

    // Epilogue: normalize, store ctx fp16
    const float inv0 = 1.f / l0, inv1 = 1.f / l1;
    const int row0 = q0 + wm + gq, row1 = row0 + 8;
    #pragma unroll
    for (int ni = 0; ni < 8; ni++) {
        const int col = ni * 8 + 2 * gt;
        *(__half2*)&ctx[((size_t)bh * LL + row0) * DKK + col] =
            __floats2half2_rn(co[ni][0] * inv0, co[ni][1] * inv0);
        *(__half2*)&ctx[((size_t)bh * LL + row1) * DKK + col] =
            __floats2half2_rn(co[ni][2] * inv1, co[ni][3] * inv1);
    }
}

// ---------------------------------------------------------------------------
extern "C" void kernel_launch(void* const* d_in, const int* in_sizes, int n_in,
                              void* d_out, int out_size)
{
    const float* x_q = (const float*)d_in[0];
    const float* x_k = (const float*)d_in[1];
    const float* x_v = (const float*)d_in[2];
    const float* Wq  = (const float*)d_in[3];
    const float* bq  = (const float*)d_in[4];
    const float* Wk  = (const float*)d_in[5];
    const float* bk  = (const float*)d_in[6];
    const float* Wv  = (const float*)d_in[7];
    const float* bv  = (const float*)d_in[8];
    const float* Wo  = (const float*)d_in[9];
    const float* bo  = (const float*)d_in[10];
    float* out = (float*)d_out;

    __half *pq, *pk, *pv, *pctx, *pxh, *pwt;
    cudaGetSymbolAddress((void**)&pq,   g_qh);
    cudaGetSymbolAddress((void**)&pk,   g_kh);
    cudaGetSymbolAddress((void**)&pv,   g_vh);
    cudaGetSymbolAddress((void**)&pctx, g_ctxh);
    cudaGetSymbolAddress((void**)&pxh,  g_xh);
    cudaGetSymbolAddress((void**)&pwt,  g_wth);
    __half* wto = pwt + (size_t)3 * DD * NN;

    cudaFuncSetAttribute(gemm_qkv, cudaFuncAttributeMaxDynamicSharedMemorySize, GSMEM);
    cudaFuncSetAttribute(gemm_out, cudaFuncAttributeMaxDynamicSharedMemorySize, GSMEM);
    cudaFuncSetAttribute(attn_mma, cudaFuncAttributeMaxDynamicSharedMemorySize, ATT_SMEM);

    dim3 tgrid(32, 32, 4), tblk(32, 8);
    dim3 cgrid(MM * DD / (256 * 4), 3);
    dim3 qkvgrid(8, 32, 3);
    dim3 ggrid(8, 32);
    dim3 agrid(LL / 128, BB * HH);

    transpose_half4<<<tgrid, tblk>>>(Wq, Wk, Wv, Wo, pwt);
    cvt_half3<<<cgrid, 256>>>(x_q, x_k, x_v, pxh);

    gemm_qkv<<<qkvgrid, 256, GSMEM>>>(pxh, pwt, bq, bk, bv, pq, pk, pv);

    attn_mma<<<agrid, 256, ATT_SMEM>>>(pq, pk, pv, pctx);

    gemm_out<<<ggrid, 256, GSMEM>>>(pctx, wto, bo, out);
}

// round 11
// speedup vs baseline: 8.0971x; 1.0852x over previous
#include <cuda_runtime.h>
#include <cuda_fp16.h>
#include <math.h>
#include <stdint.h>

// Problem dims
#define BB 2
#define LL 2048
#define DD 1024
#define HH 16
#define DKK 64
#define MM (BB*LL)     // 4096
#define NN 1024        // H*DK

// ---------------------------------------------------------------------------
// Device scratch (no cudaMalloc allowed)
// ---------------------------------------------------------------------------
__device__ __half g_qh  [BB*HH*LL*DKK];   // (b,h,l,dk)  fp16, pre-scaled log2e/8
__device__ __half g_kh  [BB*HH*LL*DKK];   // (b,h,l,dk)  fp16
__device__ __half g_vh  [BB*HH*LL*DKK];   // (b,h,dk,l)  fp16, transposed
__device__ __half g_ctxh[BB*HH*LL*DKK];   // (b,h,l,dk)  fp16
__device__ __half g_xh  [3*MM*DD];        // fp16 activations (q,k,v inputs)
__device__ __half g_wth [4*DD*NN];        // W^T fp16: Wt[n][k]

// ---------------------------------------------------------------------------
// Helpers
// ---------------------------------------------------------------------------
__device__ __forceinline__ uint32_t smem_u32(const void* p) {
    uint32_t a;
    asm("{ .reg .u64 t; cvta.to.shared.u64 t, %1; cvt.u32.u64 %0, t; }"
        : "=r"(a) : "l"(p));
    return a;
}
__device__ __forceinline__ float ex2f(float x) {
    float o;
    asm("ex2.approx.ftz.f32 %0, %1;" : "=f"(o) : "f"(x));
    return o;
}
// pack two fp32 -> f16x2 register: result lo = a, hi = b
__device__ __forceinline__ uint32_t packh2(float a, float b) {
    uint32_t o;
    asm("cvt.rn.f16x2.f32 %0, %1, %2;" : "=r"(o) : "f"(b), "f"(a));
    return o;
}

#define CP_ASYNC16(dst, src) \
    asm volatile("cp.async.cg.shared.global [%0], [%1], 16;" :: "r"(dst), "l"(src))
#define CP_COMMIT()  asm volatile("cp.async.commit_group;" ::: "memory")
#define CP_WAIT1()   asm volatile("cp.async.wait_group 1;" ::: "memory")
#define CP_WAIT0()   asm volatile("cp.async.wait_group 0;" ::: "memory")

// m16n8k16 fp16 MMA, fp32 accumulate
__device__ __forceinline__ void mma_f16(float* c, const uint32_t* a, const uint32_t* b) {
    asm volatile(
        "mma.sync.aligned.m16n8k16.row.col.f32.f16.f16.f32 "
        "{%0,%1,%2,%3}, {%4,%5,%6,%7}, {%8,%9}, {%0,%1,%2,%3};"
        : "+f"(c[0]), "+f"(c[1]), "+f"(c[2]), "+f"(c[3])
        : "r"(a[0]), "r"(a[1]), "r"(a[2]), "r"(a[3]), "r"(b[0]), "r"(b[1]));
}

__device__ __forceinline__ void ldsm4(uint32_t* r, uint32_t addr) {
    asm volatile("ldmatrix.sync.aligned.m8n8.x4.shared.b16 {%0,%1,%2,%3}, [%4];"
                 : "=r"(r[0]), "=r"(r[1]), "=r"(r[2]), "=r"(r[3]) : "r"(addr));
}

// ---------------------------------------------------------------------------
// Pre-pass 1: transpose + fp16-round weights (grid.z selects matrix)
// ---------------------------------------------------------------------------
__global__ __launch_bounds__(256)
void transpose_half4(const float* __restrict__ W0, const float* __restrict__ W1,
                     const float* __restrict__ W2, const float* __restrict__ W3,
                     __half* __restrict__ T)
{
    const float* W = (blockIdx.z == 0) ? W0 : (blockIdx.z == 1) ? W1
                   : (blockIdx.z == 2) ? W2 : W3;
    __half* Wt = T + (size_t)blockIdx.z * DD * NN;
    __shared__ float t[32][33];
    int x = blockIdx.x * 32 + threadIdx.x;
    int y = blockIdx.y * 32 + threadIdx.y;
    #pragma unroll
    for (int i = 0; i < 32; i += 8)
        t[threadIdx.y + i][threadIdx.x] = W[(size_t)(y + i) * 1024 + x];
    __syncthreads();
    x = blockIdx.y * 32 + threadIdx.x;
    y = blockIdx.x * 32 + threadIdx.y;
    #pragma unroll
    for (int i = 0; i < 32; i += 8)
        Wt[(size_t)(y + i) * 1024 + x] = __float2half_rn(t[threadIdx.x][threadIdx.y + i]);
}

// ---------------------------------------------------------------------------
// Pre-pass 2: convert activations to fp16 (grid.y = 0:q, 1:k, 2:v)
// ---------------------------------------------------------------------------
__global__ __launch_bounds__(256)
void cvt_half3(const float* __restrict__ x0, const float* __restrict__ x1,
               const float* __restrict__ x2, __half* __restrict__ o)
{
    const float* x = (blockIdx.y == 0) ? x0 : (blockIdx.y == 1) ? x1 : x2;
    __half* dst = o + (size_t)blockIdx.y * MM * DD;
    int i = blockIdx.x * 256 + threadIdx.x;        // over float4
    float4 v = *(const float4*)&x[(size_t)i * 4];
    __half2 h0 = __floats2half2_rn(v.x, v.y);
    __half2 h1 = __floats2half2_rn(v.z, v.w);
    *(__half2*)&dst[(size_t)i * 4]     = h0;
    *(__half2*)&dst[(size_t)i * 4 + 2] = h1;
}

// ---------------------------------------------------------------------------
// fp16 GEMM machinery: 128x128 CTA, 256 thr = 8 warps (2x4), warp 64x32.
// K-chunk 64 halves, 3-stage cp.async, 1 barrier per chunk.
// ---------------------------------------------------------------------------
static constexpr int HSTR   = 72;                   // row stride in halves (144B)
static constexpr int GTILEH = 128 * HSTR;           // halves per tile
static constexpr int GSMEM  = 6 * GTILEH * 2;       // 110592 B; x2 CTAs fits

struct GemmCtx {
    uint32_t sb;
    int tid, lane, wm, wn, gq, gt, aBase, bBase, m0, n0;
};

__device__ __forceinline__ void gemm_init(GemmCtx& g, const void* smem) {
    g.sb   = smem_u32(smem);
    g.tid  = threadIdx.x;
    g.lane = g.tid & 31;
    const int wid = g.tid >> 5;
    g.wm   = (wid >> 2) * 64;
    g.wn   = (wid & 3) * 32;
    g.gq   = g.lane >> 2;
    g.gt   = g.lane & 3;
    const int l7 = g.lane & 7, lg8 = (g.lane >> 3) & 1, lg16 = g.lane >> 4;
    g.aBase = (g.wm + l7 + lg8 * 8) * HSTR + lg16 * 8;   // halves
    g.bBase = (g.wn + lg16 * 8 + l7) * HSTR + lg8 * 8;   // halves
    g.m0 = blockIdx.y * 128;
    g.n0 = blockIdx.x * 128;
}

// GATHER: 0 = A plain rows [m][k]; 1 = A gathered from (b,h,l,dk)
template<int GATHER>
__device__ __forceinline__ void gemm_load_chunk(const GemmCtx& g, const __half* A,
                                                const __half* Wt, int ck, int st) {
    const int k0 = ck * 64;
    const uint32_t sa = g.sb + (uint32_t)(2 * st) * GTILEH * 2;
    const uint32_t sw = g.sb + (uint32_t)(2 * st + 1) * GTILEH * 2;
    #pragma unroll
    for (int i = 0; i < 4; i++) {
        const int id  = g.tid + 256 * i;
        const int row = id >> 3;
        const int cs  = id & 7;                    // 8-half (16B) chunk
        const __half* ga;
        if (!GATHER) {
            ga = &A[(size_t)(g.m0 + row) * 1024 + k0 + cs * 8];
        } else {
            const int m  = g.m0 + row;
            const int bb = m >> 11, l = m & 2047;
            const int kk = k0 + cs * 8;
            const int h  = kk >> 6, d = kk & 63;
            ga = &A[(size_t)((bb * HH + h) * LL + l) * DKK + d];
        }
        CP_ASYNC16(sa + (uint32_t)(row * HSTR + cs * 8) * 2, ga);
        CP_ASYNC16(sw + (uint32_t)(row * HSTR + cs * 8) * 2,
                   &Wt[(size_t)(g.n0 + row) * 1024 + k0 + cs * 8]);
    }
}

template<int GATHER>
__device__ __forceinline__ void gemm_main(const GemmCtx& g, const __half* A,
                                          const __half* Wt, float c[4][4][4]) {
    #pragma unroll
    for (int mi = 0; mi < 4; mi++)
        #pragma unroll
        for (int ni = 0; ni < 4; ni++)
            #pragma unroll
            for (int r = 0; r < 4; r++) c[mi][ni][r] = 0.f;

    gemm_load_chunk<GATHER>(g, A, Wt, 0, 0); CP_COMMIT();
    gemm_load_chunk<GATHER>(g, A, Wt, 1, 1); CP_COMMIT();

    for (int ck = 0; ck < 16; ck++) {
        if (ck < 15) CP_WAIT1(); else CP_WAIT0();
        __syncthreads();
        const int st = ck % 3;
        const uint32_t As = g.sb + (uint32_t)(2 * st) * GTILEH * 2;
        const uint32_t Ws = g.sb + (uint32_t)(2 * st + 1) * GTILEH * 2;

        #pragma unroll
        for (int ks = 0; ks < 4; ks++) {          // k16 steps within k64 chunk
            uint32_t a[4][4];
            #pragma unroll
            for (int mi = 0; mi < 4; mi++)
                ldsm4(a[mi], As + (uint32_t)(g.aBase + mi * 16 * HSTR + ks * 16) * 2);
            uint32_t b[4][2];
            #pragma unroll
            for (int nb = 0; nb < 2; nb++) {
                uint32_t r[4];
                ldsm4(r, Ws + (uint32_t)(g.bBase + nb * 16 * HSTR + ks * 16) * 2);
                b[nb * 2][0] = r[0]; b[nb * 2][1] = r[1];
                b[nb * 2 + 1][0] = r[2]; b[nb * 2 + 1][1] = r[3];
            }
            #pragma unroll
            for (int mi = 0; mi < 4; mi++)
                #pragma unroll
                for (int ni = 0; ni < 4; ni++)
                    mma_f16(c[mi][ni], a[mi], b[ni]);
        }
        if (ck + 2 < 16) { gemm_load_chunk<GATHER>(g, A, Wt, ck + 2, (ck + 2) % 3); CP_COMMIT(); }
    }
}

// ---------------------------------------------------------------------------
// Fused QKV projection GEMM (grid.z = 0:Q, 1:K, 2:V)
// ---------------------------------------------------------------------------
__global__ __launch_bounds__(256, 2)
void gemm_qkv(const __half* __restrict__ xh, const __half* __restrict__ wt,
              const float* __restrict__ bq, const float* __restrict__ bk,
              const float* __restrict__ bv,
              __half* __restrict__ oq, __half* __restrict__ ok, __half* __restrict__ ov)
{
    extern __shared__ char smem[];
    GemmCtx g; gemm_init(g, smem);
    const int z = blockIdx.z;
    const __half* A    = xh + (size_t)z * MM * DD;
    const __half* Wt   = wt + (size_t)z * DD * NN;
    const float* bias  = (z == 0) ? bq : (z == 1) ? bk : bv;
    __half* C          = (z == 0) ? oq : (z == 1) ? ok : ov;
    // Q pre-scale: 1/sqrt(64) * log2(e)  -> scores land in log2 domain
    const float scale  = (z == 0) ? 0.125f * 1.4426950408889634f : 1.0f;

    float c[4][4][4];
    gemm_main<0>(g, A, Wt, c);

    #pragma unroll
    for (int mi = 0; mi < 4; mi++) {
        const int row = g.m0 + g.wm + mi * 16 + g.gq;
        #pragma unroll
        for (int ni = 0; ni < 4; ni++) {
            const int col = g.n0 + g.wn + ni * 8 + 2 * g.gt;
            const float b0 = bias[col], b1 = bias[col + 1];
            const float v0 = (c[mi][ni][0] + b0) * scale;
            const float v1 = (c[mi][ni][1] + b1) * scale;
            const float v2 = (c[mi][ni][2] + b0) * scale;
            const float v3 = (c[mi][ni][3] + b1) * scale;
            const int h = col >> 6, d = col & 63;
            const int bb0 = row >> 11, l0 = row & 2047;
            const int r8 = row + 8;
            const int bb1 = r8 >> 11, l1 = r8 & 2047;
            if (z != 2) {
                *(__half2*)&C[(size_t)((bb0 * HH + h) * LL + l0) * DKK + d] =
                    __floats2half2_rn(v0, v1);
                *(__half2*)&C[(size_t)((bb1 * HH + h) * LL + l1) * DKK + d] =
                    __floats2half2_rn(v2, v3);
            } else {   // V: transposed scatter (b,h,dk,l)
                C[((size_t)(bb0 * HH + h) * DKK + d)     * LL + l0] = __float2half_rn(v0);
                C[((size_t)(bb0 * HH + h) * DKK + d + 1) * LL + l0] = __float2half_rn(v1);
                C[((size_t)(bb1 * HH + h) * DKK + d)     * LL + l1] = __float2half_rn(v2);
                C[((size_t)(bb1 * HH + h) * DKK + d + 1) * LL + l1] = __float2half_rn(v3);
            }
        }
    }
}

// ---------------------------------------------------------------------------
// Output projection: out = ctx(fp16, gathered) @ Wo^T + bo   (fp32 out)
// ---------------------------------------------------------------------------
__global__ __launch_bounds__(256, 2)
void gemm_out(const __half* __restrict__ ctx, const __half* __restrict__ wt,
              const float* __restrict__ bias, float* __restrict__ C)
{
    extern __shared__ char smem[];
    GemmCtx g; gemm_init(g, smem);

    float c[4][4][4];
    gemm_main<1>(g, ctx, wt, c);

    #pragma unroll
    for (int mi = 0; mi < 4; mi++) {
        const int row = g.m0 + g.wm + mi * 16 + g.gq;
        #pragma unroll
        for (int ni = 0; ni < 4; ni++) {
            const int col = g.n0 + g.wn + ni * 8 + 2 * g.gt;
            const float b0 = bias[col], b1 = bias[col + 1];
            *(float2*)&C[(size_t)row * 1024 + col] =
                make_float2(c[mi][ni][0] + b0, c[mi][ni][1] + b1);
            *(float2*)&C[(size_t)(row + 8) * 1024 + col] =
                make_float2(c[mi][ni][2] + b0, c[mi][ni][3] + b1);
        }
    }
}

// ---------------------------------------------------------------------------
// fp16 flash attention, register-resident P (C-frag == A-frag layout trick),
// log2-domain softmax (Q pre-scaled by log2e/8; probabilities via ex2).
//   256 thr = 8 warps, BM=128, warp = 16 q-rows. KV tile 64, dbl-buffered.
// ---------------------------------------------------------------------------
static constexpr int SK0 = 0;
static constexpr int SK1 = SK0 + 64 * HSTR;
static constexpr int SV0 = SK1 + 64 * HSTR;
static constexpr int SV1 = SV0 + 64 * HSTR;
static constexpr int SP  = SV1 + 64 * HSTR;               // Q staging only
static constexpr int ATT_SMEM = (SP + 128 * HSTR) * 2;    // 55296 bytes

__global__ __launch_bounds__(256, 2)
void attn_mma(const __half* __restrict__ q, const __half* __restrict__ k,
              const __half* __restrict__ v, __half* __restrict__ ctx)
{
    extern __shared__ char smraw[];
    __half* smh = (__half*)smraw;
    const uint32_t sb = smem_u32(smraw);
    const int tid = threadIdx.x, lane = tid & 31, wid = tid >> 5;
    const int gq = lane >> 2, gt = lane & 3;
    const int l7 = lane & 7, lg8 = (lane >> 3) & 1, lg16 = lane >> 4;
    const int wm = wid * 16;
    const int bh = blockIdx.y;
    const int q0 = blockIdx.x * 128;
    const __half* kb = k + (size_t)bh * LL * DKK;
    const __half* vb = v + (size_t)bh * DKK * LL;

    const int aBase = (wm + l7 + lg8 * 8) * HSTR + lg16 * 8;   // halves; +s*16
    const int bBase = (lg16 * 8 + l7) * HSTR + lg8 * 8;        // +nb*16*HSTR +s*16

    // Stage Q tile (128 rows x 64 halves), then persistent A fragments
    {
        const int row = tid >> 1, part = (tid & 1) * 32;
        const __half* gp = q + ((size_t)bh * LL + q0 + row) * DKK + part;
        #pragma unroll
        for (int i = 0; i < 4; i++)
            *(uint4*)&smh[SP + row * HSTR + part + i * 8] = *(const uint4*)&gp[i * 8];
    }
    __syncthreads();
    uint32_t aq[4][4];
    #pragma unroll
    for (int s = 0; s < 4; s++)
        ldsm4(aq[s], sb + (uint32_t)(SP + aBase + s * 16) * 2);

    float co[8][4];
    #pragma unroll
    for (int ni = 0; ni < 8; ni++)
        #pragma unroll
        for (int r = 0; r < 4; r++) co[ni][r] = 0.f;
    float m0 = -INFINITY, m1 = -INFINITY, l0 = 0.f, l1 = 0.f;

    auto load_kv = [&](int kt, int b) {
        const int koff = b ? SK1 : SK0, voff = b ? SV1 : SV0;
        #pragma unroll
        for (int i = 0; i < 2; i++) {
            const int id = tid + 256 * i;
            const int row = id >> 3, c = id & 7;
            CP_ASYNC16(sb + (uint32_t)(koff + row * HSTR + c * 8) * 2,
                       &kb[((size_t)kt * 64 + row) * DKK + c * 8]);
            CP_ASYNC16(sb + (uint32_t)(voff + row * HSTR + c * 8) * 2,
                       &vb[(size_t)row * LL + kt * 64 + c * 8]);
        }
    };
    load_kv(0, 0); CP_COMMIT();

    for (int kt = 0; kt < LL / 64; kt++) {
        __syncthreads();
        if (kt + 1 < LL / 64) { load_kv(kt + 1, (kt + 1) & 1); CP_COMMIT(); CP_WAIT1(); }
        else                  { CP_WAIT0(); }
        __syncthreads();
        const int kbuf = (kt & 1) ? SK1 : SK0;
        const int vbuf = (kt & 1) ? SV1 : SV0;

        // S = Q @ K^T  (scores already in log2 domain via Q pre-scale)
        float sc[8][4];
        #pragma unroll
        for (int ni = 0; ni < 8; ni++)
            #pragma unroll
            for (int r = 0; r < 4; r++) sc[ni][r] = 0.f;
        #pragma unroll
        for (int s = 0; s < 4; s++) {
            uint32_t bf[8][2];
            #pragma unroll
            for (int nb = 0; nb < 4; nb++) {
                uint32_t r[4];
                ldsm4(r, sb + (uint32_t)(kbuf + bBase + nb * 16 * HSTR + s * 16) * 2);
                bf[nb * 2][0] = r[0]; bf[nb * 2][1] = r[1];
                bf[nb * 2 + 1][0] = r[2]; bf[nb * 2 + 1][1] = r[3];
            }
            #pragma unroll
            for (int ni = 0; ni < 8; ni++)
                mma_f16(sc[ni], aq[s], bf[ni]);
        }

        // Online softmax (log2 domain; probabilities overwrite sc)
        float rm0 = sc[0][0], rm1 = sc[0][2];
        #pragma unroll
        for (int ni = 0; ni < 8; ni++) {
            rm0 = fmaxf(rm0, fmaxf(sc[ni][0], sc[ni][1]));
            rm1 = fmaxf(rm1, fmaxf(sc[ni][2], sc[ni][3]));
        }
        rm0 = fmaxf(rm0, __shfl_xor_sync(0xffffffff, rm0, 1));
        rm0 = fmaxf(rm0, __shfl_xor_sync(0xffffffff, rm0, 2));
        rm1 = fmaxf(rm1, __shfl_xor_sync(0xffffffff, rm1, 1));
        rm1 = fmaxf(rm1, __shfl_xor_sync(0xffffffff, rm1, 2));
        const float nm0 = fmaxf(m0, rm0), nm1 = fmaxf(m1, rm1);
        const float cr0 = ex2f(m0 - nm0), cr1 = ex2f(m1 - nm1);
        float rs0 = 0.f, rs1 = 0.f;
        #pragma unroll
        for (int ni = 0; ni < 8; ni++) {
            sc[ni][0] = ex2f(sc[ni][0] - nm0);
            sc[ni][1] = ex2f(sc[ni][1] - nm0);
            sc[ni][2] = ex2f(sc[ni][2] - nm1);
            sc[ni][3] = ex2f(sc[ni][3] - nm1);
            rs0 += sc[ni][0] + sc[ni][1];
            rs1 += sc[ni][2] + sc[ni][3];
        }
        rs0 += __shfl_xor_sync(0xffffffff, rs0, 1);
        rs0 += __shfl_xor_sync(0xffffffff, rs0, 2);
        rs1 += __shfl_xor_sync(0xffffffff, rs1, 1);
        rs1 += __shfl_xor_sync(0xffffffff, rs1, 2);
        m0 = nm0; m1 = nm1;
        l0 = l0 * cr0 + rs0;
        l1 = l1 * cr1 + rs1;
        #pragma unroll
        for (int ni = 0; ni < 8; ni++) {
            co[ni][0] *= cr0; co[ni][1] *= cr0;
            co[ni][2] *= cr1; co[ni][3] *= cr1;
        }

        // ctx += P @ V : P packs straight from sc (C-frag == A-frag layout)
        #pragma unroll
        for (int s = 0; s < 4; s++) {
            uint32_t ap[4];
            ap[0] = packh2(sc[2*s][0],   sc[2*s][1]);
            ap[1] = packh2(sc[2*s][2],   sc[2*s][3]);
            ap[2] = packh2(sc[2*s+1][0], sc[2*s+1][1]);
            ap[3] = packh2(sc[2*s+1][2], sc[2*s+1][3]);
            uint32_t bv_[8][2];
            #pragma unroll
            for (int nb = 0; nb < 4; nb++) {
                uint32_t r[4];
                ldsm4(r, sb + (uint32_t)(vbuf + bBase + nb * 16 * HSTR + s * 16) * 2);
                bv_[nb * 2][0] = r[0]; bv_[nb * 2][1] = r[1];
                bv_[nb * 2 + 1][0] = r[2]; bv_[nb * 2 + 1][1] = r[3];
            }
            #pragma unroll
            for (int ni = 0; ni < 8; ni++)
                mma_f16(co[ni], ap, bv_[ni]);
        }
    }

    // Epilogue: normalize, store ctx fp16
    const float inv0 = 1.f / l0, inv1 = 1.f / l1;
    const int row0 = q0 + wm + gq, row1 = row0 + 8;
    #pragma unroll
    for (int ni = 0; ni < 8; ni++) {
        const int col = ni * 8 + 2 * gt;
        *(__half2*)&ctx[((size_t)bh * LL + row0) * DKK + col] =
            __floats2half2_rn(co[ni][0] * inv0, co[ni][1] * inv0);
        *(__half2*)&ctx[((size_t)bh * LL + row1) * DKK + col] =
            __floats2half2_rn(co[ni][2] * inv1, co[ni][3] * inv1);
    }
}

// ---------------------------------------------------------------------------
extern "C" void kernel_launch(void* const* d_in, const int* in_sizes, int n_in,
                              void* d_out, int out_size)
{
    const float* x_q = (const float*)d_in[0];
    const float* x_k = (const float*)d_in[1];
    const float* x_v = (const float*)d_in[2];
    const float* Wq  = (const float*)d_in[3];
    const float* bq  = (const float*)d_in[4];
    const float* Wk  = (const float*)d_in[5];
    const float* bk  = (const float*)d_in[6];
    const float* Wv  = (const float*)d_in[7];
    const float* bv  = (const float*)d_in[8];
    const float* Wo  = (const float*)d_in[9];
    const float* bo  = (const float*)d_in[10];
    float* out = (float*)d_out;

    __half *pq, *pk, *pv, *pctx, *pxh, *pwt;
    cudaGetSymbolAddress((void**)&pq,   g_qh);
    cudaGetSymbolAddress((void**)&pk,   g_kh);
    cudaGetSymbolAddress((void**)&pv,   g_vh);
    cudaGetSymbolAddress((void**)&pctx, g_ctxh);
    cudaGetSymbolAddress((void**)&pxh,  g_xh);
    cudaGetSymbolAddress((void**)&pwt,  g_wth);
    __half* wto = pwt + (size_t)3 * DD * NN;

    cudaFuncSetAttribute(gemm_qkv, cudaFuncAttributeMaxDynamicSharedMemorySize, GSMEM);
    cudaFuncSetAttribute(gemm_out, cudaFuncAttributeMaxDynamicSharedMemorySize, GSMEM);
    cudaFuncSetAttribute(attn_mma, cudaFuncAttributeMaxDynamicSharedMemorySize, ATT_SMEM);

    dim3 tgrid(32, 32, 4), tblk(32, 8);
    dim3 cgrid(MM * DD / (256 * 4), 3);
    dim3 qkvgrid(8, 32, 3);
    dim3 ggrid(8, 32);
    dim3 agrid(LL / 128, BB * HH);

    transpose_half4<<<tgrid, tblk>>>(Wq, Wk, Wv, Wo, pwt);
    cvt_half3<<<cgrid, 256>>>(x_q, x_k, x_v, pxh);

    gemm_qkv<<<qkvgrid, 256, GSMEM>>>(pxh, pwt, bq, bk, bv, pq, pk, pv);

    attn_mma<<<agrid, 256, ATT_SMEM>>>(pq, pk, pv, pctx);

    gemm_out<<<ggrid, 256, GSMEM>>>(pctx, wto, bo, out);
}

// round 12
// speedup vs baseline: 8.7956x; 1.0863x over previous
#include <cuda_runtime.h>
#include <cuda_fp16.h>
#include <math.h>
#include <stdint.h>

// Problem dims
#define BB 2
#define LL 2048
#define DD 1024
#define HH 16
#define DKK 64
#define MM (BB*LL)     // 4096
#define NN 1024        // H*DK

// ---------------------------------------------------------------------------
// Device scratch
// ---------------------------------------------------------------------------
__device__ __half g_qh  [BB*HH*LL*DKK];   // (b,h,l,dk)  fp16, pre-scaled log2e/8
__device__ __half g_kh  [BB*HH*LL*DKK];   // (b,h,l,dk)  fp16
__device__ __half g_vh  [BB*HH*LL*DKK];   // (b,h,dk,l)  fp16, transposed
__device__ __half g_ctxh[BB*HH*LL*DKK];   // (b,h,l,dk)  fp16
__device__ __half g_xh  [3*MM*DD];        // fp16 activations
__device__ __half g_wth [4*DD*NN];        // W^T fp16: Wt[n][k]

// ---------------------------------------------------------------------------
// Helpers
// ---------------------------------------------------------------------------
__device__ __forceinline__ uint32_t smem_u32(const void* p) {
    uint32_t a;
    asm("{ .reg .u64 t; cvta.to.shared.u64 t, %1; cvt.u32.u64 %0, t; }"
        : "=r"(a) : "l"(p));
    return a;
}
__device__ __forceinline__ float ex2f(float x) {
    float o;
    asm("ex2.approx.ftz.f32 %0, %1;" : "=f"(o) : "f"(x));
    return o;
}
__device__ __forceinline__ uint32_t packh2(float a, float b) {
    uint32_t o;
    asm("cvt.rn.f16x2.f32 %0, %1, %2;" : "=r"(o) : "f"(b), "f"(a));
    return o;
}

#define CP_ASYNC16(dst, src) \
    asm volatile("cp.async.cg.shared.global [%0], [%1], 16;" :: "r"(dst), "l"(src))
#define CP_COMMIT()  asm volatile("cp.async.commit_group;" ::: "memory")
#define CP_WAIT1()   asm volatile("cp.async.wait_group 1;" ::: "memory")
#define CP_WAIT0()   asm volatile("cp.async.wait_group 0;" ::: "memory")

__device__ __forceinline__ void mma_f16(float* c, const uint32_t* a, const uint32_t* b) {
    asm volatile(
        "mma.sync.aligned.m16n8k16.row.col.f32.f16.f16.f32 "
        "{%0,%1,%2,%3}, {%4,%5,%6,%7}, {%8,%9}, {%0,%1,%2,%3};"
        : "+f"(c[0]), "+f"(c[1]), "+f"(c[2]), "+f"(c[3])
        : "r"(a[0]), "r"(a[1]), "r"(a[2]), "r"(a[3]), "r"(b[0]), "r"(b[1]));
}

__device__ __forceinline__ void ldsm4(uint32_t* r, uint32_t addr) {
    asm volatile("ldmatrix.sync.aligned.m8n8.x4.shared.b16 {%0,%1,%2,%3}, [%4];"
                 : "=r"(r[0]), "=r"(r[1]), "=r"(r[2]), "=r"(r[3]) : "r"(addr));
}

// ---------------------------------------------------------------------------
// Fused pre-pass: z<4 -> transpose+round W_z; z>=4 -> fp16-convert x_{z-4}
// ---------------------------------------------------------------------------
__global__ __launch_bounds__(256)
void prepass(const float* __restrict__ W0, const float* __restrict__ W1,
             const float* __restrict__ W2, const float* __restrict__ W3,
             const float* __restrict__ x0, const float* __restrict__ x1,
             const float* __restrict__ x2,
             __half* __restrict__ T, __half* __restrict__ X)
{
    const int z = blockIdx.z;
    if (z < 4) {
        const float* W = (z == 0) ? W0 : (z == 1) ? W1 : (z == 2) ? W2 : W3;
        __half* Wt = T + (size_t)z * DD * NN;
        __shared__ float t[32][33];
        int x = blockIdx.x * 32 + threadIdx.x;
        int y = blockIdx.y * 32 + threadIdx.y;
        #pragma unroll
        for (int i = 0; i < 32; i += 8)
            t[threadIdx.y + i][threadIdx.x] = W[(size_t)(y + i) * 1024 + x];
        __syncthreads();
        x = blockIdx.y * 32 + threadIdx.x;
        y = blockIdx.x * 32 + threadIdx.y;
        #pragma unroll
        for (int i = 0; i < 32; i += 8)
            Wt[(size_t)(y + i) * 1024 + x] = __float2half_rn(t[threadIdx.x][threadIdx.y + i]);
    } else {
        const float* x = (z == 4) ? x0 : (z == 5) ? x1 : x2;
        __half* dst = X + (size_t)(z - 4) * MM * DD;
        const int tid = threadIdx.y * 32 + threadIdx.x;
        const int fid = blockIdx.y * 32 + blockIdx.x;      // 0..1023
        // each block: 1024 float4 chunks; 4 per thread
        #pragma unroll
        for (int i = 0; i < 4; i++) {
            const size_t idx = (size_t)fid * 1024 + tid + 256 * i;   // float4 units
            float4 v = *(const float4*)&x[idx * 4];
            *(__half2*)&dst[idx * 4]     = __floats2half2_rn(v.x, v.y);
            *(__half2*)&dst[idx * 4 + 2] = __floats2half2_rn(v.z, v.w);
        }
    }
}

// ---------------------------------------------------------------------------
// fp16 GEMM: 128x128 CTA, 256 thr = 8 warps (2x4), warp 64x32, K-chunk 64,
// 3-stage cp.async, 1 barrier per chunk. (unchanged from R11)
// ---------------------------------------------------------------------------
static constexpr int HSTR   = 72;                   // row stride in halves
static constexpr int GTILEH = 128 * HSTR;
static constexpr int GSMEM  = 6 * GTILEH * 2;       // 110592 B

struct GemmCtx {
    uint32_t sb;
    int tid, lane, wm, wn, gq, gt, aBase, bBase, m0, n0;
};

__device__ __forceinline__ void gemm_init(GemmCtx& g, const void* smem) {
    g.sb   = smem_u32(smem);
    g.tid  = threadIdx.x;
    g.lane = g.tid & 31;
    const int wid = g.tid >> 5;
    g.wm   = (wid >> 2) * 64;
    g.wn   = (wid & 3) * 32;
    g.gq   = g.lane >> 2;
    g.gt   = g.lane & 3;
    const int l7 = g.lane & 7, lg8 = (g.lane >> 3) & 1, lg16 = g.lane >> 4;
    g.aBase = (g.wm + l7 + lg8 * 8) * HSTR + lg16 * 8;
    g.bBase = (g.wn + lg16 * 8 + l7) * HSTR + lg8 * 8;
    g.m0 = blockIdx.y * 128;
    g.n0 = blockIdx.x * 128;
}

template<int GATHER>
__device__ __forceinline__ void gemm_load_chunk(const GemmCtx& g, const __half* A,
                                                const __half* Wt, int ck, int st) {
    const int k0 = ck * 64;
    const uint32_t sa = g.sb + (uint32_t)(2 * st) * GTILEH * 2;
    const uint32_t sw = g.sb + (uint32_t)(2 * st + 1) * GTILEH * 2;
    #pragma unroll
    for (int i = 0; i < 4; i++) {
        const int id  = g.tid + 256 * i;
        const int row = id >> 3;
        const int cs  = id & 7;
        const __half* ga;
        if (!GATHER) {
            ga = &A[(size_t)(g.m0 + row) * 1024 + k0 + cs * 8];
        } else {
            const int m  = g.m0 + row;
            const int bb = m >> 11, l = m & 2047;
            const int kk = k0 + cs * 8;
            const int h  = kk >> 6, d = kk & 63;
            ga = &A[(size_t)((bb * HH + h) * LL + l) * DKK + d];
        }
        CP_ASYNC16(sa + (uint32_t)(row * HSTR + cs * 8) * 2, ga);
        CP_ASYNC16(sw + (uint32_t)(row * HSTR + cs * 8) * 2,
                   &Wt[(size_t)(g.n0 + row) * 1024 + k0 + cs * 8]);
    }
}

template<int GATHER>
__device__ __forceinline__ void gemm_main(const GemmCtx& g, const __half* A,
                                          const __half* Wt, float c[4][4][4]) {
    #pragma unroll
    for (int mi = 0; mi < 4; mi++)
        #pragma unroll
        for (int ni = 0; ni < 4; ni++)
            #pragma unroll
            for (int r = 0; r < 4; r++) c[mi][ni][r] = 0.f;

    gemm_load_chunk<GATHER>(g, A, Wt, 0, 0); CP_COMMIT();
    gemm_load_chunk<GATHER>(g, A, Wt, 1, 1); CP_COMMIT();

    for (int ck = 0; ck < 16; ck++) {
        if (ck < 15) CP_WAIT1(); else CP_WAIT0();
        __syncthreads();
        const int st = ck % 3;
        const uint32_t As = g.sb + (uint32_t)(2 * st) * GTILEH * 2;
        const uint32_t Ws = g.sb + (uint32_t)(2 * st + 1) * GTILEH * 2;

        #pragma unroll
        for (int ks = 0; ks < 4; ks++) {
            uint32_t a[4][4];
            #pragma unroll
            for (int mi = 0; mi < 4; mi++)
                ldsm4(a[mi], As + (uint32_t)(g.aBase + mi * 16 * HSTR + ks * 16) * 2);
            uint32_t b[4][2];
            #pragma unroll
            for (int nb = 0; nb < 2; nb++) {
                uint32_t r[4];
                ldsm4(r, Ws + (uint32_t)(g.bBase + nb * 16 * HSTR + ks * 16) * 2);
                b[nb * 2][0] = r[0]; b[nb * 2][1] = r[1];
                b[nb * 2 + 1][0] = r[2]; b[nb * 2 + 1][1] = r[3];
            }
            #pragma unroll
            for (int mi = 0; mi < 4; mi++)
                #pragma unroll
                for (int ni = 0; ni < 4; ni++)
                    mma_f16(c[mi][ni], a[mi], b[ni]);
        }
        if (ck + 2 < 16) { gemm_load_chunk<GATHER>(g, A, Wt, ck + 2, (ck + 2) % 3); CP_COMMIT(); }
    }
}

// ---------------------------------------------------------------------------
// Fused QKV projection GEMM (grid.z = 0:Q, 1:K, 2:V)
// ---------------------------------------------------------------------------
__global__ __launch_bounds__(256, 2)
void gemm_qkv(const __half* __restrict__ xh, const __half* __restrict__ wt,
              const float* __restrict__ bq, const float* __restrict__ bk,
              const float* __restrict__ bv,
              __half* __restrict__ oq, __half* __restrict__ ok, __half* __restrict__ ov)
{
    extern __shared__ char smem[];
    GemmCtx g; gemm_init(g, smem);
    const int z = blockIdx.z;
    const __half* A    = xh + (size_t)z * MM * DD;
    const __half* Wt   = wt + (size_t)z * DD * NN;
    const float* bias  = (z == 0) ? bq : (z == 1) ? bk : bv;
    __half* C          = (z == 0) ? oq : (z == 1) ? ok : ov;
    const float scale  = (z == 0) ? 0.125f * 1.4426950408889634f : 1.0f;

    float c[4][4][4];
    gemm_main<0>(g, A, Wt, c);

    #pragma unroll
    for (int mi = 0; mi < 4; mi++) {
        const int row = g.m0 + g.wm + mi * 16 + g.gq;
        #pragma unroll
        for (int ni = 0; ni < 4; ni++) {
            const int col = g.n0 + g.wn + ni * 8 + 2 * g.gt;
            const float b0 = bias[col], b1 = bias[col + 1];
            const float v0 = (c[mi][ni][0] + b0) * scale;
            const float v1 = (c[mi][ni][1] + b1) * scale;
            const float v2 = (c[mi][ni][2] + b0) * scale;
            const float v3 = (c[mi][ni][3] + b1) * scale;
            const int h = col >> 6, d = col & 63;
            const int bb0 = row >> 11, l0 = row & 2047;
            const int r8 = row + 8;
            const int bb1 = r8 >> 11, l1 = r8 & 2047;
            if (z != 2) {
                *(__half2*)&C[(size_t)((bb0 * HH + h) * LL + l0) * DKK + d] =
                    __floats2half2_rn(v0, v1);
                *(__half2*)&C[(size_t)((bb1 * HH + h) * LL + l1) * DKK + d] =
                    __floats2half2_rn(v2, v3);
            } else {
                C[((size_t)(bb0 * HH + h) * DKK + d)     * LL + l0] = __float2half_rn(v0);
                C[((size_t)(bb0 * HH + h) * DKK + d + 1) * LL + l0] = __float2half_rn(v1);
                C[((size_t)(bb1 * HH + h) * DKK + d)     * LL + l1] = __float2half_rn(v2);
                C[((size_t)(bb1 * HH + h) * DKK + d + 1) * LL + l1] = __float2half_rn(v3);
            }
        }
    }
}

// ---------------------------------------------------------------------------
// Output projection
// ---------------------------------------------------------------------------
__global__ __launch_bounds__(256, 2)
void gemm_out(const __half* __restrict__ ctx, const __half* __restrict__ wt,
              const float* __restrict__ bias, float* __restrict__ C)
{
    extern __shared__ char smem[];
    GemmCtx g; gemm_init(g, smem);

    float c[4][4][4];
    gemm_main<1>(g, ctx, wt, c);

    #pragma unroll
    for (int mi = 0; mi < 4; mi++) {
        const int row = g.m0 + g.wm + mi * 16 + g.gq;
        #pragma unroll
        for (int ni = 0; ni < 4; ni++) {
            const int col = g.n0 + g.wn + ni * 8 + 2 * g.gt;
            const float b0 = bias[col], b1 = bias[col + 1];
            *(float2*)&C[(size_t)row * 1024 + col] =
                make_float2(c[mi][ni][0] + b0, c[mi][ni][1] + b1);
            *(float2*)&C[(size_t)(row + 8) * 1024 + col] =
                make_float2(c[mi][ni][2] + b0, c[mi][ni][3] + b1);
        }
    }
}

// ---------------------------------------------------------------------------
// fp16 flash attention: 128 thr = 4 warps x 32 q-rows (2 m-blocks), BM=128.
// 3-stage KV cp.async pipeline, ONE barrier per iteration. Register P,
// log2-domain softmax. K/V fragment redundancy 4x (was 8x).
// ---------------------------------------------------------------------------
static constexpr int STAGEH = 128 * HSTR;                 // K(64)+V(64) rows per stage
static constexpr int SQ     = 3 * STAGEH;                 // Q after 3 stages
static constexpr int ATT_SMEM = (SQ + 128 * HSTR) * 2;    // 73728 bytes

__global__ __launch_bounds__(128, 2)
void attn_mma(const __half* __restrict__ q, const __half* __restrict__ k,
              const __half* __restrict__ v, __half* __restrict__ ctx)
{
    extern __shared__ char smraw[];
    __half* smh = (__half*)smraw;
    const uint32_t sb = smem_u32(smraw);
    const int tid = threadIdx.x, lane = tid & 31, wid = tid >> 5;
    const int gq = lane >> 2, gt = lane & 3;
    const int l7 = lane & 7, lg8 = (lane >> 3) & 1, lg16 = lane >> 4;
    const int wm = wid * 32;                   // 32 q-rows per warp
    const int bh = blockIdx.y;
    const int q0 = blockIdx.x * 128;
    const __half* kb = k + (size_t)bh * LL * DKK;
    const __half* vb = v + (size_t)bh * DKK * LL;

    const int aBase = (wm + l7 + lg8 * 8) * HSTR + lg16 * 8;   // +mb*16*HSTR +s*16
    const int bBase = (lg16 * 8 + l7) * HSTR + lg8 * 8;        // +nb*16*HSTR +s*16

    // Stage Q tile (128 rows x 64 halves): 1024 16B chunks, 8 per thread
    #pragma unroll
    for (int i = 0; i < 8; i++) {
        const int id = tid + 128 * i;
        const int row = id >> 3, c = id & 7;
        *(uint4*)&smh[SQ + row * HSTR + c * 8] =
            *(const uint4*)&q[((size_t)bh * LL + q0 + row) * DKK + c * 8];
    }
    __syncthreads();
    uint32_t aq[4][2][4];
    #pragma unroll
    for (int s = 0; s < 4; s++)
        #pragma unroll
        for (int mb = 0; mb < 2; mb++)
            ldsm4(aq[s][mb], sb + (uint32_t)(SQ + aBase + mb * 16 * HSTR + s * 16) * 2);

    float co[2][8][4];
    #pragma unroll
    for (int mb = 0; mb < 2; mb++)
        #pragma unroll
        for (int ni = 0; ni < 8; ni++)
            #pragma unroll
            for (int r = 0; r < 4; r++) co[mb][ni][r] = 0.f;
    float mx[2][2], li[2][2];
    #pragma unroll
    for (int mb = 0; mb < 2; mb++) {
        mx[mb][0] = -INFINITY; mx[mb][1] = -INFINITY;
        li[mb][0] = 0.f;       li[mb][1] = 0.f;
    }

    auto load_kv = [&](int kt, int st) {
        const uint32_t koff = (uint32_t)(st * STAGEH);
        const uint32_t voff = koff + 64 * HSTR;
        #pragma unroll
        for (int i = 0; i < 4; i++) {
            const int id = tid + 128 * i;          // 0..511
            const int row = id >> 3, c = id & 7;
            CP_ASYNC16(sb + (koff + row * HSTR + c * 8) * 2,
                       &kb[((size_t)kt * 64 + row) * DKK + c * 8]);
            CP_ASYNC16(sb + (voff + row * HSTR + c * 8) * 2,
                       &vb[(size_t)row * LL + kt * 64 + c * 8]);
        }
    };
    load_kv(0, 0); CP_COMMIT();
    load_kv(1, 1); CP_COMMIT();

    for (int kt = 0; kt < LL / 64; kt++) {
        if (kt < LL / 64 - 1) CP_WAIT1(); else CP_WAIT0();
        __syncthreads();
        const int st = kt % 3;
        const uint32_t kbuf = (uint32_t)(st * STAGEH);
        const uint32_t vbuf = kbuf + 64 * HSTR;

        // S = Q @ K^T  (log2 domain)
        float sc[2][8][4];
        #pragma unroll
        for (int mb = 0; mb < 2; mb++)
            #pragma unroll
            for (int ni = 0; ni < 8; ni++)
                #pragma unroll
                for (int r = 0; r < 4; r++) sc[mb][ni][r] = 0.f;
        #pragma unroll
        for (int s = 0; s < 4; s++) {
            uint32_t bf[8][2];
            #pragma unroll
            for (int nb = 0; nb < 4; nb++) {
                uint32_t r[4];
                ldsm4(r, sb + (kbuf + (uint32_t)(bBase + nb * 16 * HSTR + s * 16)) * 2);
                bf[nb * 2][0] = r[0]; bf[nb * 2][1] = r[1];
                bf[nb * 2 + 1][0] = r[2]; bf[nb * 2 + 1][1] = r[3];
            }
            #pragma unroll
            for (int mb = 0; mb < 2; mb++)
                #pragma unroll
                for (int ni = 0; ni < 8; ni++)
                    mma_f16(sc[mb][ni], aq[s][mb], bf[ni]);
        }

        // Online softmax per m-block (log2 domain)
        #pragma unroll
        for (int mb = 0; mb < 2; mb++) {
            float rm0 = sc[mb][0][0], rm1 = sc[mb][0][2];
            #pragma unroll
            for (int ni = 0; ni < 8; ni++) {
                rm0 = fmaxf(rm0, fmaxf(sc[mb][ni][0], sc[mb][ni][1]));
                rm1 = fmaxf(rm1, fmaxf(sc[mb][ni][2], sc[mb][ni][3]));
            }
            rm0 = fmaxf(rm0, __shfl_xor_sync(0xffffffff, rm0, 1));
            rm0 = fmaxf(rm0, __shfl_xor_sync(0xffffffff, rm0, 2));
            rm1 = fmaxf(rm1, __shfl_xor_sync(0xffffffff, rm1, 1));
            rm1 = fmaxf(rm1, __shfl_xor_sync(0xffffffff, rm1, 2));
            const float nm0 = fmaxf(mx[mb][0], rm0), nm1 = fmaxf(mx[mb][1], rm1);
            const float cr0 = ex2f(mx[mb][0] - nm0), cr1 = ex2f(mx[mb][1] - nm1);
            float rs0 = 0.f, rs1 = 0.f;
            #pragma unroll
            for (int ni = 0; ni < 8; ni++) {
                sc[mb][ni][0] = ex2f(sc[mb][ni][0] - nm0);
                sc[mb][ni][1] = ex2f(sc[mb][ni][1] - nm0);
                sc[mb][ni][2] = ex2f(sc[mb][ni][2] - nm1);
                sc[mb][ni][3] = ex2f(sc[mb][ni][3] - nm1);
                rs0 += sc[mb][ni][0] + sc[mb][ni][1];
                rs1 += sc[mb][ni][2] + sc[mb][ni][3];
            }
            rs0 += __shfl_xor_sync(0xffffffff, rs0, 1);
            rs0 += __shfl_xor_sync(0xffffffff, rs0, 2);
            rs1 += __shfl_xor_sync(0xffffffff, rs1, 1);
            rs1 += __shfl_xor_sync(0xffffffff, rs1, 2);
            mx[mb][0] = nm0; mx[mb][1] = nm1;
            li[mb][0] = li[mb][0] * cr0 + rs0;
            li[mb][1] = li[mb][1] * cr1 + rs1;
            #pragma unroll
            for (int ni = 0; ni < 8; ni++) {
                co[mb][ni][0] *= cr0; co[mb][ni][1] *= cr0;
                co[mb][ni][2] *= cr1; co[mb][ni][3] *= cr1;
            }
        }

        // ctx += P @ V  (P packed from sc; C-frag == A-frag layout)
        #pragma unroll
        for (int s = 0; s < 4; s++) {
            uint32_t ap[2][4];
            #pragma unroll
            for (int mb = 0; mb < 2; mb++) {
                ap[mb][0] = packh2(sc[mb][2*s][0],   sc[mb][2*s][1]);
                ap[mb][1] = packh2(sc[mb][2*s][2],   sc[mb][2*s][3]);
                ap[mb][2] = packh2(sc[mb][2*s+1][0], sc[mb][2*s+1][1]);
                ap[mb][3] = packh2(sc[mb][2*s+1][2], sc[mb][2*s+1][3]);
            }
            uint32_t bv_[8][2];
            #pragma unroll
            for (int nb = 0; nb < 4; nb++) {
                uint32_t r[4];
                ldsm4(r, sb + (vbuf + (uint32_t)(bBase + nb * 16 * HSTR + s * 16)) * 2);
                bv_[nb * 2][0] = r[0]; bv_[nb * 2][1] = r[1];
                bv_[nb * 2 + 1][0] = r[2]; bv_[nb * 2 + 1][1] = r[3];
            }
            #pragma unroll
            for (int mb = 0; mb < 2; mb++)
                #pragma unroll
                for (int ni = 0; ni < 8; ni++)
                    mma_f16(co[mb][ni], ap[mb], bv_[ni]);
        }

        if (kt + 2 < LL / 64) { load_kv(kt + 2, (kt + 2) % 3); CP_COMMIT(); }
    }

    // Epilogue: normalize, store ctx fp16
    #pragma unroll
    for (int mb = 0; mb < 2; mb++) {
        const float inv0 = 1.f / li[mb][0], inv1 = 1.f / li[mb][1];
        const int row0 = q0 + wm + mb * 16 + gq, row1 = row0 + 8;
        #pragma unroll
        for (int ni = 0; ni < 8; ni++) {
            const int col = ni * 8 + 2 * gt;
            *(__half2*)&ctx[((size_t)bh * LL + row0) * DKK + col] =
                __floats2half2_rn(co[mb][ni][0] * inv0, co[mb][ni][1] * inv0);
            *(__half2*)&ctx[((size_t)bh * LL + row1) * DKK + col] =
                __floats2half2_rn(co[mb][ni][2] * inv1, co[mb][ni][3] * inv1);
        }
    }
}

// ---------------------------------------------------------------------------
extern "C" void kernel_launch(void* const* d_in, const int* in_sizes, int n_in,
                              void* d_out, int out_size)
{
    const float* x_q = (const float*)d_in[0];
    const float* x_k = (const float*)d_in[1];
    const float* x_v = (const float*)d_in[2];
    const float* Wq  = (const float*)d_in[3];
    const float* bq  = (const float*)d_in[4];
    const float* Wk  = (const float*)d_in[5];
    const float* bk  = (const float*)d_in[6];
    const float* Wv  = (const float*)d_in[7];
    const float* bv  = (const float*)d_in[8];
    const float* Wo  = (const float*)d_in[9];
    const float* bo  = (const float*)d_in[10];
    float* out = (float*)d_out;

    __half *pq, *pk, *pv, *pctx, *pxh, *pwt;
    cudaGetSymbolAddress((void**)&pq,   g_qh);
    cudaGetSymbolAddress((void**)&pk,   g_kh);
    cudaGetSymbolAddress((void**)&pv,   g_vh);
    cudaGetSymbolAddress((void**)&pctx, g_ctxh);
    cudaGetSymbolAddress((void**)&pxh,  g_xh);
    cudaGetSymbolAddress((void**)&pwt,  g_wth);
    __half* wto = pwt + (size_t)3 * DD * NN;

    cudaFuncSetAttribute(gemm_qkv, cudaFuncAttributeMaxDynamicSharedMemorySize, GSMEM);
    cudaFuncSetAttribute(gemm_out, cudaFuncAttributeMaxDynamicSharedMemorySize, GSMEM);
    cudaFuncSetAttribute(attn_mma, cudaFuncAttributeMaxDynamicSharedMemorySize, ATT_SMEM);

    dim3 pgrid(32, 32, 7), pblk(32, 8);
    dim3 qkvgrid(8, 32, 3);
    dim3 ggrid(8, 32);
    dim3 agrid(LL / 128, BB * HH);

    prepass<<<pgrid, pblk>>>(Wq, Wk, Wv, Wo, x_q, x_k, x_v, pwt, pxh);

    gemm_qkv<<<qkvgrid, 256, GSMEM>>>(pxh, pwt, bq, bk, bv, pq, pk, pv);

    attn_mma<<<agrid, 128, ATT_SMEM>>>(pq, pk, pv, pctx);

    gemm_out<<<ggrid, 256, GSMEM>>>(pctx, wto, bo, out);
}